// round 2
// baseline (speedup 1.0000x reference)
#include <cuda_runtime.h>
#include <math.h>

// ---------------------------------------------------------------------------
// SlotAttention fp32 baseline.
// B=32, N=2048, DIN=DOUT=HID=512, S=2, ITERS=3.
// Output layout (float32, concatenated): slots[32,2,512], q[32,2,512],
//   k[32,2048,512], attn[32,2,2048]  => 33,751,040 floats total.
// ---------------------------------------------------------------------------

#define NROWS 65536      // B*N
#define D 512

// ---- scratch: one big __device__ global (no allocations allowed) ----
#define OFF_V     0                       // v: 32*2048*512 = 33554432
#define OFF_MEAN  33554432                // 65536
#define OFF_RSTD  (33554432 + 65536)      // 65536
#define OFF_ATTN  (33554432 + 131072)     // attn_pre: 32*2*2048 = 131072
#define OFF_SLN   (OFF_ATTN + 131072)     // 64*512
#define OFF_UPD   (OFF_SLN  + 32768)      // 64*512
#define OFF_GX    (OFF_UPD  + 32768)      // 64*1536
#define OFF_GH    (OFF_GX   + 98304)      // 64*1536
#define OFF_HNEW  (OFF_GH   + 98304)      // 64*512
#define OFF_HLN   (OFF_HNEW + 32768)      // 64*512
#define OFF_T     (OFF_HLN  + 32768)      // 64*512
#define SCRATCH_FLOATS (OFF_T + 32768)    // 34177024

__device__ float g_scratch[SCRATCH_FLOATS];

static __device__ __forceinline__ float sigmoidf_(float x) {
    return 1.0f / (1.0f + expf(-x));
}

// ---------------------------------------------------------------------------
// Kernel 0: per-row mean / rstd of inputs (rows of 512). 65536 blocks x 128.
// ---------------------------------------------------------------------------
__global__ void k_rowstats(const float* __restrict__ x,
                           float* __restrict__ mean, float* __restrict__ rstd) {
    int row = blockIdx.x;
    int t = threadIdx.x;  // 128 threads, one float4 each
    float4 v = ((const float4*)(x + (size_t)row * D))[t];
    float s  = v.x + v.y + v.z + v.w;
    float s2 = v.x * v.x + v.y * v.y + v.z * v.z + v.w * v.w;
#pragma unroll
    for (int o = 16; o; o >>= 1) {
        s  += __shfl_down_sync(0xffffffffu, s,  o);
        s2 += __shfl_down_sync(0xffffffffu, s2, o);
    }
    __shared__ float ss[4], ss2[4];
    if ((t & 31) == 0) { ss[t >> 5] = s; ss2[t >> 5] = s2; }
    __syncthreads();
    if (t == 0) {
        float S  = ss[0] + ss[1] + ss[2] + ss[3];
        float S2 = ss2[0] + ss2[1] + ss2[2] + ss2[3];
        float m   = S * (1.0f / 512.0f);
        float var = S2 * (1.0f / 512.0f) - m * m;
        mean[row] = m;
        rstd[row] = rsqrtf(var + 1e-5f);
    }
}

// ---------------------------------------------------------------------------
// Kernel 1: fused LN(inputs) @ {Wk, Wv} + bias  -> k (d_out slice), v (scratch)
// BM=128, BN=64, BK=16, 256 threads, thread tile 8x4 per output.
// Grid (512, 8).
// ---------------------------------------------------------------------------
__global__ __launch_bounds__(256) void k_lngemm2(
    const float* __restrict__ A, const float* __restrict__ Wk,
    const float* __restrict__ Wv, const float* __restrict__ bk,
    const float* __restrict__ bv, const float* __restrict__ g,
    const float* __restrict__ bln, const float* __restrict__ mean,
    const float* __restrict__ rstd, float* __restrict__ outK,
    float* __restrict__ outV) {
    __shared__ float As[16][128];
    __shared__ float Bks[16][64];
    __shared__ float Bvs[16][64];
    __shared__ float gsh[512], bsh[512];

    int tid  = threadIdx.x;
    int row0 = blockIdx.x << 7;
    int col0 = blockIdx.y << 6;

    for (int i = tid; i < 512; i += 256) { gsh[i] = g[i]; bsh[i] = bln[i]; }

    int arow = tid >> 1;
    int akc  = (tid & 1) << 3;
    float m  = mean[row0 + arow];
    float rs = rstd[row0 + arow];
    const float* Arow = A + (size_t)(row0 + arow) * D;

    int wkr = tid >> 4;
    int wn  = (tid & 15) << 2;
    const float* WkP = Wk + (size_t)wkr * D + col0 + wn;
    const float* WvP = Wv + (size_t)wkr * D + col0 + wn;

    int ty = tid >> 4, tx = tid & 15;

    float acck[8][4], accv[8][4];
#pragma unroll
    for (int r = 0; r < 8; r++)
#pragma unroll
        for (int c = 0; c < 4; c++) { acck[r][c] = 0.f; accv[r][c] = 0.f; }

    __syncthreads();

    for (int kt = 0; kt < 512; kt += 16) {
        float4 a0 = *(const float4*)(Arow + kt + akc);
        float4 a1 = *(const float4*)(Arow + kt + akc + 4);
        float4 w0 = *(const float4*)(WkP + (size_t)kt * D);
        float4 w1 = *(const float4*)(WvP + (size_t)kt * D);

        As[akc + 0][arow] = (a0.x - m) * rs * gsh[kt + akc + 0] + bsh[kt + akc + 0];
        As[akc + 1][arow] = (a0.y - m) * rs * gsh[kt + akc + 1] + bsh[kt + akc + 1];
        As[akc + 2][arow] = (a0.z - m) * rs * gsh[kt + akc + 2] + bsh[kt + akc + 2];
        As[akc + 3][arow] = (a0.w - m) * rs * gsh[kt + akc + 3] + bsh[kt + akc + 3];
        As[akc + 4][arow] = (a1.x - m) * rs * gsh[kt + akc + 4] + bsh[kt + akc + 4];
        As[akc + 5][arow] = (a1.y - m) * rs * gsh[kt + akc + 5] + bsh[kt + akc + 5];
        As[akc + 6][arow] = (a1.z - m) * rs * gsh[kt + akc + 6] + bsh[kt + akc + 6];
        As[akc + 7][arow] = (a1.w - m) * rs * gsh[kt + akc + 7] + bsh[kt + akc + 7];
        *(float4*)&Bks[wkr][wn] = w0;
        *(float4*)&Bvs[wkr][wn] = w1;
        __syncthreads();

#pragma unroll
        for (int kk = 0; kk < 16; kk++) {
            float a[8];
            *(float4*)&a[0] = *(const float4*)&As[kk][ty << 3];
            *(float4*)&a[4] = *(const float4*)&As[kk][(ty << 3) + 4];
            float4 bkv = *(const float4*)&Bks[kk][tx << 2];
            float4 bvv = *(const float4*)&Bvs[kk][tx << 2];
#pragma unroll
            for (int r = 0; r < 8; r++) {
                acck[r][0] += a[r] * bkv.x;
                acck[r][1] += a[r] * bkv.y;
                acck[r][2] += a[r] * bkv.z;
                acck[r][3] += a[r] * bkv.w;
                accv[r][0] += a[r] * bvv.x;
                accv[r][1] += a[r] * bvv.y;
                accv[r][2] += a[r] * bvv.z;
                accv[r][3] += a[r] * bvv.w;
            }
        }
        __syncthreads();
    }

    float4 biask = *(const float4*)(bk + col0 + (tx << 2));
    float4 biasv = *(const float4*)(bv + col0 + (tx << 2));
#pragma unroll
    for (int r = 0; r < 8; r++) {
        size_t o = (size_t)(row0 + (ty << 3) + r) * D + col0 + (tx << 2);
        float4 ok, ov;
        ok.x = acck[r][0] + biask.x; ok.y = acck[r][1] + biask.y;
        ok.z = acck[r][2] + biask.z; ok.w = acck[r][3] + biask.w;
        ov.x = accv[r][0] + biasv.x; ov.y = accv[r][1] + biasv.y;
        ov.z = accv[r][2] + biasv.z; ov.w = accv[r][3] + biasv.w;
        *(float4*)&outK[o] = ok;
        *(float4*)&outV[o] = ov;
    }
}

// ---------------------------------------------------------------------------
// LN over 64 rows of 512 (slots / h_new). 64 blocks x 128 threads.
// ---------------------------------------------------------------------------
__global__ void k_ln64(const float* __restrict__ in, const float* __restrict__ g,
                       const float* __restrict__ b, float* __restrict__ out) {
    int r = blockIdx.x, t = threadIdx.x;
    float4 v = ((const float4*)(in + (size_t)r * D))[t];
    float s  = v.x + v.y + v.z + v.w;
    float s2 = v.x * v.x + v.y * v.y + v.z * v.z + v.w * v.w;
#pragma unroll
    for (int o = 16; o; o >>= 1) {
        s  += __shfl_down_sync(0xffffffffu, s,  o);
        s2 += __shfl_down_sync(0xffffffffu, s2, o);
    }
    __shared__ float ss[4], ss2[4];
    __shared__ float sm, srs;
    if ((t & 31) == 0) { ss[t >> 5] = s; ss2[t >> 5] = s2; }
    __syncthreads();
    if (t == 0) {
        float S  = ss[0] + ss[1] + ss[2] + ss[3];
        float S2 = ss2[0] + ss2[1] + ss2[2] + ss2[3];
        float m   = S * (1.0f / 512.0f);
        float var = S2 * (1.0f / 512.0f) - m * m;
        sm = m; srs = rsqrtf(var + 1e-5f);
    }
    __syncthreads();
    float m = sm, rs = srs;
    float4 gg = ((const float4*)g)[t];
    float4 bb = ((const float4*)b)[t];
    float4 o;
    o.x = (v.x - m) * rs * gg.x + bb.x;
    o.y = (v.y - m) * rs * gg.y + bb.y;
    o.z = (v.z - m) * rs * gg.z + bb.z;
    o.w = (v.w - m) * rs * gg.w + bb.w;
    ((float4*)(out + (size_t)r * D))[t] = o;
}

// ---------------------------------------------------------------------------
// Small GEMM: C[64, ncols] = A[64,512] @ W (+bias)(relu?)(+resid).
// TRANSW=0: W is [512, ncols] row-major (C = A@W).
// TRANSW=1: W is [ncols, 512] row-major (C = A@W^T).
// Block: 32-col tile, 256 threads (8 row-groups x 32 cols), thread tile 8x1.
// ---------------------------------------------------------------------------
template <int TRANSW>
__global__ __launch_bounds__(256) void k_gemm64(
    const float* __restrict__ A, const float* __restrict__ W,
    const float* __restrict__ bias, const float* __restrict__ resid,
    float* __restrict__ out, int ncols, int relu) {
    __shared__ float As[32][64];
    __shared__ float Ws[32][33];
    int tid  = threadIdx.x;
    int col0 = blockIdx.x << 5;
    int ty = tid >> 5, tx = tid & 31;
    int ar0 = tid >> 3, akp = (tid & 7) << 2;

    float acc[8];
#pragma unroll
    for (int i = 0; i < 8; i++) acc[i] = 0.f;

    for (int kt = 0; kt < 512; kt += 32) {
        float4 a0 = *(const float4*)(A + (size_t)ar0 * D + kt + akp);
        float4 a1 = *(const float4*)(A + (size_t)(ar0 + 32) * D + kt + akp);
        As[akp + 0][ar0] = a0.x; As[akp + 1][ar0] = a0.y;
        As[akp + 2][ar0] = a0.z; As[akp + 3][ar0] = a0.w;
        As[akp + 0][ar0 + 32] = a1.x; As[akp + 1][ar0 + 32] = a1.y;
        As[akp + 2][ar0 + 32] = a1.z; As[akp + 3][ar0 + 32] = a1.w;
        if (TRANSW) {
            int wn = tid >> 3, wkp = (tid & 7) << 2;
            float4 w0 = *(const float4*)(W + (size_t)(col0 + wn) * D + kt + wkp);
            Ws[wkp + 0][wn] = w0.x; Ws[wkp + 1][wn] = w0.y;
            Ws[wkp + 2][wn] = w0.z; Ws[wkp + 3][wn] = w0.w;
        } else {
            int wk = tid >> 3, wnp = (tid & 7) << 2;
            float4 w0 = *(const float4*)(W + (size_t)(kt + wk) * ncols + col0 + wnp);
            Ws[wk][wnp + 0] = w0.x; Ws[wk][wnp + 1] = w0.y;
            Ws[wk][wnp + 2] = w0.z; Ws[wk][wnp + 3] = w0.w;
        }
        __syncthreads();
#pragma unroll
        for (int kk = 0; kk < 32; kk++) {
            float w = Ws[kk][tx];
            float a[8];
            *(float4*)&a[0] = *(const float4*)&As[kk][ty << 3];
            *(float4*)&a[4] = *(const float4*)&As[kk][(ty << 3) + 4];
#pragma unroll
            for (int r = 0; r < 8; r++) acc[r] += a[r] * w;
        }
        __syncthreads();
    }

    float bvv = bias[col0 + tx];
#pragma unroll
    for (int r = 0; r < 8; r++) {
        int row = (ty << 3) + r;
        float val = acc[r] + bvv;
        if (relu) val = fmaxf(val, 0.f);
        if (resid) val += resid[(size_t)row * D + col0 + tx];
        out[(size_t)row * ncols + col0 + tx] = val;
    }
}

// ---------------------------------------------------------------------------
// dots + softmax over the slot axis. Grid (16 j-tiles, 32 batches) x 128.
// attn_pre[b][i][j] = softmax_i( SCALE * q[b,i,:] . k[b,j,:] )
// ---------------------------------------------------------------------------
__global__ __launch_bounds__(128) void k_dots(const float* __restrict__ q,
                                              const float* __restrict__ k,
                                              float* __restrict__ attn_pre) {
    int b = blockIdx.y, j0 = blockIdx.x << 7;
    int t = threadIdx.x;
    __shared__ float qs0[512], qs1[512];
    __shared__ float ks[128][65];
    {
        float4 q0 = ((const float4*)(q + (size_t)(b * 2 + 0) * D))[t];
        float4 q1 = ((const float4*)(q + (size_t)(b * 2 + 1) * D))[t];
        *(float4*)&qs0[t << 2] = q0;
        *(float4*)&qs1[t << 2] = q1;
    }
    float d0 = 0.f, d1 = 0.f;
    const float* kb = k + ((size_t)b * 2048 + j0) * D;
    for (int kc = 0; kc < 512; kc += 64) {
        __syncthreads();
#pragma unroll
        for (int i = 0; i < 16; i++) {
            int f = t + (i << 7);
            int j = f >> 4, kp = (f & 15) << 2;
            float4 kv = *(const float4*)(kb + (size_t)j * D + kc + kp);
            ks[j][kp + 0] = kv.x; ks[j][kp + 1] = kv.y;
            ks[j][kp + 2] = kv.z; ks[j][kp + 3] = kv.w;
        }
        __syncthreads();
#pragma unroll
        for (int kk = 0; kk < 64; kk++) {
            float kv = ks[t][kk];
            d0 += kv * qs0[kc + kk];
            d1 += kv * qs1[kc + kk];
        }
    }
    const float SC = 0.044194173824159216f;  // 512^-0.5
    d0 *= SC; d1 *= SC;
    float mx = fmaxf(d0, d1);
    float e0 = expf(d0 - mx), e1 = expf(d1 - mx);
    float inv = 1.0f / (e0 + e1);
    attn_pre[b * 4096 + (j0 + t)]        = e0 * inv;
    attn_pre[b * 4096 + 2048 + (j0 + t)] = e1 * inv;
}

// ---------------------------------------------------------------------------
// updates[b,i,:] = (sum_j v[b,j,:] * attn_pre[b,i,j]) / (rowsum_i + 1e-8)
// Grid (4 d-tiles, 32 batches) x 128.
// ---------------------------------------------------------------------------
__global__ __launch_bounds__(128) void k_upd(const float* __restrict__ attn_pre,
                                             const float* __restrict__ v,
                                             float* __restrict__ upd) {
    int b = blockIdx.y, d0 = blockIdx.x << 7, t = threadIdx.x;
    const float* a0p = attn_pre + b * 4096;
    const float* a1p = a0p + 2048;
    float s0 = 0.f, s1 = 0.f;
    for (int j = t; j < 2048; j += 128) { s0 += a0p[j]; s1 += a1p[j]; }
#pragma unroll
    for (int o = 16; o; o >>= 1) {
        s0 += __shfl_down_sync(0xffffffffu, s0, o);
        s1 += __shfl_down_sync(0xffffffffu, s1, o);
    }
    __shared__ float r0[4], r1[4];
    if ((t & 31) == 0) { r0[t >> 5] = s0; r1[t >> 5] = s1; }
    __syncthreads();
    float inv0 = 1.0f / (r0[0] + r0[1] + r0[2] + r0[3] + 1e-8f);
    float inv1 = 1.0f / (r1[0] + r1[1] + r1[2] + r1[3] + 1e-8f);

    __shared__ float w0[256], w1[256];
    float acc0 = 0.f, acc1 = 0.f;
    const float* vb = v + (size_t)b * 2048 * D + d0 + t;
    for (int jc = 0; jc < 2048; jc += 256) {
        __syncthreads();
        w0[t] = a0p[jc + t]; w0[t + 128] = a0p[jc + t + 128];
        w1[t] = a1p[jc + t]; w1[t + 128] = a1p[jc + t + 128];
        __syncthreads();
#pragma unroll 8
        for (int jj = 0; jj < 256; jj++) {
            float vv = vb[(size_t)(jc + jj) * D];
            acc0 += vv * w0[jj];
            acc1 += vv * w1[jj];
        }
    }
    upd[(size_t)(b * 2 + 0) * D + d0 + t] = acc0 * inv0;
    upd[(size_t)(b * 2 + 1) * D + d0 + t] = acc1 * inv1;
}

// ---------------------------------------------------------------------------
// attn output: attn_pre / (rowsum + 1e-8). 64 blocks (one per b,i) x 256.
// ---------------------------------------------------------------------------
__global__ void k_attnnorm(const float* __restrict__ attn_pre,
                           float* __restrict__ attn_out) {
    int r = blockIdx.x, t = threadIdx.x;
    size_t off = (size_t)(r >> 1) * 4096 + (size_t)(r & 1) * 2048;
    const float* p = attn_pre + off;
    float s = 0.f;
    for (int j = t; j < 2048; j += 256) s += p[j];
#pragma unroll
    for (int o = 16; o; o >>= 1) s += __shfl_down_sync(0xffffffffu, s, o);
    __shared__ float ss[8];
    if ((t & 31) == 0) ss[t >> 5] = s;
    __syncthreads();
    float inv = 1.0f / (ss[0] + ss[1] + ss[2] + ss[3] + ss[4] + ss[5] + ss[6] + ss[7] + 1e-8f);
    float* o = attn_out + off;
    for (int j = t; j < 2048; j += 256) o[j] = p[j] * inv;
}

// ---------------------------------------------------------------------------
// GRU gates. 128 blocks x 256 threads, one thread per (row, d).
// ---------------------------------------------------------------------------
__global__ void k_gru2(const float* __restrict__ gx, const float* __restrict__ gh,
                       const float* __restrict__ slots, float* __restrict__ hnew) {
    int idx = blockIdx.x * 256 + threadIdx.x;  // 0..32767
    int r = idx >> 9, d = idx & 511;
    const float* gxr = gx + (size_t)r * 1536;
    const float* ghr = gh + (size_t)r * 1536;
    float rg = sigmoidf_(gxr[d] + ghr[d]);
    float z  = sigmoidf_(gxr[512 + d] + ghr[512 + d]);
    float n  = tanhf(gxr[1024 + d] + rg * ghr[1024 + d]);
    hnew[idx] = (1.0f - z) * n + z * slots[idx];
}

// ---------------------------------------------------------------------------
// host
// ---------------------------------------------------------------------------
extern "C" void kernel_launch(void* const* d_in, const int* in_sizes, int n_in,
                              void* d_out, int out_size) {
    (void)in_sizes; (void)n_in; (void)out_size;
    const float* inputs     = (const float*)d_in[0];
    const float* init_slots = (const float*)d_in[1];
    const float* Wq  = (const float*)d_in[2];
    const float* bq  = (const float*)d_in[3];
    const float* Wk  = (const float*)d_in[4];
    const float* bk  = (const float*)d_in[5];
    const float* Wv  = (const float*)d_in[6];
    const float* bv  = (const float*)d_in[7];
    const float* ln_in_g = (const float*)d_in[8];
    const float* ln_in_b = (const float*)d_in[9];
    const float* ln_s_g  = (const float*)d_in[10];
    const float* ln_s_b  = (const float*)d_in[11];
    const float* ln_f_g  = (const float*)d_in[12];
    const float* ln_f_b  = (const float*)d_in[13];
    const float* gru_wih = (const float*)d_in[14];
    const float* gru_whh = (const float*)d_in[15];
    const float* gru_bih = (const float*)d_in[16];
    const float* gru_bhh = (const float*)d_in[17];
    const float* W1 = (const float*)d_in[18];
    const float* b1 = (const float*)d_in[19];
    const float* W2 = (const float*)d_in[20];
    const float* b2 = (const float*)d_in[21];

    float* out      = (float*)d_out;
    float* slots    = out;                       // 32*2*512
    float* qout     = out + 32768;               // 32*2*512
    float* kout     = out + 65536;               // 32*2048*512
    float* attn_out = out + 65536 + 33554432;    // 32*2*2048

    float* S = nullptr;
    cudaGetSymbolAddress((void**)&S, g_scratch);
    float* v    = S + OFF_V;
    float* mean = S + OFF_MEAN;
    float* rstd = S + OFF_RSTD;
    float* attn = S + OFF_ATTN;
    float* sln  = S + OFF_SLN;
    float* upd  = S + OFF_UPD;
    float* gx   = S + OFF_GX;
    float* gh   = S + OFF_GH;
    float* hnew = S + OFF_HNEW;
    float* hln  = S + OFF_HLN;
    float* tbuf = S + OFF_T;

    cudaMemcpyAsync(slots, init_slots, 32768 * sizeof(float),
                    cudaMemcpyDeviceToDevice);

    k_rowstats<<<NROWS, 128>>>(inputs, mean, rstd);
    k_lngemm2<<<dim3(512, 8), 256>>>(inputs, Wk, Wv, bk, bv, ln_in_g, ln_in_b,
                                     mean, rstd, kout, v);

    for (int it = 0; it < 3; ++it) {
        k_ln64<<<64, 128>>>(slots, ln_s_g, ln_s_b, sln);
        k_gemm64<0><<<16, 256>>>(sln, Wq, bq, nullptr, qout, 512, 0);
        k_dots<<<dim3(16, 32), 128>>>(qout, kout, attn);
        k_upd<<<dim3(4, 32), 128>>>(attn, v, upd);
        k_attnnorm<<<64, 256>>>(attn, attn_out);
        k_gemm64<1><<<48, 256>>>(upd, gru_wih, gru_bih, nullptr, gx, 1536, 0);
        k_gemm64<1><<<48, 256>>>(slots, gru_whh, gru_bhh, nullptr, gh, 1536, 0);
        k_gru2<<<128, 256>>>(gx, gh, slots, hnew);
        k_ln64<<<64, 128>>>(hnew, ln_f_g, ln_f_b, hln);
        k_gemm64<0><<<16, 256>>>(hln, W1, b1, nullptr, tbuf, 512, 1);
        k_gemm64<0><<<16, 256>>>(tbuf, W2, b2, hnew, slots, 512, 0);
    }
}

// round 5
// speedup vs baseline: 1.1804x; 1.1804x over previous
#include <cuda_runtime.h>
#include <cuda_bf16.h>
#include <math.h>
#include <stdint.h>

// ---------------------------------------------------------------------------
// SlotAttention. B=32, N=2048, DIN=DOUT=HID=512, S=2, ITERS=3.
// Big LN+GEMM (k,v) via mma.sync bf16 3-pass split precision (sm_103-legal).
// Output: slots[32,2,512], q[32,2,512], k[32,2048,512], attn[32,2,2048].
// ---------------------------------------------------------------------------

#define NROWS 65536
#define D 512

// ---- scratch ----
#define OFF_V     0
#define OFF_MEAN  33554432
#define OFF_RSTD  (33554432 + 65536)
#define OFF_ATTN  (33554432 + 131072)
#define OFF_SLN   (OFF_ATTN + 131072)
#define OFF_UPD   (OFF_SLN  + 32768)
#define OFF_GX    (OFF_UPD  + 32768)
#define OFF_GH    (OFF_GX   + 98304)
#define OFF_HNEW  (OFF_GH   + 98304)
#define OFF_HLN   (OFF_HNEW + 32768)
#define OFF_T     (OFF_HLN  + 32768)
#define OFF_WHI   (OFF_T    + 32768)   // 1024x512 bf16 = 262144 "floats"
#define OFF_WLO   (OFF_WHI  + 262144)
#define SCRATCH_FLOATS (OFF_WLO + 262144)

__device__ float g_scratch[SCRATCH_FLOATS];

static __device__ __forceinline__ float sigmoidf_(float x) {
    return 1.0f / (1.0f + expf(-x));
}

static __device__ __forceinline__ uint32_t smem_u32(const void* p) {
    uint32_t a;
    asm("{ .reg .u64 t; cvta.to.shared.u64 t, %1; cvt.u32.u64 %0, t; }"
        : "=r"(a) : "l"(p));
    return a;
}
static __device__ __forceinline__ uint32_t b2u(__nv_bfloat162 h) {
    return *reinterpret_cast<uint32_t*>(&h);
}

#define LDSM4(r0, r1, r2, r3, a)                                              \
    asm volatile("ldmatrix.sync.aligned.m8n8.x4.shared.b16 {%0,%1,%2,%3}, [%4];" \
                 : "=r"(r0), "=r"(r1), "=r"(r2), "=r"(r3) : "r"(a))

#define MMA16816(c, a, b0, b1)                                                \
    asm volatile("mma.sync.aligned.m16n8k16.row.col.f32.bf16.bf16.f32 "       \
                 "{%0,%1,%2,%3}, {%4,%5,%6,%7}, {%8,%9}, {%0,%1,%2,%3};"      \
                 : "+f"((c)[0]), "+f"((c)[1]), "+f"((c)[2]), "+f"((c)[3])     \
                 : "r"((a)[0]), "r"((a)[1]), "r"((a)[2]), "r"((a)[3]),        \
                   "r"(b0), "r"(b1))

// ---------------------------------------------------------------------------
// k_rowstats: per-row mean / rstd of inputs.
// ---------------------------------------------------------------------------
__global__ void k_rowstats(const float* __restrict__ x,
                           float* __restrict__ mean, float* __restrict__ rstd) {
    int row = blockIdx.x;
    int t = threadIdx.x;
    float4 v = ((const float4*)(x + (size_t)row * D))[t];
    float s  = v.x + v.y + v.z + v.w;
    float s2 = v.x * v.x + v.y * v.y + v.z * v.z + v.w * v.w;
#pragma unroll
    for (int o = 16; o; o >>= 1) {
        s  += __shfl_down_sync(0xffffffffu, s,  o);
        s2 += __shfl_down_sync(0xffffffffu, s2, o);
    }
    __shared__ float ss[4], ss2[4];
    if ((t & 31) == 0) { ss[t >> 5] = s; ss2[t >> 5] = s2; }
    __syncthreads();
    if (t == 0) {
        float S  = ss[0] + ss[1] + ss[2] + ss[3];
        float S2 = ss2[0] + ss2[1] + ss2[2] + ss2[3];
        float m   = S * (1.0f / 512.0f);
        float var = S2 * (1.0f / 512.0f) - m * m;
        mean[row] = m;
        rstd[row] = rsqrtf(var + 1e-5f);
    }
}

// ---------------------------------------------------------------------------
// k_prepw: W = [Wk | Wv] -> K-major bf16 hi/lo:  Bhi/Blo[n][k], n in [0,1024).
// ---------------------------------------------------------------------------
__global__ void k_prepw(const float* __restrict__ Wk, const float* __restrict__ Wv,
                        __nv_bfloat16* __restrict__ Bhi, __nv_bfloat16* __restrict__ Blo) {
    int idx = blockIdx.x * 256 + threadIdx.x;  // 0..524287
    int k = idx >> 10;
    int n = idx & 1023;
    float w = (n < 512) ? Wk[k * 512 + n] : Wv[k * 512 + (n - 512)];
    __nv_bfloat16 h = __float2bfloat16(w);
    float l = w - __bfloat162float(h);
    Bhi[(size_t)n * 512 + k] = h;
    Blo[(size_t)n * 512 + k] = __float2bfloat16(l);
}

// ---------------------------------------------------------------------------
// k_mmagemm: [K|V] = LN(x) @ [Wk|Wv] + bias, mma.sync bf16 3-pass split.
// Block tile M=128 (blockIdx.y), N=128 (blockIdx.x 0..7). K chunks of 64.
// 8 warps: warp m = (wid&3)*32, warp n = (wid>>2)*64 (warp tile 32x64).
// smem: Ah/Al/Bh/Bl 16KB each (SW128 rows of 128B), LN params after.
// Epilogue stages fp32 in smem (tiles dead) for coalesced stores.
// ---------------------------------------------------------------------------
#define GSM_AHI   0
#define GSM_ALO   16384
#define GSM_BHI   32768
#define GSM_BLO   49152
#define GSM_G     65536
#define GSM_BB    67584
#define GSM_TOTAL 70688   // incl. 1KB align slack

__global__ __launch_bounds__(256, 2)
void k_mmagemm(const float* __restrict__ x,
               const __nv_bfloat16* __restrict__ Bhi,
               const __nv_bfloat16* __restrict__ Blo,
               const float* __restrict__ bk, const float* __restrict__ bv,
               const float* __restrict__ g, const float* __restrict__ bln,
               const float* __restrict__ mean, const float* __restrict__ rstd,
               float* __restrict__ outK, float* __restrict__ outV) {
    extern __shared__ char smraw[];
    char* smb = (char*)((((uintptr_t)smraw) + 1023) & ~(uintptr_t)1023);
    uint32_t sb = smem_u32(smb);
    int tid = threadIdx.x;
    int wid = tid >> 5;
    int lid = tid & 31;
    int n0 = blockIdx.x << 7;
    int m0 = blockIdx.y << 7;

    float* gs  = (float*)(smb + GSM_G);
    float* bsn = (float*)(smb + GSM_BB);
    for (int i = tid; i < 512; i += 256) { gs[i] = g[i]; bsn[i] = bln[i]; }

    const int ln = tid >> 1;          // local row 0..127
    const int kh = (tid & 1) << 5;    // k half 0/32 within 64-chunk
    const float m  = mean[m0 + ln];
    const float rs = rstd[m0 + ln];
    const float* xrow = x + (size_t)(m0 + ln) * D;
    const __nv_bfloat16* bhr = Bhi + (size_t)(n0 + ln) * D;
    const __nv_bfloat16* blr = Blo + (size_t)(n0 + ln) * D;

    const int wm = (wid & 3) << 5;    // warp m offset 0..96
    const int wn = (wid >> 2) << 6;   // warp n offset 0/64

    // Fragment smem addresses (depend only on lane, k-step varies by +32B).
    // A (m16k16 tiles): lane -> row wm+mt*16+(lid&15), byte (lid>>4)*16.
    uint32_t aoffA0, aoffA1, aoffB[4];
    {
        uint32_t r0 = (uint32_t)(wm + (lid & 15));
        uint32_t o0 = (r0 << 7) + ((lid >> 4) << 4);
        aoffA0 = o0;
        uint32_t r1 = r0 + 16;
        aoffA1 = (r1 << 7) + ((lid >> 4) << 4);
#pragma unroll
        for (int gh = 0; gh < 4; ++gh) {
            uint32_t rn = (uint32_t)(wn + (gh << 4) + (lid & 7) + ((lid >> 4) << 3));
            aoffB[gh] = (rn << 7) + (((lid >> 3) & 1) << 4);
        }
    }

    float acc[2][8][4];
#pragma unroll
    for (int i = 0; i < 2; i++)
#pragma unroll
        for (int j = 0; j < 8; j++)
#pragma unroll
            for (int q = 0; q < 4; q++) acc[i][j][q] = 0.f;

    __syncthreads();

    for (int c = 0; c < 8; ++c) {
        const int k0 = c << 6;
        // ---- fill tiles: A (LDG fp32 -> LN -> bf16 hi/lo), B (bf16 copy) ----
#pragma unroll
        for (int j = 0; j < 8; ++j) {
            const int kk = kh + (j << 2);
            float4 a = *(const float4*)(xrow + k0 + kk);
            float v0 = (a.x - m) * rs * gs[k0 + kk + 0] + bsn[k0 + kk + 0];
            float v1 = (a.y - m) * rs * gs[k0 + kk + 1] + bsn[k0 + kk + 1];
            float v2 = (a.z - m) * rs * gs[k0 + kk + 2] + bsn[k0 + kk + 2];
            float v3 = (a.w - m) * rs * gs[k0 + kk + 3] + bsn[k0 + kk + 3];
            __nv_bfloat16 h0 = __float2bfloat16(v0), h1 = __float2bfloat16(v1);
            __nv_bfloat16 h2 = __float2bfloat16(v2), h3 = __float2bfloat16(v3);
            __nv_bfloat162 H01 = __halves2bfloat162(h0, h1);
            __nv_bfloat162 H23 = __halves2bfloat162(h2, h3);
            __nv_bfloat162 L01 = __floats2bfloat162_rn(v0 - __bfloat162float(h0),
                                                       v1 - __bfloat162float(h1));
            __nv_bfloat162 L23 = __floats2bfloat162_rn(v2 - __bfloat162float(h2),
                                                       v3 - __bfloat162float(h3));
            uint32_t off = (ln << 7) + (kk << 1);
            uint32_t sw = off ^ ((off >> 3) & 0x70);
            *(uint2*)(smb + GSM_AHI + sw) = make_uint2(b2u(H01), b2u(H23));
            *(uint2*)(smb + GSM_ALO + sw) = make_uint2(b2u(L01), b2u(L23));
        }
#pragma unroll
        for (int j = 0; j < 4; ++j) {
            uint4 bh  = *(const uint4*)(bhr + k0 + kh + (j << 3));
            uint4 bl  = *(const uint4*)(blr + k0 + kh + (j << 3));
            uint32_t off = (ln << 7) + ((kh + (j << 3)) << 1);
            uint32_t sw = off ^ ((off >> 3) & 0x70);
            *(uint4*)(smb + GSM_BHI + sw) = bh;
            *(uint4*)(smb + GSM_BLO + sw) = bl;
        }
        __syncthreads();

        // ---- compute: 4 k16 steps x (2 m-tiles x 8 n-tiles) x 3 passes ----
#pragma unroll
        for (int s = 0; s < 4; ++s) {
            const uint32_t kb = s << 5;  // +32B per k16
            uint32_t o0 = aoffA0 + kb, o1 = aoffA1 + kb;
            uint32_t sw0 = o0 ^ ((o0 >> 3) & 0x70);
            uint32_t sw1 = o1 ^ ((o1 >> 3) & 0x70);
            uint32_t ah[2][4], al[2][4];
            LDSM4(ah[0][0], ah[0][1], ah[0][2], ah[0][3], sb + GSM_AHI + sw0);
            LDSM4(ah[1][0], ah[1][1], ah[1][2], ah[1][3], sb + GSM_AHI + sw1);
            LDSM4(al[0][0], al[0][1], al[0][2], al[0][3], sb + GSM_ALO + sw0);
            LDSM4(al[1][0], al[1][1], al[1][2], al[1][3], sb + GSM_ALO + sw1);
#pragma unroll
            for (int gh = 0; gh < 4; ++gh) {
                uint32_t ob = aoffB[gh] + kb;
                uint32_t swb = ob ^ ((ob >> 3) & 0x70);
                uint32_t bh[4], bl[4];
                LDSM4(bh[0], bh[1], bh[2], bh[3], sb + GSM_BHI + swb);
                LDSM4(bl[0], bl[1], bl[2], bl[3], sb + GSM_BLO + swb);
#pragma unroll
                for (int mt = 0; mt < 2; ++mt) {
                    MMA16816(acc[mt][gh * 2 + 0], ah[mt], bh[0], bh[1]);
                    MMA16816(acc[mt][gh * 2 + 1], ah[mt], bh[2], bh[3]);
                    MMA16816(acc[mt][gh * 2 + 0], ah[mt], bl[0], bl[1]);
                    MMA16816(acc[mt][gh * 2 + 1], ah[mt], bl[2], bl[3]);
                    MMA16816(acc[mt][gh * 2 + 0], al[mt], bh[0], bh[1]);
                    MMA16816(acc[mt][gh * 2 + 1], al[mt], bh[2], bh[3]);
                }
            }
        }
        __syncthreads();
    }

    // ---- epilogue: regs -> smem stage -> coalesced gmem (+bias) ----
    float* stage = (float*)smb;   // [128][132] fp32, overlays dead tiles
    const int qrow = lid >> 2;
    const int qcol = (lid & 3) << 1;
#pragma unroll
    for (int mt = 0; mt < 2; ++mt) {
#pragma unroll
        for (int nt = 0; nt < 8; ++nt) {
            int r = wm + mt * 16 + qrow;
            int ccol = wn + nt * 8 + qcol;
            *(float2*)&stage[r * 132 + ccol] =
                make_float2(acc[mt][nt][0], acc[mt][nt][1]);
            *(float2*)&stage[(r + 8) * 132 + ccol] =
                make_float2(acc[mt][nt][2], acc[mt][nt][3]);
        }
    }
    __syncthreads();

    const float* bias = (n0 < 512) ? (bk + n0) : (bv + (n0 - 512));
    float* outp = (n0 < 512) ? (outK + n0) : (outV + (n0 - 512));
    {
        int row = tid >> 1;
        int ch = (tid & 1) << 6;
#pragma unroll
        for (int i = 0; i < 16; ++i) {
            int cb = ch + (i << 2);
            float4 o;
            o.x = stage[row * 132 + cb + 0] + bias[cb + 0];
            o.y = stage[row * 132 + cb + 1] + bias[cb + 1];
            o.z = stage[row * 132 + cb + 2] + bias[cb + 2];
            o.w = stage[row * 132 + cb + 3] + bias[cb + 3];
            *(float4*)(outp + (size_t)(m0 + row) * D + cb) = o;
        }
    }
}

// ---------------------------------------------------------------------------
// LN over 64 rows of 512. 64 blocks x 128 threads.
// ---------------------------------------------------------------------------
__global__ void k_ln64(const float* __restrict__ in, const float* __restrict__ g,
                       const float* __restrict__ b, float* __restrict__ out) {
    int r = blockIdx.x, t = threadIdx.x;
    float4 v = ((const float4*)(in + (size_t)r * D))[t];
    float s  = v.x + v.y + v.z + v.w;
    float s2 = v.x * v.x + v.y * v.y + v.z * v.z + v.w * v.w;
#pragma unroll
    for (int o = 16; o; o >>= 1) {
        s  += __shfl_down_sync(0xffffffffu, s,  o);
        s2 += __shfl_down_sync(0xffffffffu, s2, o);
    }
    __shared__ float ss[4], ss2[4];
    __shared__ float sm, srs;
    if ((t & 31) == 0) { ss[t >> 5] = s; ss2[t >> 5] = s2; }
    __syncthreads();
    if (t == 0) {
        float S  = ss[0] + ss[1] + ss[2] + ss[3];
        float S2 = ss2[0] + ss2[1] + ss2[2] + ss2[3];
        float m   = S * (1.0f / 512.0f);
        float var = S2 * (1.0f / 512.0f) - m * m;
        sm = m; srs = rsqrtf(var + 1e-5f);
    }
    __syncthreads();
    float m = sm, rs = srs;
    float4 gg = ((const float4*)g)[t];
    float4 bb = ((const float4*)b)[t];
    float4 o;
    o.x = (v.x - m) * rs * gg.x + bb.x;
    o.y = (v.y - m) * rs * gg.y + bb.y;
    o.z = (v.z - m) * rs * gg.z + bb.z;
    o.w = (v.w - m) * rs * gg.w + bb.w;
    ((float4*)(out + (size_t)r * D))[t] = o;
}

// ---------------------------------------------------------------------------
// Small GEMM: C[64, ncols] = A[64,512] @ W (+bias)(relu?)(+resid).
// ---------------------------------------------------------------------------
template <int TRANSW>
__global__ __launch_bounds__(256) void k_gemm64(
    const float* __restrict__ A, const float* __restrict__ W,
    const float* __restrict__ bias, const float* __restrict__ resid,
    float* __restrict__ out, int ncols, int relu) {
    __shared__ float As[32][64];
    __shared__ float Ws[32][33];
    int tid  = threadIdx.x;
    int col0 = blockIdx.x << 5;
    int ty = tid >> 5, tx = tid & 31;
    int ar0 = tid >> 3, akp = (tid & 7) << 2;

    float acc[8];
#pragma unroll
    for (int i = 0; i < 8; i++) acc[i] = 0.f;

    for (int kt = 0; kt < 512; kt += 32) {
        float4 a0 = *(const float4*)(A + (size_t)ar0 * D + kt + akp);
        float4 a1 = *(const float4*)(A + (size_t)(ar0 + 32) * D + kt + akp);
        As[akp + 0][ar0] = a0.x; As[akp + 1][ar0] = a0.y;
        As[akp + 2][ar0] = a0.z; As[akp + 3][ar0] = a0.w;
        As[akp + 0][ar0 + 32] = a1.x; As[akp + 1][ar0 + 32] = a1.y;
        As[akp + 2][ar0 + 32] = a1.z; As[akp + 3][ar0 + 32] = a1.w;
        if (TRANSW) {
            int wn = tid >> 3, wkp = (tid & 7) << 2;
            float4 w0 = *(const float4*)(W + (size_t)(col0 + wn) * D + kt + wkp);
            Ws[wkp + 0][wn] = w0.x; Ws[wkp + 1][wn] = w0.y;
            Ws[wkp + 2][wn] = w0.z; Ws[wkp + 3][wn] = w0.w;
        } else {
            int wk = tid >> 3, wnp = (tid & 7) << 2;
            float4 w0 = *(const float4*)(W + (size_t)(kt + wk) * ncols + col0 + wnp);
            Ws[wk][wnp + 0] = w0.x; Ws[wk][wnp + 1] = w0.y;
            Ws[wk][wnp + 2] = w0.z; Ws[wk][wnp + 3] = w0.w;
        }
        __syncthreads();
#pragma unroll
        for (int kk = 0; kk < 32; kk++) {
            float w = Ws[kk][tx];
            float a[8];
            *(float4*)&a[0] = *(const float4*)&As[kk][ty << 3];
            *(float4*)&a[4] = *(const float4*)&As[kk][(ty << 3) + 4];
#pragma unroll
            for (int r = 0; r < 8; r++) acc[r] += a[r] * w;
        }
        __syncthreads();
    }

    float bvv = bias[col0 + tx];
#pragma unroll
    for (int r = 0; r < 8; r++) {
        int row = (ty << 3) + r;
        float val = acc[r] + bvv;
        if (relu) val = fmaxf(val, 0.f);
        if (resid) val += resid[(size_t)row * D + col0 + tx];
        out[(size_t)row * ncols + col0 + tx] = val;
    }
}

// ---------------------------------------------------------------------------
// dots + softmax over the slot axis.
// ---------------------------------------------------------------------------
__global__ __launch_bounds__(128) void k_dots(const float* __restrict__ q,
                                              const float* __restrict__ k,
                                              float* __restrict__ attn_pre) {
    int b = blockIdx.y, j0 = blockIdx.x << 7;
    int t = threadIdx.x;
    __shared__ float qs0[512], qs1[512];
    __shared__ float ks[128][65];
    {
        float4 q0 = ((const float4*)(q + (size_t)(b * 2 + 0) * D))[t];
        float4 q1 = ((const float4*)(q + (size_t)(b * 2 + 1) * D))[t];
        *(float4*)&qs0[t << 2] = q0;
        *(float4*)&qs1[t << 2] = q1;
    }
    float d0 = 0.f, d1 = 0.f;
    const float* kb = k + ((size_t)b * 2048 + j0) * D;
    for (int kc = 0; kc < 512; kc += 64) {
        __syncthreads();
#pragma unroll
        for (int i = 0; i < 16; i++) {
            int f = t + (i << 7);
            int j = f >> 4, kp = (f & 15) << 2;
            float4 kv = *(const float4*)(kb + (size_t)j * D + kc + kp);
            ks[j][kp + 0] = kv.x; ks[j][kp + 1] = kv.y;
            ks[j][kp + 2] = kv.z; ks[j][kp + 3] = kv.w;
        }
        __syncthreads();
#pragma unroll
        for (int kk = 0; kk < 64; kk++) {
            float kv = ks[t][kk];
            d0 += kv * qs0[kc + kk];
            d1 += kv * qs1[kc + kk];
        }
    }
    const float SC = 0.044194173824159216f;
    d0 *= SC; d1 *= SC;
    float mx = fmaxf(d0, d1);
    float e0 = expf(d0 - mx), e1 = expf(d1 - mx);
    float inv = 1.0f / (e0 + e1);
    attn_pre[b * 4096 + (j0 + t)]        = e0 * inv;
    attn_pre[b * 4096 + 2048 + (j0 + t)] = e1 * inv;
}

// ---------------------------------------------------------------------------
// updates = (v^T @ attn_row) / (rowsum + eps)
// ---------------------------------------------------------------------------
__global__ __launch_bounds__(128) void k_upd(const float* __restrict__ attn_pre,
                                             const float* __restrict__ v,
                                             float* __restrict__ upd) {
    int b = blockIdx.y, d0 = blockIdx.x << 7, t = threadIdx.x;
    const float* a0p = attn_pre + b * 4096;
    const float* a1p = a0p + 2048;
    float s0 = 0.f, s1 = 0.f;
    for (int j = t; j < 2048; j += 128) { s0 += a0p[j]; s1 += a1p[j]; }
#pragma unroll
    for (int o = 16; o; o >>= 1) {
        s0 += __shfl_down_sync(0xffffffffu, s0, o);
        s1 += __shfl_down_sync(0xffffffffu, s1, o);
    }
    __shared__ float r0[4], r1[4];
    if ((t & 31) == 0) { r0[t >> 5] = s0; r1[t >> 5] = s1; }
    __syncthreads();
    float inv0 = 1.0f / (r0[0] + r0[1] + r0[2] + r0[3] + 1e-8f);
    float inv1 = 1.0f / (r1[0] + r1[1] + r1[2] + r1[3] + 1e-8f);

    __shared__ float w0[256], w1[256];
    float acc0 = 0.f, acc1 = 0.f;
    const float* vb = v + (size_t)b * 2048 * D + d0 + t;
    for (int jc = 0; jc < 2048; jc += 256) {
        __syncthreads();
        w0[t] = a0p[jc + t]; w0[t + 128] = a0p[jc + t + 128];
        w1[t] = a1p[jc + t]; w1[t + 128] = a1p[jc + t + 128];
        __syncthreads();
#pragma unroll 8
        for (int jj = 0; jj < 256; jj++) {
            float vv = vb[(size_t)(jc + jj) * D];
            acc0 += vv * w0[jj];
            acc1 += vv * w1[jj];
        }
    }
    upd[(size_t)(b * 2 + 0) * D + d0 + t] = acc0 * inv0;
    upd[(size_t)(b * 2 + 1) * D + d0 + t] = acc1 * inv1;
}

// ---------------------------------------------------------------------------
// attn output normalize
// ---------------------------------------------------------------------------
__global__ void k_attnnorm(const float* __restrict__ attn_pre,
                           float* __restrict__ attn_out) {
    int r = blockIdx.x, t = threadIdx.x;
    size_t off = (size_t)(r >> 1) * 4096 + (size_t)(r & 1) * 2048;
    const float* p = attn_pre + off;
    float s = 0.f;
    for (int j = t; j < 2048; j += 256) s += p[j];
#pragma unroll
    for (int o = 16; o; o >>= 1) s += __shfl_down_sync(0xffffffffu, s, o);
    __shared__ float ss[8];
    if ((t & 31) == 0) ss[t >> 5] = s;
    __syncthreads();
    float inv = 1.0f / (ss[0] + ss[1] + ss[2] + ss[3] + ss[4] + ss[5] + ss[6] + ss[7] + 1e-8f);
    float* o = attn_out + off;
    for (int j = t; j < 2048; j += 256) o[j] = p[j] * inv;
}

// ---------------------------------------------------------------------------
// GRU gates
// ---------------------------------------------------------------------------
__global__ void k_gru2(const float* __restrict__ gx, const float* __restrict__ gh,
                       const float* __restrict__ slots, float* __restrict__ hnew) {
    int idx = blockIdx.x * 256 + threadIdx.x;
    int r = idx >> 9, d = idx & 511;
    const float* gxr = gx + (size_t)r * 1536;
    const float* ghr = gh + (size_t)r * 1536;
    float rg = sigmoidf_(gxr[d] + ghr[d]);
    float z  = sigmoidf_(gxr[512 + d] + ghr[512 + d]);
    float n  = tanhf(gxr[1024 + d] + rg * ghr[1024 + d]);
    hnew[idx] = (1.0f - z) * n + z * slots[idx];
}

// ---------------------------------------------------------------------------
// host
// ---------------------------------------------------------------------------
extern "C" void kernel_launch(void* const* d_in, const int* in_sizes, int n_in,
                              void* d_out, int out_size) {
    (void)in_sizes; (void)n_in; (void)out_size;
    const float* inputs     = (const float*)d_in[0];
    const float* init_slots = (const float*)d_in[1];
    const float* Wq  = (const float*)d_in[2];
    const float* bq  = (const float*)d_in[3];
    const float* Wk  = (const float*)d_in[4];
    const float* bk  = (const float*)d_in[5];
    const float* Wv  = (const float*)d_in[6];
    const float* bv  = (const float*)d_in[7];
    const float* ln_in_g = (const float*)d_in[8];
    const float* ln_in_b = (const float*)d_in[9];
    const float* ln_s_g  = (const float*)d_in[10];
    const float* ln_s_b  = (const float*)d_in[11];
    const float* ln_f_g  = (const float*)d_in[12];
    const float* ln_f_b  = (const float*)d_in[13];
    const float* gru_wih = (const float*)d_in[14];
    const float* gru_whh = (const float*)d_in[15];
    const float* gru_bih = (const float*)d_in[16];
    const float* gru_bhh = (const float*)d_in[17];
    const float* W1 = (const float*)d_in[18];
    const float* b1 = (const float*)d_in[19];
    const float* W2 = (const float*)d_in[20];
    const float* b2 = (const float*)d_in[21];

    float* out      = (float*)d_out;
    float* slots    = out;
    float* qout     = out + 32768;
    float* kout     = out + 65536;
    float* attn_out = out + 65536 + 33554432;

    float* S = nullptr;
    cudaGetSymbolAddress((void**)&S, g_scratch);
    float* v    = S + OFF_V;
    float* mean = S + OFF_MEAN;
    float* rstd = S + OFF_RSTD;
    float* attn = S + OFF_ATTN;
    float* sln  = S + OFF_SLN;
    float* upd  = S + OFF_UPD;
    float* gx   = S + OFF_GX;
    float* gh   = S + OFF_GH;
    float* hnew = S + OFF_HNEW;
    float* hln  = S + OFF_HLN;
    float* tbuf = S + OFF_T;
    __nv_bfloat16* whi = (__nv_bfloat16*)(S + OFF_WHI);
    __nv_bfloat16* wlo = (__nv_bfloat16*)(S + OFF_WLO);

    cudaFuncSetAttribute(k_mmagemm, cudaFuncAttributeMaxDynamicSharedMemorySize,
                         GSM_TOTAL);

    cudaMemcpyAsync(slots, init_slots, 32768 * sizeof(float),
                    cudaMemcpyDeviceToDevice);

    k_prepw<<<2048, 256>>>(Wk, Wv, whi, wlo);
    k_rowstats<<<NROWS, 128>>>(inputs, mean, rstd);
    k_mmagemm<<<dim3(8, 512), 256, GSM_TOTAL>>>(inputs, whi, wlo, bk, bv,
                                                ln_in_g, ln_in_b, mean, rstd,
                                                kout, v);

    for (int it = 0; it < 3; ++it) {
        k_ln64<<<64, 128>>>(slots, ln_s_g, ln_s_b, sln);
        k_gemm64<0><<<16, 256>>>(sln, Wq, bq, nullptr, qout, 512, 0);
        k_dots<<<dim3(16, 32), 128>>>(qout, kout, attn);
        k_upd<<<dim3(4, 32), 128>>>(attn, v, upd);
        k_attnnorm<<<64, 256>>>(attn, attn_out);
        k_gemm64<1><<<48, 256>>>(upd, gru_wih, gru_bih, nullptr, gx, 1536, 0);
        k_gemm64<1><<<48, 256>>>(slots, gru_whh, gru_bhh, nullptr, gh, 1536, 0);
        k_gru2<<<128, 256>>>(gx, gh, slots, hnew);
        k_ln64<<<64, 128>>>(hnew, ln_f_g, ln_f_b, hln);
        k_gemm64<0><<<16, 256>>>(hln, W1, b1, nullptr, tbuf, 512, 1);
        k_gemm64<0><<<16, 256>>>(tbuf, W2, b2, hnew, slots, 512, 0);
    }
}

// round 6
// speedup vs baseline: 1.2211x; 1.0345x over previous
#include <cuda_runtime.h>
#include <cuda_bf16.h>
#include <math.h>
#include <stdint.h>

// ---------------------------------------------------------------------------
// SlotAttention. B=32, N=2048, DIN=DOUT=HID=512, S=2, ITERS=3.
// Big LN+GEMM (k,v): pipelined double-buffered mma.sync bf16 3-pass split.
// Output: slots[32,2,512], q[32,2,512], k[32,2048,512], attn[32,2,2048].
// ---------------------------------------------------------------------------

#define NROWS 65536
#define D 512

// ---- scratch ----
#define OFF_V     0
#define OFF_MEAN  33554432
#define OFF_RSTD  (33554432 + 65536)
#define OFF_ATTN  (33554432 + 131072)
#define OFF_SLN   (OFF_ATTN + 131072)
#define OFF_UPD   (OFF_SLN  + 32768)
#define OFF_GX    (OFF_UPD  + 32768)
#define OFF_GH    (OFF_GX   + 98304)
#define OFF_HNEW  (OFF_GH   + 98304)
#define OFF_HLN   (OFF_HNEW + 32768)
#define OFF_T     (OFF_HLN  + 32768)
#define OFF_WHI   (OFF_T    + 32768)   // 1024x512 bf16
#define OFF_WLO   (OFF_WHI  + 262144)
#define SCRATCH_FLOATS (OFF_WLO + 262144)

__device__ __align__(256) float g_scratch[SCRATCH_FLOATS];

static __device__ __forceinline__ float sigmoidf_(float x) {
    return 1.0f / (1.0f + expf(-x));
}

static __device__ __forceinline__ uint32_t smem_u32(const void* p) {
    uint32_t a;
    asm("{ .reg .u64 t; cvta.to.shared.u64 t, %1; cvt.u32.u64 %0, t; }"
        : "=r"(a) : "l"(p));
    return a;
}
static __device__ __forceinline__ uint32_t b2u(__nv_bfloat162 h) {
    return *reinterpret_cast<uint32_t*>(&h);
}

#define LDSM4(r0, r1, r2, r3, a)                                              \
    asm volatile("ldmatrix.sync.aligned.m8n8.x4.shared.b16 {%0,%1,%2,%3}, [%4];" \
                 : "=r"(r0), "=r"(r1), "=r"(r2), "=r"(r3) : "r"(a))

#define MMA16816(c, a, b0, b1)                                                \
    asm volatile("mma.sync.aligned.m16n8k16.row.col.f32.bf16.bf16.f32 "       \
                 "{%0,%1,%2,%3}, {%4,%5,%6,%7}, {%8,%9}, {%0,%1,%2,%3};"      \
                 : "+f"((c)[0]), "+f"((c)[1]), "+f"((c)[2]), "+f"((c)[3])     \
                 : "r"((a)[0]), "r"((a)[1]), "r"((a)[2]), "r"((a)[3]),        \
                   "r"(b0), "r"(b1))

#define CP16(dst, src)                                                        \
    asm volatile("cp.async.cg.shared.global [%0], [%1], 16;"                  \
                 :: "r"(dst), "l"(src))
#define CP_COMMIT() asm volatile("cp.async.commit_group;" ::: "memory")
#define CP_WAIT0()  asm volatile("cp.async.wait_group 0;" ::: "memory")

// ---------------------------------------------------------------------------
// k_rowstats
// ---------------------------------------------------------------------------
__global__ void k_rowstats(const float* __restrict__ x,
                           float* __restrict__ mean, float* __restrict__ rstd) {
    int row = blockIdx.x;
    int t = threadIdx.x;
    float4 v = ((const float4*)(x + (size_t)row * D))[t];
    float s  = v.x + v.y + v.z + v.w;
    float s2 = v.x * v.x + v.y * v.y + v.z * v.z + v.w * v.w;
#pragma unroll
    for (int o = 16; o; o >>= 1) {
        s  += __shfl_down_sync(0xffffffffu, s,  o);
        s2 += __shfl_down_sync(0xffffffffu, s2, o);
    }
    __shared__ float ss[4], ss2[4];
    if ((t & 31) == 0) { ss[t >> 5] = s; ss2[t >> 5] = s2; }
    __syncthreads();
    if (t == 0) {
        float S  = ss[0] + ss[1] + ss[2] + ss[3];
        float S2 = ss2[0] + ss2[1] + ss2[2] + ss2[3];
        float m   = S * (1.0f / 512.0f);
        float var = S2 * (1.0f / 512.0f) - m * m;
        mean[row] = m;
        rstd[row] = rsqrtf(var + 1e-5f);
    }
}

// ---------------------------------------------------------------------------
// k_prepw: W = [Wk | Wv] -> K-major bf16 hi/lo.
// ---------------------------------------------------------------------------
__global__ void k_prepw(const float* __restrict__ Wk, const float* __restrict__ Wv,
                        __nv_bfloat16* __restrict__ Bhi, __nv_bfloat16* __restrict__ Blo) {
    int idx = blockIdx.x * 256 + threadIdx.x;
    int k = idx >> 10;
    int n = idx & 1023;
    float w = (n < 512) ? Wk[k * 512 + n] : Wv[k * 512 + (n - 512)];
    __nv_bfloat16 h = __float2bfloat16(w);
    float l = w - __bfloat162float(h);
    Bhi[(size_t)n * 512 + k] = h;
    Blo[(size_t)n * 512 + k] = __float2bfloat16(l);
}

// ---------------------------------------------------------------------------
// k_mmagemm (pipelined): [K|V] = LN(x) @ [Wk|Wv] + bias.
// Double-buffered smem (2 x 64KB), cp.async for B, A prefetch in regs.
// ---------------------------------------------------------------------------
#define PBUF  65536
#define PAHI  0
#define PALO  16384
#define PBHI  32768
#define PBLO  49152
#define PG    131072
#define PBB   133120
#define PTOT  136192

__global__ __launch_bounds__(256, 1)
void k_mmagemm(const float* __restrict__ x,
               const __nv_bfloat16* __restrict__ Bhi,
               const __nv_bfloat16* __restrict__ Blo,
               const float* __restrict__ bk, const float* __restrict__ bv,
               const float* __restrict__ g, const float* __restrict__ bln,
               const float* __restrict__ mean, const float* __restrict__ rstd,
               float* __restrict__ outK, float* __restrict__ outV) {
    extern __shared__ char smraw[];
    char* smb = (char*)((((uintptr_t)smraw) + 1023) & ~(uintptr_t)1023);
    uint32_t sb = smem_u32(smb);
    int tid = threadIdx.x;
    int wid = tid >> 5;
    int lid = tid & 31;
    int n0 = blockIdx.x << 7;
    int m0 = blockIdx.y << 7;

    float* gs  = (float*)(smb + PG);
    float* bsn = (float*)(smb + PBB);
    for (int i = tid; i < 512; i += 256) { gs[i] = g[i]; bsn[i] = bln[i]; }

    const int ln = tid >> 1;
    const int kh = (tid & 1) << 5;
    const float m  = mean[m0 + ln];
    const float rs = rstd[m0 + ln];
    const float* xrow = x + (size_t)(m0 + ln) * D;
    const __nv_bfloat16* bhr = Bhi + (size_t)(n0 + ln) * D;
    const __nv_bfloat16* blr = Blo + (size_t)(n0 + ln) * D;

    const int wm = (wid & 3) << 5;
    const int wn = (wid >> 2) << 6;

    uint32_t aoffA0, aoffA1, aoffB[4];
    {
        uint32_t r0 = (uint32_t)(wm + (lid & 15));
        aoffA0 = (r0 << 7) + ((lid >> 4) << 4);
        uint32_t r1 = r0 + 16;
        aoffA1 = (r1 << 7) + ((lid >> 4) << 4);
#pragma unroll
        for (int gh = 0; gh < 4; ++gh) {
            uint32_t rn = (uint32_t)(wn + (gh << 4) + (lid & 7) + ((lid >> 4) << 3));
            aoffB[gh] = (rn << 7) + (((lid >> 3) & 1) << 4);
        }
    }

    float acc[2][8][4];
#pragma unroll
    for (int i = 0; i < 2; i++)
#pragma unroll
        for (int j = 0; j < 8; j++)
#pragma unroll
            for (int q = 0; q < 4; q++) acc[i][j][q] = 0.f;

    __syncthreads();   // gs/bsn visible before any transform

    float4 ra[8];

    // B cp.async for chunk c into buffer p
    auto cpB = [&](int c, int p) {
        const int k0 = c << 6;
#pragma unroll
        for (int j = 0; j < 4; ++j) {
            uint32_t off = (ln << 7) + ((kh + (j << 3)) << 1);
            uint32_t sw = off ^ ((off >> 3) & 0x70);
            CP16(sb + p * PBUF + PBHI + sw, bhr + k0 + kh + (j << 3));
            CP16(sb + p * PBUF + PBLO + sw, blr + k0 + kh + (j << 3));
        }
        CP_COMMIT();
    };
    auto ldgA = [&](int c) {
        const int k0 = c << 6;
#pragma unroll
        for (int j = 0; j < 8; ++j)
            ra[j] = *(const float4*)(xrow + k0 + kh + (j << 2));
    };
    auto stsA = [&](int c, int p) {
        const int k0 = c << 6;
#pragma unroll
        for (int j = 0; j < 8; ++j) {
            const int kk = kh + (j << 2);
            float4 a = ra[j];
            float v0 = (a.x - m) * rs * gs[k0 + kk + 0] + bsn[k0 + kk + 0];
            float v1 = (a.y - m) * rs * gs[k0 + kk + 1] + bsn[k0 + kk + 1];
            float v2 = (a.z - m) * rs * gs[k0 + kk + 2] + bsn[k0 + kk + 2];
            float v3 = (a.w - m) * rs * gs[k0 + kk + 3] + bsn[k0 + kk + 3];
            __nv_bfloat16 h0 = __float2bfloat16(v0), h1 = __float2bfloat16(v1);
            __nv_bfloat16 h2 = __float2bfloat16(v2), h3 = __float2bfloat16(v3);
            __nv_bfloat162 H01 = __halves2bfloat162(h0, h1);
            __nv_bfloat162 H23 = __halves2bfloat162(h2, h3);
            __nv_bfloat162 L01 = __floats2bfloat162_rn(v0 - __bfloat162float(h0),
                                                       v1 - __bfloat162float(h1));
            __nv_bfloat162 L23 = __floats2bfloat162_rn(v2 - __bfloat162float(h2),
                                                       v3 - __bfloat162float(h3));
            uint32_t off = (ln << 7) + (kk << 1);
            uint32_t sw = off ^ ((off >> 3) & 0x70);
            *(uint2*)(smb + p * PBUF + PAHI + sw) = make_uint2(b2u(H01), b2u(H23));
            *(uint2*)(smb + p * PBUF + PALO + sw) = make_uint2(b2u(L01), b2u(L23));
        }
    };
    auto compute = [&](int p) {
        const uint32_t base = sb + p * PBUF;
#pragma unroll
        for (int s = 0; s < 4; ++s) {
            const uint32_t kb = s << 5;
            uint32_t o0 = aoffA0 + kb, o1 = aoffA1 + kb;
            uint32_t sw0 = o0 ^ ((o0 >> 3) & 0x70);
            uint32_t sw1 = o1 ^ ((o1 >> 3) & 0x70);
            uint32_t ah[2][4], al[2][4];
            LDSM4(ah[0][0], ah[0][1], ah[0][2], ah[0][3], base + PAHI + sw0);
            LDSM4(ah[1][0], ah[1][1], ah[1][2], ah[1][3], base + PAHI + sw1);
            LDSM4(al[0][0], al[0][1], al[0][2], al[0][3], base + PALO + sw0);
            LDSM4(al[1][0], al[1][1], al[1][2], al[1][3], base + PALO + sw1);
#pragma unroll
            for (int gh = 0; gh < 4; ++gh) {
                uint32_t ob = aoffB[gh] + kb;
                uint32_t swb = ob ^ ((ob >> 3) & 0x70);
                uint32_t bh[4], bl[4];
                LDSM4(bh[0], bh[1], bh[2], bh[3], base + PBHI + swb);
                LDSM4(bl[0], bl[1], bl[2], bl[3], base + PBLO + swb);
#pragma unroll
                for (int mt = 0; mt < 2; ++mt) {
                    MMA16816(acc[mt][gh * 2 + 0], ah[mt], bh[0], bh[1]);
                    MMA16816(acc[mt][gh * 2 + 1], ah[mt], bh[2], bh[3]);
                    MMA16816(acc[mt][gh * 2 + 0], ah[mt], bl[0], bl[1]);
                    MMA16816(acc[mt][gh * 2 + 1], ah[mt], bl[2], bl[3]);
                    MMA16816(acc[mt][gh * 2 + 0], al[mt], bh[0], bh[1]);
                    MMA16816(acc[mt][gh * 2 + 1], al[mt], bh[2], bh[3]);
                }
            }
        }
    };

    // ---- prologue: fill buffer 0, prefetch A chunk 1 ----
    ldgA(0);
    cpB(0, 0);
    stsA(0, 0);
    ldgA(1);
    CP_WAIT0();
    __syncthreads();

    // ---- pipelined main loop ----
    for (int c = 0; c < 8; ++c) {
        const int p = c & 1;
        if (c < 7) cpB(c + 1, p ^ 1);     // arrives during compute
        compute(p);
        if (c < 7) {
            stsA(c + 1, p ^ 1);           // A chunk c+1 from regs
            if (c < 6) ldgA(c + 2);       // prefetch next A
            CP_WAIT0();
            __syncthreads();
        }
    }
    __syncthreads();   // all warps done before stage overlays buffers

    // ---- epilogue: regs -> smem stage -> coalesced gmem (+bias) ----
    float* stage = (float*)smb;   // [128][132]
    const int qrow = lid >> 2;
    const int qcol = (lid & 3) << 1;
#pragma unroll
    for (int mt = 0; mt < 2; ++mt) {
#pragma unroll
        for (int nt = 0; nt < 8; ++nt) {
            int r = wm + mt * 16 + qrow;
            int ccol = wn + nt * 8 + qcol;
            *(float2*)&stage[r * 132 + ccol] =
                make_float2(acc[mt][nt][0], acc[mt][nt][1]);
            *(float2*)&stage[(r + 8) * 132 + ccol] =
                make_float2(acc[mt][nt][2], acc[mt][nt][3]);
        }
    }
    __syncthreads();

    const float* bias = (n0 < 512) ? (bk + n0) : (bv + (n0 - 512));
    float* outp = (n0 < 512) ? (outK + n0) : (outV + (n0 - 512));
    {
        int row = tid >> 1;
        int ch = (tid & 1) << 6;
#pragma unroll
        for (int i = 0; i < 16; ++i) {
            int cb = ch + (i << 2);
            float4 o;
            o.x = stage[row * 132 + cb + 0] + bias[cb + 0];
            o.y = stage[row * 132 + cb + 1] + bias[cb + 1];
            o.z = stage[row * 132 + cb + 2] + bias[cb + 2];
            o.w = stage[row * 132 + cb + 3] + bias[cb + 3];
            *(float4*)(outp + (size_t)(m0 + row) * D + cb) = o;
        }
    }
}

// ---------------------------------------------------------------------------
// LN over 64 rows of 512.
// ---------------------------------------------------------------------------
__global__ void k_ln64(const float* __restrict__ in, const float* __restrict__ g,
                       const float* __restrict__ b, float* __restrict__ out) {
    int r = blockIdx.x, t = threadIdx.x;
    float4 v = ((const float4*)(in + (size_t)r * D))[t];
    float s  = v.x + v.y + v.z + v.w;
    float s2 = v.x * v.x + v.y * v.y + v.z * v.z + v.w * v.w;
#pragma unroll
    for (int o = 16; o; o >>= 1) {
        s  += __shfl_down_sync(0xffffffffu, s,  o);
        s2 += __shfl_down_sync(0xffffffffu, s2, o);
    }
    __shared__ float ss[4], ss2[4];
    __shared__ float sm, srs;
    if ((t & 31) == 0) { ss[t >> 5] = s; ss2[t >> 5] = s2; }
    __syncthreads();
    if (t == 0) {
        float S  = ss[0] + ss[1] + ss[2] + ss[3];
        float S2 = ss2[0] + ss2[1] + ss2[2] + ss2[3];
        float m   = S * (1.0f / 512.0f);
        float var = S2 * (1.0f / 512.0f) - m * m;
        sm = m; srs = rsqrtf(var + 1e-5f);
    }
    __syncthreads();
    float m = sm, rs = srs;
    float4 gg = ((const float4*)g)[t];
    float4 bb = ((const float4*)b)[t];
    float4 o;
    o.x = (v.x - m) * rs * gg.x + bb.x;
    o.y = (v.y - m) * rs * gg.y + bb.y;
    o.z = (v.z - m) * rs * gg.z + bb.z;
    o.w = (v.w - m) * rs * gg.w + bb.w;
    ((float4*)(out + (size_t)r * D))[t] = o;
}

// ---------------------------------------------------------------------------
// Small GEMM with register prefetch; gridDim.y selects (A,out) pair (dual mode).
// C[64, ncols] = A[64,512] @ W (+bias)(relu?)(+resid).
// ---------------------------------------------------------------------------
template <int TRANSW>
__global__ __launch_bounds__(256) void k_gemm64(
    const float* __restrict__ A, const float* __restrict__ A2,
    const float* __restrict__ W,
    const float* __restrict__ bias, const float* __restrict__ resid,
    float* __restrict__ out, float* __restrict__ out2, int ncols, int relu) {
    __shared__ float As[32][64];
    __shared__ float Ws[32][33];
    int tid  = threadIdx.x;
    int col0 = blockIdx.x << 5;
    int ty = tid >> 5, tx = tid & 31;
    int ar0 = tid >> 3, akp = (tid & 7) << 2;

    const float* Ause = blockIdx.y ? A2 : A;
    float* outuse = blockIdx.y ? out2 : out;

    float acc[8];
#pragma unroll
    for (int i = 0; i < 8; i++) acc[i] = 0.f;

    int wn = tid >> 3, wkp = (tid & 7) << 2;   // TRANSW=1 mapping
    int wk = tid >> 3, wnp = (tid & 7) << 2;   // TRANSW=0 mapping

    // prefetch tile 0
    float4 pa0 = *(const float4*)(Ause + (size_t)ar0 * D + akp);
    float4 pa1 = *(const float4*)(Ause + (size_t)(ar0 + 32) * D + akp);
    float4 pw;
    if (TRANSW)
        pw = *(const float4*)(W + (size_t)(col0 + wn) * D + wkp);
    else
        pw = *(const float4*)(W + (size_t)wk * ncols + col0 + wnp);

    for (int kt = 0; kt < 512; kt += 32) {
        As[akp + 0][ar0] = pa0.x; As[akp + 1][ar0] = pa0.y;
        As[akp + 2][ar0] = pa0.z; As[akp + 3][ar0] = pa0.w;
        As[akp + 0][ar0 + 32] = pa1.x; As[akp + 1][ar0 + 32] = pa1.y;
        As[akp + 2][ar0 + 32] = pa1.z; As[akp + 3][ar0 + 32] = pa1.w;
        if (TRANSW) {
            Ws[wkp + 0][wn] = pw.x; Ws[wkp + 1][wn] = pw.y;
            Ws[wkp + 2][wn] = pw.z; Ws[wkp + 3][wn] = pw.w;
        } else {
            Ws[wk][wnp + 0] = pw.x; Ws[wk][wnp + 1] = pw.y;
            Ws[wk][wnp + 2] = pw.z; Ws[wk][wnp + 3] = pw.w;
        }
        __syncthreads();
        if (kt + 32 < 512) {   // prefetch next tile during compute
            pa0 = *(const float4*)(Ause + (size_t)ar0 * D + kt + 32 + akp);
            pa1 = *(const float4*)(Ause + (size_t)(ar0 + 32) * D + kt + 32 + akp);
            if (TRANSW)
                pw = *(const float4*)(W + (size_t)(col0 + wn) * D + kt + 32 + wkp);
            else
                pw = *(const float4*)(W + (size_t)(kt + 32 + wk) * ncols + col0 + wnp);
        }
#pragma unroll
        for (int kk = 0; kk < 32; kk++) {
            float w = Ws[kk][tx];
            float a[8];
            *(float4*)&a[0] = *(const float4*)&As[kk][ty << 3];
            *(float4*)&a[4] = *(const float4*)&As[kk][(ty << 3) + 4];
#pragma unroll
            for (int r = 0; r < 8; r++) acc[r] += a[r] * w;
        }
        __syncthreads();
    }

    float bvv = bias[col0 + tx];
#pragma unroll
    for (int r = 0; r < 8; r++) {
        int row = (ty << 3) + r;
        float val = acc[r] + bvv;
        if (relu) val = fmaxf(val, 0.f);
        if (resid) val += resid[(size_t)row * D + col0 + tx];
        outuse[(size_t)row * ncols + col0 + tx] = val;
    }
}

// ---------------------------------------------------------------------------
// dots + softmax over the slot axis.
// ---------------------------------------------------------------------------
__global__ __launch_bounds__(128) void k_dots(const float* __restrict__ q,
                                              const float* __restrict__ k,
                                              float* __restrict__ attn_pre) {
    int b = blockIdx.y, j0 = blockIdx.x << 7;
    int t = threadIdx.x;
    __shared__ float qs0[512], qs1[512];
    __shared__ float ks[128][65];
    {
        float4 q0 = ((const float4*)(q + (size_t)(b * 2 + 0) * D))[t];
        float4 q1 = ((const float4*)(q + (size_t)(b * 2 + 1) * D))[t];
        *(float4*)&qs0[t << 2] = q0;
        *(float4*)&qs1[t << 2] = q1;
    }
    float d0 = 0.f, d1 = 0.f;
    const float* kb = k + ((size_t)b * 2048 + j0) * D;
    for (int kc = 0; kc < 512; kc += 64) {
        __syncthreads();
#pragma unroll
        for (int i = 0; i < 16; i++) {
            int f = t + (i << 7);
            int j = f >> 4, kp = (f & 15) << 2;
            float4 kv = *(const float4*)(kb + (size_t)j * D + kc + kp);
            ks[j][kp + 0] = kv.x; ks[j][kp + 1] = kv.y;
            ks[j][kp + 2] = kv.z; ks[j][kp + 3] = kv.w;
        }
        __syncthreads();
#pragma unroll
        for (int kk = 0; kk < 64; kk++) {
            float kv = ks[t][kk];
            d0 += kv * qs0[kc + kk];
            d1 += kv * qs1[kc + kk];
        }
    }
    const float SC = 0.044194173824159216f;
    d0 *= SC; d1 *= SC;
    float mx = fmaxf(d0, d1);
    float e0 = expf(d0 - mx), e1 = expf(d1 - mx);
    float inv = 1.0f / (e0 + e1);
    attn_pre[b * 4096 + (j0 + t)]        = e0 * inv;
    attn_pre[b * 4096 + 2048 + (j0 + t)] = e1 * inv;
}

// ---------------------------------------------------------------------------
// updates = (v^T @ attn_row) / (rowsum + eps); d-tile 0 also writes attn_out.
// ---------------------------------------------------------------------------
__global__ __launch_bounds__(128) void k_upd(const float* __restrict__ attn_pre,
                                             const float* __restrict__ v,
                                             float* __restrict__ upd,
                                             float* __restrict__ attn_out) {
    int b = blockIdx.y, d0 = blockIdx.x << 7, t = threadIdx.x;
    const float* a0p = attn_pre + b * 4096;
    const float* a1p = a0p + 2048;
    float s0 = 0.f, s1 = 0.f;
    for (int j = t; j < 2048; j += 128) { s0 += a0p[j]; s1 += a1p[j]; }
#pragma unroll
    for (int o = 16; o; o >>= 1) {
        s0 += __shfl_down_sync(0xffffffffu, s0, o);
        s1 += __shfl_down_sync(0xffffffffu, s1, o);
    }
    __shared__ float r0[4], r1[4];
    if ((t & 31) == 0) { r0[t >> 5] = s0; r1[t >> 5] = s1; }
    __syncthreads();
    float inv0 = 1.0f / (r0[0] + r0[1] + r0[2] + r0[3] + 1e-8f);
    float inv1 = 1.0f / (r1[0] + r1[1] + r1[2] + r1[3] + 1e-8f);

    if (d0 == 0) {   // fused attn normalize output
        float* ao0 = attn_out + b * 4096;
        float* ao1 = ao0 + 2048;
        for (int j = t; j < 2048; j += 128) {
            ao0[j] = a0p[j] * inv0;
            ao1[j] = a1p[j] * inv1;
        }
    }

    __shared__ float w0[256], w1[256];
    float acc0 = 0.f, acc1 = 0.f;
    const float* vb = v + (size_t)b * 2048 * D + d0 + t;
    for (int jc = 0; jc < 2048; jc += 256) {
        __syncthreads();
        w0[t] = a0p[jc + t]; w0[t + 128] = a0p[jc + t + 128];
        w1[t] = a1p[jc + t]; w1[t + 128] = a1p[jc + t + 128];
        __syncthreads();
#pragma unroll 8
        for (int jj = 0; jj < 256; jj++) {
            float vv = vb[(size_t)(jc + jj) * D];
            acc0 += vv * w0[jj];
            acc1 += vv * w1[jj];
        }
    }
    upd[(size_t)(b * 2 + 0) * D + d0 + t] = acc0 * inv0;
    upd[(size_t)(b * 2 + 1) * D + d0 + t] = acc1 * inv1;
}

// ---------------------------------------------------------------------------
// GRU gates
// ---------------------------------------------------------------------------
__global__ void k_gru2(const float* __restrict__ gx, const float* __restrict__ gh,
                       const float* __restrict__ slots, float* __restrict__ hnew) {
    int idx = blockIdx.x * 256 + threadIdx.x;
    int r = idx >> 9, d = idx & 511;
    const float* gxr = gx + (size_t)r * 1536;
    const float* ghr = gh + (size_t)r * 1536;
    float rg = sigmoidf_(gxr[d] + ghr[d]);
    float z  = sigmoidf_(gxr[512 + d] + ghr[512 + d]);
    float n  = tanhf(gxr[1024 + d] + rg * ghr[1024 + d]);
    hnew[idx] = (1.0f - z) * n + z * slots[idx];
}

// ---------------------------------------------------------------------------
// host
// ---------------------------------------------------------------------------
extern "C" void kernel_launch(void* const* d_in, const int* in_sizes, int n_in,
                              void* d_out, int out_size) {
    (void)in_sizes; (void)n_in; (void)out_size;
    const float* inputs     = (const float*)d_in[0];
    const float* init_slots = (const float*)d_in[1];
    const float* Wq  = (const float*)d_in[2];
    const float* bq  = (const float*)d_in[3];
    const float* Wk  = (const float*)d_in[4];
    const float* bk  = (const float*)d_in[5];
    const float* Wv  = (const float*)d_in[6];
    const float* bv  = (const float*)d_in[7];
    const float* ln_in_g = (const float*)d_in[8];
    const float* ln_in_b = (const float*)d_in[9];
    const float* ln_s_g  = (const float*)d_in[10];
    const float* ln_s_b  = (const float*)d_in[11];
    const float* ln_f_g  = (const float*)d_in[12];
    const float* ln_f_b  = (const float*)d_in[13];
    const float* gru_wih = (const float*)d_in[14];
    const float* gru_whh = (const float*)d_in[15];
    const float* gru_bih = (const float*)d_in[16];
    const float* gru_bhh = (const float*)d_in[17];
    const float* W1 = (const float*)d_in[18];
    const float* b1 = (const float*)d_in[19];
    const float* W2 = (const float*)d_in[20];
    const float* b2 = (const float*)d_in[21];

    float* out      = (float*)d_out;
    float* slots    = out;
    float* qout     = out + 32768;
    float* kout     = out + 65536;
    float* attn_out = out + 65536 + 33554432;

    float* S = nullptr;
    cudaGetSymbolAddress((void**)&S, g_scratch);
    float* v    = S + OFF_V;
    float* mean = S + OFF_MEAN;
    float* rstd = S + OFF_RSTD;
    float* attn = S + OFF_ATTN;
    float* sln  = S + OFF_SLN;
    float* upd  = S + OFF_UPD;
    float* gx   = S + OFF_GX;
    float* gh   = S + OFF_GH;
    float* hnew = S + OFF_HNEW;
    float* hln  = S + OFF_HLN;
    float* tbuf = S + OFF_T;
    __nv_bfloat16* whi = (__nv_bfloat16*)(S + OFF_WHI);
    __nv_bfloat16* wlo = (__nv_bfloat16*)(S + OFF_WLO);

    cudaFuncSetAttribute(k_mmagemm, cudaFuncAttributeMaxDynamicSharedMemorySize,
                         PTOT);

    cudaMemcpyAsync(slots, init_slots, 32768 * sizeof(float),
                    cudaMemcpyDeviceToDevice);

    k_prepw<<<2048, 256>>>(Wk, Wv, whi, wlo);
    k_rowstats<<<NROWS, 128>>>(inputs, mean, rstd);
    k_mmagemm<<<dim3(8, 512), 256, PTOT>>>(inputs, whi, wlo, bk, bv,
                                           ln_in_g, ln_in_b, mean, rstd,
                                           kout, v);

    for (int it = 0; it < 3; ++it) {
        k_ln64<<<64, 128>>>(slots, ln_s_g, ln_s_b, sln);
        k_gemm64<0><<<dim3(16, 1), 256>>>(sln, sln, Wq, bq, nullptr,
                                          qout, qout, 512, 0);
        k_dots<<<dim3(16, 32), 128>>>(qout, kout, attn);
        k_upd<<<dim3(4, 32), 128>>>(attn, v, upd, attn_out);
        k_gemm64<1><<<dim3(48, 2), 256>>>(upd, slots, gru_wih, gru_bih, nullptr,
                                          gx, gh, 1536, 0);
        // NOTE: gh uses gru_whh/gru_bhh, not wih/bih — needs separate weights.
        k_gemm64<1><<<dim3(48, 1), 256>>>(slots, slots, gru_whh, gru_bhh, nullptr,
                                          gh, gh, 1536, 0);
        k_gru2<<<128, 256>>>(gx, gh, slots, hnew);
        k_ln64<<<64, 128>>>(hnew, ln_f_g, ln_f_b, hln);
        k_gemm64<0><<<dim3(16, 1), 256>>>(hln, hln, W1, b1, nullptr,
                                          tbuf, tbuf, 512, 1);
        k_gemm64<0><<<dim3(16, 1), 256>>>(tbuf, tbuf, W2, b2, hnew,
                                          slots, slots, 512, 0);
    }
}

// round 9
// speedup vs baseline: 1.2700x; 1.0400x over previous
#include <cuda_runtime.h>
#include <cuda_bf16.h>
#include <math.h>
#include <stdint.h>

// ---------------------------------------------------------------------------
// SlotAttention. B=32, N=2048, DIN=DOUT=HID=512, S=2, ITERS=3.
// Big LN+GEMM (k,v): pipelined mma.sync bf16 3-pass split, independent-acc
// MMA schedule (16-deep dependency distance).
// ---------------------------------------------------------------------------

#define NROWS 65536
#define D 512

// ---- scratch ----
#define OFF_V     0
#define OFF_MEAN  33554432
#define OFF_RSTD  (33554432 + 65536)
#define OFF_ATTN  (33554432 + 131072)
#define OFF_SLN   (OFF_ATTN + 131072)
#define OFF_UPD   (OFF_SLN  + 32768)
#define OFF_GX    (OFF_UPD  + 32768)
#define OFF_GH    (OFF_GX   + 98304)
#define OFF_HNEW  (OFF_GH   + 98304)
#define OFF_HLN   (OFF_HNEW + 32768)
#define OFF_T     (OFF_HLN  + 32768)
#define OFF_WHI   (OFF_T    + 32768)
#define OFF_WLO   (OFF_WHI  + 262144)
#define SCRATCH_FLOATS (OFF_WLO + 262144)

__device__ __align__(256) float g_scratch[SCRATCH_FLOATS];

static __device__ __forceinline__ float sigmoidf_(float x) {
    return 1.0f / (1.0f + expf(-x));
}

static __device__ __forceinline__ uint32_t smem_u32(const void* p) {
    uint32_t a;
    asm("{ .reg .u64 t; cvta.to.shared.u64 t, %1; cvt.u32.u64 %0, t; }"
        : "=r"(a) : "l"(p));
    return a;
}
static __device__ __forceinline__ uint32_t b2u(__nv_bfloat162 h) {
    return *reinterpret_cast<uint32_t*>(&h);
}

#define LDSM4(r0, r1, r2, r3, a)                                              \
    asm volatile("ldmatrix.sync.aligned.m8n8.x4.shared.b16 {%0,%1,%2,%3}, [%4];" \
                 : "=r"(r0), "=r"(r1), "=r"(r2), "=r"(r3) : "r"(a))

#define MMA16816(c, a, b0, b1)                                                \
    asm volatile("mma.sync.aligned.m16n8k16.row.col.f32.bf16.bf16.f32 "       \
                 "{%0,%1,%2,%3}, {%4,%5,%6,%7}, {%8,%9}, {%0,%1,%2,%3};"      \
                 : "+f"((c)[0]), "+f"((c)[1]), "+f"((c)[2]), "+f"((c)[3])     \
                 : "r"((a)[0]), "r"((a)[1]), "r"((a)[2]), "r"((a)[3]),        \
                   "r"(b0), "r"(b1))

#define CP16(dst, src)                                                        \
    asm volatile("cp.async.cg.shared.global [%0], [%1], 16;"                  \
                 :: "r"(dst), "l"(src))
#define CP_COMMIT() asm volatile("cp.async.commit_group;" ::: "memory")
#define CP_WAIT0()  asm volatile("cp.async.wait_group 0;" ::: "memory")

// ---------------------------------------------------------------------------
// k_rowstats
// ---------------------------------------------------------------------------
__global__ void k_rowstats(const float* __restrict__ x,
                           float* __restrict__ mean, float* __restrict__ rstd) {
    int row = blockIdx.x;
    int t = threadIdx.x;
    float4 v = ((const float4*)(x + (size_t)row * D))[t];
    float s  = v.x + v.y + v.z + v.w;
    float s2 = v.x * v.x + v.y * v.y + v.z * v.z + v.w * v.w;
#pragma unroll
    for (int o = 16; o; o >>= 1) {
        s  += __shfl_down_sync(0xffffffffu, s,  o);
        s2 += __shfl_down_sync(0xffffffffu, s2, o);
    }
    __shared__ float ss[4], ss2[4];
    if ((t & 31) == 0) { ss[t >> 5] = s; ss2[t >> 5] = s2; }
    __syncthreads();
    if (t == 0) {
        float S  = ss[0] + ss[1] + ss[2] + ss[3];
        float S2 = ss2[0] + ss2[1] + ss2[2] + ss2[3];
        float m   = S * (1.0f / 512.0f);
        float var = S2 * (1.0f / 512.0f) - m * m;
        mean[row] = m;
        rstd[row] = rsqrtf(var + 1e-5f);
    }
}

// ---------------------------------------------------------------------------
// k_prepw
// ---------------------------------------------------------------------------
__global__ void k_prepw(const float* __restrict__ Wk, const float* __restrict__ Wv,
                        __nv_bfloat16* __restrict__ Bhi, __nv_bfloat16* __restrict__ Blo) {
    int idx = blockIdx.x * 256 + threadIdx.x;
    int k = idx >> 10;
    int n = idx & 1023;
    float w = (n < 512) ? Wk[k * 512 + n] : Wv[k * 512 + (n - 512)];
    __nv_bfloat16 h = __float2bfloat16(w);
    float l = w - __bfloat162float(h);
    Bhi[(size_t)n * 512 + k] = h;
    Blo[(size_t)n * 512 + k] = __float2bfloat16(l);
}

// ---------------------------------------------------------------------------
// k_mmagemm
// ---------------------------------------------------------------------------
#define PBUF  65536
#define PAHI  0
#define PALO  16384
#define PBHI  32768
#define PBLO  49152
#define PG    131072
#define PBB   133120
#define PTOT  136192

__global__ __launch_bounds__(256, 1)
void k_mmagemm(const float* __restrict__ x,
               const __nv_bfloat16* __restrict__ Bhi,
               const __nv_bfloat16* __restrict__ Blo,
               const float* __restrict__ bk, const float* __restrict__ bv,
               const float* __restrict__ g, const float* __restrict__ bln,
               const float* __restrict__ mean, const float* __restrict__ rstd,
               float* __restrict__ outK, float* __restrict__ outV) {
    extern __shared__ char smraw[];
    char* smb = (char*)((((uintptr_t)smraw) + 1023) & ~(uintptr_t)1023);
    uint32_t sb = smem_u32(smb);
    int tid = threadIdx.x;
    int wid = tid >> 5;
    int lid = tid & 31;
    int n0 = blockIdx.x << 7;
    int m0 = blockIdx.y << 7;

    float* gs  = (float*)(smb + PG);
    float* bsn = (float*)(smb + PBB);
    for (int i = tid; i < 512; i += 256) { gs[i] = g[i]; bsn[i] = bln[i]; }

    const int ln = tid >> 1;
    const int kh = (tid & 1) << 5;
    const float m  = mean[m0 + ln];
    const float rs = rstd[m0 + ln];
    const float* xrow = x + (size_t)(m0 + ln) * D;
    const __nv_bfloat16* bhr = Bhi + (size_t)(n0 + ln) * D;
    const __nv_bfloat16* blr = Blo + (size_t)(n0 + ln) * D;

    const int wm = (wid & 3) << 5;
    const int wn = (wid >> 2) << 6;

    uint32_t aoffA0, aoffA1, aoffB[4];
    {
        uint32_t r0 = (uint32_t)(wm + (lid & 15));
        aoffA0 = (r0 << 7) + ((lid >> 4) << 4);
        uint32_t r1 = r0 + 16;
        aoffA1 = (r1 << 7) + ((lid >> 4) << 4);
#pragma unroll
        for (int gi = 0; gi < 4; ++gi) {
            uint32_t rn = (uint32_t)(wn + (gi << 4) + (lid & 7) + ((lid >> 4) << 3));
            aoffB[gi] = (rn << 7) + (((lid >> 3) & 1) << 4);
        }
    }

    float acc[2][8][4];
#pragma unroll
    for (int i = 0; i < 2; i++)
#pragma unroll
        for (int j = 0; j < 8; j++)
#pragma unroll
            for (int q = 0; q < 4; q++) acc[i][j][q] = 0.f;

    __syncthreads();

    float4 ra[8];

    auto cpB = [&](int c, int p) {
        const int k0 = c << 6;
#pragma unroll
        for (int j = 0; j < 4; ++j) {
            uint32_t off = (ln << 7) + ((kh + (j << 3)) << 1);
            uint32_t sw = off ^ ((off >> 3) & 0x70);
            CP16(sb + p * PBUF + PBHI + sw, bhr + k0 + kh + (j << 3));
            CP16(sb + p * PBUF + PBLO + sw, blr + k0 + kh + (j << 3));
        }
        CP_COMMIT();
    };
    auto ldgA = [&](int c) {
        const int k0 = c << 6;
#pragma unroll
        for (int j = 0; j < 8; ++j)
            ra[j] = *(const float4*)(xrow + k0 + kh + (j << 2));
    };
    auto stsA = [&](int c, int p) {
        const int k0 = c << 6;
#pragma unroll
        for (int j = 0; j < 8; ++j) {
            const int kk = kh + (j << 2);
            float4 a = ra[j];
            float v0 = (a.x - m) * rs * gs[k0 + kk + 0] + bsn[k0 + kk + 0];
            float v1 = (a.y - m) * rs * gs[k0 + kk + 1] + bsn[k0 + kk + 1];
            float v2 = (a.z - m) * rs * gs[k0 + kk + 2] + bsn[k0 + kk + 2];
            float v3 = (a.w - m) * rs * gs[k0 + kk + 3] + bsn[k0 + kk + 3];
            __nv_bfloat16 h0 = __float2bfloat16(v0), h1 = __float2bfloat16(v1);
            __nv_bfloat16 h2 = __float2bfloat16(v2), h3 = __float2bfloat16(v3);
            __nv_bfloat162 H01 = __halves2bfloat162(h0, h1);
            __nv_bfloat162 H23 = __halves2bfloat162(h2, h3);
            __nv_bfloat162 L01 = __floats2bfloat162_rn(v0 - __bfloat162float(h0),
                                                       v1 - __bfloat162float(h1));
            __nv_bfloat162 L23 = __floats2bfloat162_rn(v2 - __bfloat162float(h2),
                                                       v3 - __bfloat162float(h3));
            uint32_t off = (ln << 7) + (kk << 1);
            uint32_t sw = off ^ ((off >> 3) & 0x70);
            *(uint2*)(smb + p * PBUF + PAHI + sw) = make_uint2(b2u(H01), b2u(H23));
            *(uint2*)(smb + p * PBUF + PALO + sw) = make_uint2(b2u(L01), b2u(L23));
        }
    };

    // Independent-accumulator schedule: per k16 step load ALL fragments,
    // then 3 passes of 16 independent MMAs (acc reuse distance = 16).
    auto compute = [&](int p) {
        const uint32_t base = sb + p * PBUF;
#pragma unroll
        for (int s = 0; s < 4; ++s) {
            const uint32_t kb = s << 5;
            uint32_t o0 = aoffA0 + kb, o1 = aoffA1 + kb;
            uint32_t sw0 = o0 ^ ((o0 >> 3) & 0x70);
            uint32_t sw1 = o1 ^ ((o1 >> 3) & 0x70);
            uint32_t ah[2][4], al[2][4], bh[4][4], bl[4][4];
            LDSM4(ah[0][0], ah[0][1], ah[0][2], ah[0][3], base + PAHI + sw0);
            LDSM4(ah[1][0], ah[1][1], ah[1][2], ah[1][3], base + PAHI + sw1);
            LDSM4(al[0][0], al[0][1], al[0][2], al[0][3], base + PALO + sw0);
            LDSM4(al[1][0], al[1][1], al[1][2], al[1][3], base + PALO + sw1);
#pragma unroll
            for (int gi = 0; gi < 4; ++gi) {
                uint32_t ob = aoffB[gi] + kb;
                uint32_t swb = ob ^ ((ob >> 3) & 0x70);
                LDSM4(bh[gi][0], bh[gi][1], bh[gi][2], bh[gi][3], base + PBHI + swb);
                LDSM4(bl[gi][0], bl[gi][1], bl[gi][2], bl[gi][3], base + PBLO + swb);
            }
            // pass 1: Ah x Bh  (16 independent MMAs)
#pragma unroll
            for (int gi = 0; gi < 4; ++gi)
#pragma unroll
                for (int mt = 0; mt < 2; ++mt) {
                    MMA16816(acc[mt][gi * 2 + 0], ah[mt], bh[gi][0], bh[gi][1]);
                    MMA16816(acc[mt][gi * 2 + 1], ah[mt], bh[gi][2], bh[gi][3]);
                }
            // pass 2: Ah x Bl
#pragma unroll
            for (int gi = 0; gi < 4; ++gi)
#pragma unroll
                for (int mt = 0; mt < 2; ++mt) {
                    MMA16816(acc[mt][gi * 2 + 0], ah[mt], bl[gi][0], bl[gi][1]);
                    MMA16816(acc[mt][gi * 2 + 1], ah[mt], bl[gi][2], bl[gi][3]);
                }
            // pass 3: Al x Bh
#pragma unroll
            for (int gi = 0; gi < 4; ++gi)
#pragma unroll
                for (int mt = 0; mt < 2; ++mt) {
                    MMA16816(acc[mt][gi * 2 + 0], al[mt], bh[gi][0], bh[gi][1]);
                    MMA16816(acc[mt][gi * 2 + 1], al[mt], bh[gi][2], bh[gi][3]);
                }
        }
    };

    // prologue
    ldgA(0);
    cpB(0, 0);
    stsA(0, 0);
    ldgA(1);
    CP_WAIT0();
    __syncthreads();

    for (int c = 0; c < 8; ++c) {
        const int p = c & 1;
        if (c < 7) cpB(c + 1, p ^ 1);
        compute(p);
        if (c < 7) {
            stsA(c + 1, p ^ 1);
            if (c < 6) ldgA(c + 2);
            CP_WAIT0();
            __syncthreads();
        }
    }
    __syncthreads();

    // epilogue
    float* stage = (float*)smb;
    const int qrow = lid >> 2;
    const int qcol = (lid & 3) << 1;
#pragma unroll
    for (int mt = 0; mt < 2; ++mt) {
#pragma unroll
        for (int nt = 0; nt < 8; ++nt) {
            int r = wm + mt * 16 + qrow;
            int ccol = wn + nt * 8 + qcol;
            *(float2*)&stage[r * 132 + ccol] =
                make_float2(acc[mt][nt][0], acc[mt][nt][1]);
            *(float2*)&stage[(r + 8) * 132 + ccol] =
                make_float2(acc[mt][nt][2], acc[mt][nt][3]);
        }
    }
    __syncthreads();

    const float* bias = (n0 < 512) ? (bk + n0) : (bv + (n0 - 512));
    float* outp = (n0 < 512) ? (outK + n0) : (outV + (n0 - 512));
    {
        int row = tid >> 1;
        int ch = (tid & 1) << 6;
#pragma unroll
        for (int i = 0; i < 16; ++i) {
            int cb = ch + (i << 2);
            float4 o;
            o.x = stage[row * 132 + cb + 0] + bias[cb + 0];
            o.y = stage[row * 132 + cb + 1] + bias[cb + 1];
            o.z = stage[row * 132 + cb + 2] + bias[cb + 2];
            o.w = stage[row * 132 + cb + 3] + bias[cb + 3];
            *(float4*)(outp + (size_t)(m0 + row) * D + cb) = o;
        }
    }
}

// ---------------------------------------------------------------------------
// LN over 64 rows of 512.
// ---------------------------------------------------------------------------
__global__ void k_ln64(const float* __restrict__ in, const float* __restrict__ g,
                       const float* __restrict__ b, float* __restrict__ out) {
    int r = blockIdx.x, t = threadIdx.x;
    float4 v = ((const float4*)(in + (size_t)r * D))[t];
    float s  = v.x + v.y + v.z + v.w;
    float s2 = v.x * v.x + v.y * v.y + v.z * v.z + v.w * v.w;
#pragma unroll
    for (int o = 16; o; o >>= 1) {
        s  += __shfl_down_sync(0xffffffffu, s,  o);
        s2 += __shfl_down_sync(0xffffffffu, s2, o);
    }
    __shared__ float ss[4], ss2[4];
    __shared__ float sm, srs;
    if ((t & 31) == 0) { ss[t >> 5] = s; ss2[t >> 5] = s2; }
    __syncthreads();
    if (t == 0) {
        float S  = ss[0] + ss[1] + ss[2] + ss[3];
        float S2 = ss2[0] + ss2[1] + ss2[2] + ss2[3];
        float m   = S * (1.0f / 512.0f);
        float var = S2 * (1.0f / 512.0f) - m * m;
        sm = m; srs = rsqrtf(var + 1e-5f);
    }
    __syncthreads();
    float m = sm, rs = srs;
    float4 gg = ((const float4*)g)[t];
    float4 bb = ((const float4*)b)[t];
    float4 o;
    o.x = (v.x - m) * rs * gg.x + bb.x;
    o.y = (v.y - m) * rs * gg.y + bb.y;
    o.z = (v.z - m) * rs * gg.z + bb.z;
    o.w = (v.w - m) * rs * gg.w + bb.w;
    ((float4*)(out + (size_t)r * D))[t] = o;
}

// ---------------------------------------------------------------------------
// Small GEMM with register prefetch; gridDim.y selects (A,W,bias,out) set.
// ---------------------------------------------------------------------------
template <int TRANSW>
__global__ __launch_bounds__(256) void k_gemm64(
    const float* __restrict__ A, const float* __restrict__ A2,
    const float* __restrict__ W, const float* __restrict__ W2,
    const float* __restrict__ bias, const float* __restrict__ bias2,
    const float* __restrict__ resid,
    float* __restrict__ out, float* __restrict__ out2, int ncols, int relu) {
    __shared__ float As[32][64];
    __shared__ float Ws[32][33];
    int tid  = threadIdx.x;
    int col0 = blockIdx.x << 5;
    int ty = tid >> 5, tx = tid & 31;
    int ar0 = tid >> 3, akp = (tid & 7) << 2;

    const float* Ause = blockIdx.y ? A2 : A;
    const float* Wuse = blockIdx.y ? W2 : W;
    const float* buse = blockIdx.y ? bias2 : bias;
    float* outuse = blockIdx.y ? out2 : out;

    float acc[8];
#pragma unroll
    for (int i = 0; i < 8; i++) acc[i] = 0.f;

    int wn = tid >> 3, wkp = (tid & 7) << 2;
    int wk = tid >> 3, wnp = (tid & 7) << 2;

    float4 pa0 = *(const float4*)(Ause + (size_t)ar0 * D + akp);
    float4 pa1 = *(const float4*)(Ause + (size_t)(ar0 + 32) * D + akp);
    float4 pw;
    if (TRANSW)
        pw = *(const float4*)(Wuse + (size_t)(col0 + wn) * D + wkp);
    else
        pw = *(const float4*)(Wuse + (size_t)wk * ncols + col0 + wnp);

    for (int kt = 0; kt < 512; kt += 32) {
        As[akp + 0][ar0] = pa0.x; As[akp + 1][ar0] = pa0.y;
        As[akp + 2][ar0] = pa0.z; As[akp + 3][ar0] = pa0.w;
        As[akp + 0][ar0 + 32] = pa1.x; As[akp + 1][ar0 + 32] = pa1.y;
        As[akp + 2][ar0 + 32] = pa1.z; As[akp + 3][ar0 + 32] = pa1.w;
        if (TRANSW) {
            Ws[wkp + 0][wn] = pw.x; Ws[wkp + 1][wn] = pw.y;
            Ws[wkp + 2][wn] = pw.z; Ws[wkp + 3][wn] = pw.w;
        } else {
            Ws[wk][wnp + 0] = pw.x; Ws[wk][wnp + 1] = pw.y;
            Ws[wk][wnp + 2] = pw.z; Ws[wk][wnp + 3] = pw.w;
        }
        __syncthreads();
        if (kt + 32 < 512) {
            pa0 = *(const float4*)(Ause + (size_t)ar0 * D + kt + 32 + akp);
            pa1 = *(const float4*)(Ause + (size_t)(ar0 + 32) * D + kt + 32 + akp);
            if (TRANSW)
                pw = *(const float4*)(Wuse + (size_t)(col0 + wn) * D + kt + 32 + wkp);
            else
                pw = *(const float4*)(Wuse + (size_t)(kt + 32 + wk) * ncols + col0 + wnp);
        }
#pragma unroll
        for (int kk = 0; kk < 32; kk++) {
            float w = Ws[kk][tx];
            float a[8];
            *(float4*)&a[0] = *(const float4*)&As[kk][ty << 3];
            *(float4*)&a[4] = *(const float4*)&As[kk][(ty << 3) + 4];
#pragma unroll
            for (int r = 0; r < 8; r++) acc[r] += a[r] * w;
        }
        __syncthreads();
    }

    float bvv = buse[col0 + tx];
#pragma unroll
    for (int r = 0; r < 8; r++) {
        int row = (ty << 3) + r;
        float val = acc[r] + bvv;
        if (relu) val = fmaxf(val, 0.f);
        if (resid) val += resid[(size_t)row * D + col0 + tx];
        outuse[(size_t)row * ncols + col0 + tx] = val;
    }
}

// ---------------------------------------------------------------------------
// dots + softmax over the slot axis.
// ---------------------------------------------------------------------------
__global__ __launch_bounds__(128) void k_dots(const float* __restrict__ q,
                                              const float* __restrict__ k,
                                              float* __restrict__ attn_pre) {
    int b = blockIdx.y, j0 = blockIdx.x << 7;
    int t = threadIdx.x;
    __shared__ float qs0[512], qs1[512];
    __shared__ float ks[128][65];
    {
        float4 q0 = ((const float4*)(q + (size_t)(b * 2 + 0) * D))[t];
        float4 q1 = ((const float4*)(q + (size_t)(b * 2 + 1) * D))[t];
        *(float4*)&qs0[t << 2] = q0;
        *(float4*)&qs1[t << 2] = q1;
    }
    float d0 = 0.f, d1 = 0.f;
    const float* kb = k + ((size_t)b * 2048 + j0) * D;
    for (int kc = 0; kc < 512; kc += 64) {
        __syncthreads();
#pragma unroll
        for (int i = 0; i < 16; i++) {
            int f = t + (i << 7);
            int j = f >> 4, kp = (f & 15) << 2;
            float4 kv = *(const float4*)(kb + (size_t)j * D + kc + kp);
            ks[j][kp + 0] = kv.x; ks[j][kp + 1] = kv.y;
            ks[j][kp + 2] = kv.z; ks[j][kp + 3] = kv.w;
        }
        __syncthreads();
#pragma unroll
        for (int kk = 0; kk < 64; kk++) {
            float kv = ks[t][kk];
            d0 += kv * qs0[kc + kk];
            d1 += kv * qs1[kc + kk];
        }
    }
    const float SC = 0.044194173824159216f;
    d0 *= SC; d1 *= SC;
    float mx = fmaxf(d0, d1);
    float e0 = expf(d0 - mx), e1 = expf(d1 - mx);
    float inv = 1.0f / (e0 + e1);
    attn_pre[b * 4096 + (j0 + t)]        = e0 * inv;
    attn_pre[b * 4096 + 2048 + (j0 + t)] = e1 * inv;
}

// ---------------------------------------------------------------------------
// updates = (v^T @ attn_row) / (rowsum + eps); d-tile 0 also writes attn_out.
// ---------------------------------------------------------------------------
__global__ __launch_bounds__(128) void k_upd(const float* __restrict__ attn_pre,
                                             const float* __restrict__ v,
                                             float* __restrict__ upd,
                                             float* __restrict__ attn_out) {
    int b = blockIdx.y, d0 = blockIdx.x << 7, t = threadIdx.x;
    const float* a0p = attn_pre + b * 4096;
    const float* a1p = a0p + 2048;
    float s0 = 0.f, s1 = 0.f;
    for (int j = t; j < 2048; j += 128) { s0 += a0p[j]; s1 += a1p[j]; }
#pragma unroll
    for (int o = 16; o; o >>= 1) {
        s0 += __shfl_down_sync(0xffffffffu, s0, o);
        s1 += __shfl_down_sync(0xffffffffu, s1, o);
    }
    __shared__ float r0[4], r1[4];
    if ((t & 31) == 0) { r0[t >> 5] = s0; r1[t >> 5] = s1; }
    __syncthreads();
    float inv0 = 1.0f / (r0[0] + r0[1] + r0[2] + r0[3] + 1e-8f);
    float inv1 = 1.0f / (r1[0] + r1[1] + r1[2] + r1[3] + 1e-8f);

    if (d0 == 0) {
        float* ao0 = attn_out + b * 4096;
        float* ao1 = ao0 + 2048;
        for (int j = t; j < 2048; j += 128) {
            ao0[j] = a0p[j] * inv0;
            ao1[j] = a1p[j] * inv1;
        }
    }

    __shared__ float w0[256], w1[256];
    float acc0 = 0.f, acc1 = 0.f;
    const float* vb = v + (size_t)b * 2048 * D + d0 + t;
    for (int jc = 0; jc < 2048; jc += 256) {
        __syncthreads();
        w0[t] = a0p[jc + t]; w0[t + 128] = a0p[jc + t + 128];
        w1[t] = a1p[jc + t]; w1[t + 128] = a1p[jc + t + 128];
        __syncthreads();
#pragma unroll 8
        for (int jj = 0; jj < 256; jj++) {
            float vv = vb[(size_t)(jc + jj) * D];
            acc0 += vv * w0[jj];
            acc1 += vv * w1[jj];
        }
    }
    upd[(size_t)(b * 2 + 0) * D + d0 + t] = acc0 * inv0;
    upd[(size_t)(b * 2 + 1) * D + d0 + t] = acc1 * inv1;
}

// ---------------------------------------------------------------------------
// Fused GRU gates + LayerNorm(h_new). 64 blocks (one per row) x 128 threads.
// ---------------------------------------------------------------------------
__global__ void k_gruln(const float* __restrict__ gx, const float* __restrict__ gh,
                        const float* __restrict__ slots,
                        const float* __restrict__ g, const float* __restrict__ b,
                        float* __restrict__ hnew, float* __restrict__ hln) {
    int r = blockIdx.x, t = threadIdx.x;
    const float* gxr = gx + (size_t)r * 1536;
    const float* ghr = gh + (size_t)r * 1536;
    float4 xr = ((const float4*)(gxr))[t];
    float4 hr = ((const float4*)(ghr))[t];
    float4 xz = ((const float4*)(gxr + 512))[t];
    float4 hz = ((const float4*)(ghr + 512))[t];
    float4 xn = ((const float4*)(gxr + 1024))[t];
    float4 hn = ((const float4*)(ghr + 1024))[t];
    float4 hp = ((const float4*)(slots + (size_t)r * D))[t];

    float h[4];
    {
        float rg, z, n;
        rg = sigmoidf_(xr.x + hr.x); z = sigmoidf_(xz.x + hz.x);
        n = tanhf(xn.x + rg * hn.x); h[0] = (1.f - z) * n + z * hp.x;
        rg = sigmoidf_(xr.y + hr.y); z = sigmoidf_(xz.y + hz.y);
        n = tanhf(xn.y + rg * hn.y); h[1] = (1.f - z) * n + z * hp.y;
        rg = sigmoidf_(xr.z + hr.z); z = sigmoidf_(xz.z + hz.z);
        n = tanhf(xn.z + rg * hn.z); h[2] = (1.f - z) * n + z * hp.z;
        rg = sigmoidf_(xr.w + hr.w); z = sigmoidf_(xz.w + hz.w);
        n = tanhf(xn.w + rg * hn.w); h[3] = (1.f - z) * n + z * hp.w;
    }
    ((float4*)(hnew + (size_t)r * D))[t] = make_float4(h[0], h[1], h[2], h[3]);

    float s  = h[0] + h[1] + h[2] + h[3];
    float s2 = h[0]*h[0] + h[1]*h[1] + h[2]*h[2] + h[3]*h[3];
#pragma unroll
    for (int o = 16; o; o >>= 1) {
        s  += __shfl_down_sync(0xffffffffu, s,  o);
        s2 += __shfl_down_sync(0xffffffffu, s2, o);
    }
    __shared__ float ss[4], ss2[4];
    __shared__ float sm, srs;
    if ((t & 31) == 0) { ss[t >> 5] = s; ss2[t >> 5] = s2; }
    __syncthreads();
    if (t == 0) {
        float S  = ss[0] + ss[1] + ss[2] + ss[3];
        float S2 = ss2[0] + ss2[1] + ss2[2] + ss2[3];
        float mm  = S * (1.0f / 512.0f);
        float var = S2 * (1.0f / 512.0f) - mm * mm;
        sm = mm; srs = rsqrtf(var + 1e-5f);
    }
    __syncthreads();
    float mm = sm, rs = srs;
    float4 gg = ((const float4*)g)[t];
    float4 bb = ((const float4*)b)[t];
    float4 o;
    o.x = (h[0] - mm) * rs * gg.x + bb.x;
    o.y = (h[1] - mm) * rs * gg.y + bb.y;
    o.z = (h[2] - mm) * rs * gg.z + bb.z;
    o.w = (h[3] - mm) * rs * gg.w + bb.w;
    ((float4*)(hln + (size_t)r * D))[t] = o;
}

// ---------------------------------------------------------------------------
// host
// ---------------------------------------------------------------------------
extern "C" void kernel_launch(void* const* d_in, const int* in_sizes, int n_in,
                              void* d_out, int out_size) {
    (void)in_sizes; (void)n_in; (void)out_size;
    const float* inputs     = (const float*)d_in[0];
    const float* init_slots = (const float*)d_in[1];
    const float* Wq  = (const float*)d_in[2];
    const float* bq  = (const float*)d_in[3];
    const float* Wk  = (const float*)d_in[4];
    const float* bk  = (const float*)d_in[5];
    const float* Wv  = (const float*)d_in[6];
    const float* bv  = (const float*)d_in[7];
    const float* ln_in_g = (const float*)d_in[8];
    const float* ln_in_b = (const float*)d_in[9];
    const float* ln_s_g  = (const float*)d_in[10];
    const float* ln_s_b  = (const float*)d_in[11];
    const float* ln_f_g  = (const float*)d_in[12];
    const float* ln_f_b  = (const float*)d_in[13];
    const float* gru_wih = (const float*)d_in[14];
    const float* gru_whh = (const float*)d_in[15];
    const float* gru_bih = (const float*)d_in[16];
    const float* gru_bhh = (const float*)d_in[17];
    const float* W1 = (const float*)d_in[18];
    const float* b1 = (const float*)d_in[19];
    const float* W2 = (const float*)d_in[20];
    const float* b2 = (const float*)d_in[21];

    float* out      = (float*)d_out;
    float* slots    = out;
    float* qout     = out + 32768;
    float* kout     = out + 65536;
    float* attn_out = out + 65536 + 33554432;

    float* S = nullptr;
    cudaGetSymbolAddress((void**)&S, g_scratch);
    float* v    = S + OFF_V;
    float* mean = S + OFF_MEAN;
    float* rstd = S + OFF_RSTD;
    float* attn = S + OFF_ATTN;
    float* sln  = S + OFF_SLN;
    float* upd  = S + OFF_UPD;
    float* gx   = S + OFF_GX;
    float* gh   = S + OFF_GH;
    float* hnew = S + OFF_HNEW;
    float* hln  = S + OFF_HLN;
    float* tbuf = S + OFF_T;
    __nv_bfloat16* whi = (__nv_bfloat16*)(S + OFF_WHI);
    __nv_bfloat16* wlo = (__nv_bfloat16*)(S + OFF_WLO);

    cudaFuncSetAttribute(k_mmagemm, cudaFuncAttributeMaxDynamicSharedMemorySize,
                         PTOT);

    cudaMemcpyAsync(slots, init_slots, 32768 * sizeof(float),
                    cudaMemcpyDeviceToDevice);

    k_prepw<<<2048, 256>>>(Wk, Wv, whi, wlo);
    k_rowstats<<<NROWS, 128>>>(inputs, mean, rstd);
    k_mmagemm<<<dim3(8, 512), 256, PTOT>>>(inputs, whi, wlo, bk, bv,
                                           ln_in_g, ln_in_b, mean, rstd,
                                           kout, v);

    for (int it = 0; it < 3; ++it) {
        k_ln64<<<64, 128>>>(slots, ln_s_g, ln_s_b, sln);
        k_gemm64<0><<<dim3(16, 1), 256>>>(sln, sln, Wq, Wq, bq, bq, nullptr,
                                          qout, qout, 512, 0);
        k_dots<<<dim3(16, 32), 128>>>(qout, kout, attn);
        k_upd<<<dim3(4, 32), 128>>>(attn, v, upd, attn_out);
        k_gemm64<1><<<dim3(48, 2), 256>>>(upd, slots, gru_wih, gru_whh,
                                          gru_bih, gru_bhh, nullptr,
                                          gx, gh, 1536, 0);
        k_gruln<<<64, 128>>>(gx, gh, slots, ln_f_g, ln_f_b, hnew, hln);
        k_gemm64<0><<<dim3(16, 1), 256>>>(hln, hln, W1, W1, b1, b1, nullptr,
                                          tbuf, tbuf, 512, 1);
        k_gemm64<0><<<dim3(16, 1), 256>>>(tbuf, tbuf, W2, W2, b2, b2, hnew,
                                          slots, slots, 512, 0);
    }
}

// round 11
// speedup vs baseline: 1.3801x; 1.0867x over previous
#include <cuda_runtime.h>
#include <cuda_fp16.h>
#include <math.h>
#include <stdint.h>

// ---------------------------------------------------------------------------
// SlotAttention. B=32, N=2048, DIN=DOUT=HID=512, S=2, ITERS=3.
// Big LN+GEMM (k,v): pipelined mma.sync fp16 2-pass split precision
// (A = Ah + Al in fp16, B single fp16; computed = A*fp16(B)).
// Legacy-HMMA rate-capped => minimize MMA instruction count.
// ---------------------------------------------------------------------------

#define NROWS 65536
#define D 512

// ---- scratch ----
#define OFF_V     0
#define OFF_MEAN  33554432
#define OFF_RSTD  (33554432 + 65536)
#define OFF_ATTN  (33554432 + 131072)
#define OFF_SLN   (OFF_ATTN + 131072)
#define OFF_UPD   (OFF_SLN  + 32768)
#define OFF_GX    (OFF_UPD  + 32768)
#define OFF_GH    (OFF_GX   + 98304)
#define OFF_HNEW  (OFF_GH   + 98304)
#define OFF_HLN   (OFF_HNEW + 32768)
#define OFF_T     (OFF_HLN  + 32768)
#define OFF_WHI   (OFF_T    + 32768)   // 1024x512 fp16 = 131072 "floats"
#define SCRATCH_FLOATS (OFF_WHI + 131072)

__device__ __align__(256) float g_scratch[SCRATCH_FLOATS];

static __device__ __forceinline__ float sigmoidf_(float x) {
    return 1.0f / (1.0f + expf(-x));
}

static __device__ __forceinline__ uint32_t smem_u32(const void* p) {
    uint32_t a;
    asm("{ .reg .u64 t; cvta.to.shared.u64 t, %1; cvt.u32.u64 %0, t; }"
        : "=r"(a) : "l"(p));
    return a;
}
static __device__ __forceinline__ uint32_t h2u(__half2 h) {
    return *reinterpret_cast<uint32_t*>(&h);
}

#define LDSM4(r0, r1, r2, r3, a)                                              \
    asm volatile("ldmatrix.sync.aligned.m8n8.x4.shared.b16 {%0,%1,%2,%3}, [%4];" \
                 : "=r"(r0), "=r"(r1), "=r"(r2), "=r"(r3) : "r"(a))

#define MMA16816H(c, a, b0, b1)                                               \
    asm volatile("mma.sync.aligned.m16n8k16.row.col.f32.f16.f16.f32 "         \
                 "{%0,%1,%2,%3}, {%4,%5,%6,%7}, {%8,%9}, {%0,%1,%2,%3};"      \
                 : "+f"((c)[0]), "+f"((c)[1]), "+f"((c)[2]), "+f"((c)[3])     \
                 : "r"((a)[0]), "r"((a)[1]), "r"((a)[2]), "r"((a)[3]),        \
                   "r"(b0), "r"(b1))

#define CP16(dst, src)                                                        \
    asm volatile("cp.async.cg.shared.global [%0], [%1], 16;"                  \
                 :: "r"(dst), "l"(src))
#define CP_COMMIT() asm volatile("cp.async.commit_group;" ::: "memory")
#define CP_WAIT0()  asm volatile("cp.async.wait_group 0;" ::: "memory")

// ---------------------------------------------------------------------------
// k_rowstats
// ---------------------------------------------------------------------------
__global__ void k_rowstats(const float* __restrict__ x,
                           float* __restrict__ mean, float* __restrict__ rstd) {
    int row = blockIdx.x;
    int t = threadIdx.x;
    float4 v = ((const float4*)(x + (size_t)row * D))[t];
    float s  = v.x + v.y + v.z + v.w;
    float s2 = v.x * v.x + v.y * v.y + v.z * v.z + v.w * v.w;
#pragma unroll
    for (int o = 16; o; o >>= 1) {
        s  += __shfl_down_sync(0xffffffffu, s,  o);
        s2 += __shfl_down_sync(0xffffffffu, s2, o);
    }
    __shared__ float ss[4], ss2[4];
    if ((t & 31) == 0) { ss[t >> 5] = s; ss2[t >> 5] = s2; }
    __syncthreads();
    if (t == 0) {
        float S  = ss[0] + ss[1] + ss[2] + ss[3];
        float S2 = ss2[0] + ss2[1] + ss2[2] + ss2[3];
        float m   = S * (1.0f / 512.0f);
        float var = S2 * (1.0f / 512.0f) - m * m;
        mean[row] = m;
        rstd[row] = rsqrtf(var + 1e-5f);
    }
}

// ---------------------------------------------------------------------------
// k_prepw: W = [Wk | Wv] -> K-major fp16: Bh[n][k], n in [0,1024).
// ---------------------------------------------------------------------------
__global__ void k_prepw(const float* __restrict__ Wk, const float* __restrict__ Wv,
                        __half* __restrict__ Bh) {
    int idx = blockIdx.x * 256 + threadIdx.x;   // 0..524287
    int k = idx >> 10;
    int n = idx & 1023;
    float w = (n < 512) ? Wk[k * 512 + n] : Wv[k * 512 + (n - 512)];
    Bh[(size_t)n * 512 + k] = __float2half_rn(w);
}

// ---------------------------------------------------------------------------
// k_mmagemm: [K|V] = LN(x) @ fp16([Wk|Wv]) + bias, fp16 2-pass A-split.
// Double-buffered smem; cp.async B; A LDG->LN->fp16 hi/lo in regs.
// Per k16 step: 32 independent MMAs (2 passes x 16 accs).
// ---------------------------------------------------------------------------
#define PBUF  49152
#define PAHI  0
#define PALO  16384
#define PBHI  32768
#define PG    98304
#define PBB   100352
#define PTOT  103424

__global__ __launch_bounds__(256, 1)
void k_mmagemm(const float* __restrict__ x,
               const __half* __restrict__ Bhg,
               const float* __restrict__ bk, const float* __restrict__ bv,
               const float* __restrict__ g, const float* __restrict__ bln,
               const float* __restrict__ mean, const float* __restrict__ rstd,
               float* __restrict__ outK, float* __restrict__ outV) {
    extern __shared__ char smraw[];
    char* smb = (char*)((((uintptr_t)smraw) + 1023) & ~(uintptr_t)1023);
    uint32_t sb = smem_u32(smb);
    int tid = threadIdx.x;
    int wid = tid >> 5;
    int lid = tid & 31;
    int n0 = blockIdx.x << 7;
    int m0 = blockIdx.y << 7;

    float* gs  = (float*)(smb + PG);
    float* bsn = (float*)(smb + PBB);
    for (int i = tid; i < 512; i += 256) { gs[i] = g[i]; bsn[i] = bln[i]; }

    const int ln = tid >> 1;          // local row 0..127
    const int kh = (tid & 1) << 5;    // k half 0/32 within 64-chunk
    const float m  = mean[m0 + ln];
    const float rs = rstd[m0 + ln];
    const float* xrow = x + (size_t)(m0 + ln) * D;
    const __half* bhr = Bhg + (size_t)(n0 + ln) * D;

    const int wm = (wid & 3) << 5;
    const int wn = (wid >> 2) << 6;

    uint32_t aoffA0, aoffA1, aoffB[4];
    {
        uint32_t r0 = (uint32_t)(wm + (lid & 15));
        aoffA0 = (r0 << 7) + ((lid >> 4) << 4);
        uint32_t r1 = r0 + 16;
        aoffA1 = (r1 << 7) + ((lid >> 4) << 4);
#pragma unroll
        for (int gi = 0; gi < 4; ++gi) {
            uint32_t rn = (uint32_t)(wn + (gi << 4) + (lid & 7) + ((lid >> 4) << 3));
            aoffB[gi] = (rn << 7) + (((lid >> 3) & 1) << 4);
        }
    }

    float acc[2][8][4];
#pragma unroll
    for (int i = 0; i < 2; i++)
#pragma unroll
        for (int j = 0; j < 8; j++)
#pragma unroll
            for (int q = 0; q < 4; q++) acc[i][j][q] = 0.f;

    __syncthreads();   // gs/bsn visible

    float4 ra[8];

    auto cpB = [&](int c, int p) {
        const int k0 = c << 6;
#pragma unroll
        for (int j = 0; j < 4; ++j) {
            uint32_t off = (ln << 7) + ((kh + (j << 3)) << 1);
            uint32_t sw = off ^ ((off >> 3) & 0x70);
            CP16(sb + p * PBUF + PBHI + sw, bhr + k0 + kh + (j << 3));
        }
        CP_COMMIT();
    };
    auto ldgA = [&](int c) {
        const int k0 = c << 6;
#pragma unroll
        for (int j = 0; j < 8; ++j)
            ra[j] = *(const float4*)(xrow + k0 + kh + (j << 2));
    };
    auto stsA = [&](int c, int p) {
        const int k0 = c << 6;
#pragma unroll
        for (int j = 0; j < 8; ++j) {
            const int kk = kh + (j << 2);
            float4 a = ra[j];
            float v0 = (a.x - m) * rs * gs[k0 + kk + 0] + bsn[k0 + kk + 0];
            float v1 = (a.y - m) * rs * gs[k0 + kk + 1] + bsn[k0 + kk + 1];
            float v2 = (a.z - m) * rs * gs[k0 + kk + 2] + bsn[k0 + kk + 2];
            float v3 = (a.w - m) * rs * gs[k0 + kk + 3] + bsn[k0 + kk + 3];
            __half h0 = __float2half_rn(v0), h1 = __float2half_rn(v1);
            __half h2 = __float2half_rn(v2), h3 = __float2half_rn(v3);
            __half l0 = __float2half_rn(v0 - __half2float(h0));
            __half l1 = __float2half_rn(v1 - __half2float(h1));
            __half l2 = __float2half_rn(v2 - __half2float(h2));
            __half l3 = __float2half_rn(v3 - __half2float(h3));
            uint32_t off = (ln << 7) + (kk << 1);
            uint32_t sw = off ^ ((off >> 3) & 0x70);
            *(uint2*)(smb + p * PBUF + PAHI + sw) =
                make_uint2(h2u(__halves2half2(h0, h1)), h2u(__halves2half2(h2, h3)));
            *(uint2*)(smb + p * PBUF + PALO + sw) =
                make_uint2(h2u(__halves2half2(l0, l1)), h2u(__halves2half2(l2, l3)));
        }
    };

    // 2 passes of 16 independent MMAs per k16 step.
    auto compute = [&](int p) {
        const uint32_t base = sb + p * PBUF;
#pragma unroll
        for (int s = 0; s < 4; ++s) {
            const uint32_t kb = s << 5;
            uint32_t o0 = aoffA0 + kb, o1 = aoffA1 + kb;
            uint32_t sw0 = o0 ^ ((o0 >> 3) & 0x70);
            uint32_t sw1 = o1 ^ ((o1 >> 3) & 0x70);
            uint32_t ah[2][4], al[2][4], bh[4][4];
            LDSM4(ah[0][0], ah[0][1], ah[0][2], ah[0][3], base + PAHI + sw0);
            LDSM4(ah[1][0], ah[1][1], ah[1][2], ah[1][3], base + PAHI + sw1);
            LDSM4(al[0][0], al[0][1], al[0][2], al[0][3], base + PALO + sw0);
            LDSM4(al[1][0], al[1][1], al[1][2], al[1][3], base + PALO + sw1);
#pragma unroll
            for (int gi = 0; gi < 4; ++gi) {
                uint32_t ob = aoffB[gi] + kb;
                uint32_t swb = ob ^ ((ob >> 3) & 0x70);
                LDSM4(bh[gi][0], bh[gi][1], bh[gi][2], bh[gi][3], base + PBHI + swb);
            }
            // pass 1: Ah x Bh (16 independent MMAs)
#pragma unroll
            for (int gi = 0; gi < 4; ++gi)
#pragma unroll
                for (int mt = 0; mt < 2; ++mt) {
                    MMA16816H(acc[mt][gi * 2 + 0], ah[mt], bh[gi][0], bh[gi][1]);
                    MMA16816H(acc[mt][gi * 2 + 1], ah[mt], bh[gi][2], bh[gi][3]);
                }
            // pass 2: Al x Bh
#pragma unroll
            for (int gi = 0; gi < 4; ++gi)
#pragma unroll
                for (int mt = 0; mt < 2; ++mt) {
                    MMA16816H(acc[mt][gi * 2 + 0], al[mt], bh[gi][0], bh[gi][1]);
                    MMA16816H(acc[mt][gi * 2 + 1], al[mt], bh[gi][2], bh[gi][3]);
                }
        }
    };

    // prologue
    ldgA(0);
    cpB(0, 0);
    stsA(0, 0);
    ldgA(1);
    CP_WAIT0();
    __syncthreads();

    for (int c = 0; c < 8; ++c) {
        const int p = c & 1;
        if (c < 7) cpB(c + 1, p ^ 1);
        compute(p);
        if (c < 7) {
            stsA(c + 1, p ^ 1);
            if (c < 6) ldgA(c + 2);
            CP_WAIT0();
            __syncthreads();
        }
    }
    __syncthreads();

    // epilogue: regs -> smem stage -> coalesced gmem (+bias)
    float* stage = (float*)smb;   // [128][132] = 67584B <= 2*PBUF
    const int qrow = lid >> 2;
    const int qcol = (lid & 3) << 1;
#pragma unroll
    for (int mt = 0; mt < 2; ++mt) {
#pragma unroll
        for (int nt = 0; nt < 8; ++nt) {
            int r = wm + mt * 16 + qrow;
            int ccol = wn + nt * 8 + qcol;
            *(float2*)&stage[r * 132 + ccol] =
                make_float2(acc[mt][nt][0], acc[mt][nt][1]);
            *(float2*)&stage[(r + 8) * 132 + ccol] =
                make_float2(acc[mt][nt][2], acc[mt][nt][3]);
        }
    }
    __syncthreads();

    const float* bias = (n0 < 512) ? (bk + n0) : (bv + (n0 - 512));
    float* outp = (n0 < 512) ? (outK + n0) : (outV + (n0 - 512));
    {
        int row = tid >> 1;
        int ch = (tid & 1) << 6;
#pragma unroll
        for (int i = 0; i < 16; ++i) {
            int cb = ch + (i << 2);
            float4 o;
            o.x = stage[row * 132 + cb + 0] + bias[cb + 0];
            o.y = stage[row * 132 + cb + 1] + bias[cb + 1];
            o.z = stage[row * 132 + cb + 2] + bias[cb + 2];
            o.w = stage[row * 132 + cb + 3] + bias[cb + 3];
            *(float4*)(outp + (size_t)(m0 + row) * D + cb) = o;
        }
    }
}

// ---------------------------------------------------------------------------
// LN over 64 rows of 512.
// ---------------------------------------------------------------------------
__global__ void k_ln64(const float* __restrict__ in, const float* __restrict__ g,
                       const float* __restrict__ b, float* __restrict__ out) {
    int r = blockIdx.x, t = threadIdx.x;
    float4 v = ((const float4*)(in + (size_t)r * D))[t];
    float s  = v.x + v.y + v.z + v.w;
    float s2 = v.x * v.x + v.y * v.y + v.z * v.z + v.w * v.w;
#pragma unroll
    for (int o = 16; o; o >>= 1) {
        s  += __shfl_down_sync(0xffffffffu, s,  o);
        s2 += __shfl_down_sync(0xffffffffu, s2, o);
    }
    __shared__ float ss[4], ss2[4];
    __shared__ float sm, srs;
    if ((t & 31) == 0) { ss[t >> 5] = s; ss2[t >> 5] = s2; }
    __syncthreads();
    if (t == 0) {
        float S  = ss[0] + ss[1] + ss[2] + ss[3];
        float S2 = ss2[0] + ss2[1] + ss2[2] + ss2[3];
        float m   = S * (1.0f / 512.0f);
        float var = S2 * (1.0f / 512.0f) - m * m;
        sm = m; srs = rsqrtf(var + 1e-5f);
    }
    __syncthreads();
    float m = sm, rs = srs;
    float4 gg = ((const float4*)g)[t];
    float4 bb = ((const float4*)b)[t];
    float4 o;
    o.x = (v.x - m) * rs * gg.x + bb.x;
    o.y = (v.y - m) * rs * gg.y + bb.y;
    o.z = (v.z - m) * rs * gg.z + bb.z;
    o.w = (v.w - m) * rs * gg.w + bb.w;
    ((float4*)(out + (size_t)r * D))[t] = o;
}

// ---------------------------------------------------------------------------
// Small GEMM with register prefetch; gridDim.y selects (A,W,bias,out) set.
// ---------------------------------------------------------------------------
template <int TRANSW>
__global__ __launch_bounds__(256) void k_gemm64(
    const float* __restrict__ A, const float* __restrict__ A2,
    const float* __restrict__ W, const float* __restrict__ W2,
    const float* __restrict__ bias, const float* __restrict__ bias2,
    const float* __restrict__ resid,
    float* __restrict__ out, float* __restrict__ out2, int ncols, int relu) {
    __shared__ float As[32][64];
    __shared__ float Ws[32][33];
    int tid  = threadIdx.x;
    int col0 = blockIdx.x << 5;
    int ty = tid >> 5, tx = tid & 31;
    int ar0 = tid >> 3, akp = (tid & 7) << 2;

    const float* Ause = blockIdx.y ? A2 : A;
    const float* Wuse = blockIdx.y ? W2 : W;
    const float* buse = blockIdx.y ? bias2 : bias;
    float* outuse = blockIdx.y ? out2 : out;

    float acc[8];
#pragma unroll
    for (int i = 0; i < 8; i++) acc[i] = 0.f;

    int wn = tid >> 3, wkp = (tid & 7) << 2;
    int wk = tid >> 3, wnp = (tid & 7) << 2;

    float4 pa0 = *(const float4*)(Ause + (size_t)ar0 * D + akp);
    float4 pa1 = *(const float4*)(Ause + (size_t)(ar0 + 32) * D + akp);
    float4 pw;
    if (TRANSW)
        pw = *(const float4*)(Wuse + (size_t)(col0 + wn) * D + wkp);
    else
        pw = *(const float4*)(Wuse + (size_t)wk * ncols + col0 + wnp);

    for (int kt = 0; kt < 512; kt += 32) {
        As[akp + 0][ar0] = pa0.x; As[akp + 1][ar0] = pa0.y;
        As[akp + 2][ar0] = pa0.z; As[akp + 3][ar0] = pa0.w;
        As[akp + 0][ar0 + 32] = pa1.x; As[akp + 1][ar0 + 32] = pa1.y;
        As[akp + 2][ar0 + 32] = pa1.z; As[akp + 3][ar0 + 32] = pa1.w;
        if (TRANSW) {
            Ws[wkp + 0][wn] = pw.x; Ws[wkp + 1][wn] = pw.y;
            Ws[wkp + 2][wn] = pw.z; Ws[wkp + 3][wn] = pw.w;
        } else {
            Ws[wk][wnp + 0] = pw.x; Ws[wk][wnp + 1] = pw.y;
            Ws[wk][wnp + 2] = pw.z; Ws[wk][wnp + 3] = pw.w;
        }
        __syncthreads();
        if (kt + 32 < 512) {
            pa0 = *(const float4*)(Ause + (size_t)ar0 * D + kt + 32 + akp);
            pa1 = *(const float4*)(Ause + (size_t)(ar0 + 32) * D + kt + 32 + akp);
            if (TRANSW)
                pw = *(const float4*)(Wuse + (size_t)(col0 + wn) * D + kt + 32 + wkp);
            else
                pw = *(const float4*)(Wuse + (size_t)(kt + 32 + wk) * ncols + col0 + wnp);
        }
#pragma unroll
        for (int kk = 0; kk < 32; kk++) {
            float w = Ws[kk][tx];
            float a[8];
            *(float4*)&a[0] = *(const float4*)&As[kk][ty << 3];
            *(float4*)&a[4] = *(const float4*)&As[kk][(ty << 3) + 4];
#pragma unroll
            for (int r = 0; r < 8; r++) acc[r] += a[r] * w;
        }
        __syncthreads();
    }

    float bvv = buse[col0 + tx];
#pragma unroll
    for (int r = 0; r < 8; r++) {
        int row = (ty << 3) + r;
        float val = acc[r] + bvv;
        if (relu) val = fmaxf(val, 0.f);
        if (resid) val += resid[(size_t)row * D + col0 + tx];
        outuse[(size_t)row * ncols + col0 + tx] = val;
    }
}

// ---------------------------------------------------------------------------
// dots + softmax over the slot axis.
// ---------------------------------------------------------------------------
__global__ __launch_bounds__(128) void k_dots(const float* __restrict__ q,
                                              const float* __restrict__ k,
                                              float* __restrict__ attn_pre) {
    int b = blockIdx.y, j0 = blockIdx.x << 7;
    int t = threadIdx.x;
    __shared__ float qs0[512], qs1[512];
    __shared__ float ks[128][65];
    {
        float4 q0 = ((const float4*)(q + (size_t)(b * 2 + 0) * D))[t];
        float4 q1 = ((const float4*)(q + (size_t)(b * 2 + 1) * D))[t];
        *(float4*)&qs0[t << 2] = q0;
        *(float4*)&qs1[t << 2] = q1;
    }
    float d0 = 0.f, d1 = 0.f;
    const float* kb = k + ((size_t)b * 2048 + j0) * D;
    for (int kc = 0; kc < 512; kc += 64) {
        __syncthreads();
#pragma unroll
        for (int i = 0; i < 16; i++) {
            int f = t + (i << 7);
            int j = f >> 4, kp = (f & 15) << 2;
            float4 kv = *(const float4*)(kb + (size_t)j * D + kc + kp);
            ks[j][kp + 0] = kv.x; ks[j][kp + 1] = kv.y;
            ks[j][kp + 2] = kv.z; ks[j][kp + 3] = kv.w;
        }
        __syncthreads();
#pragma unroll
        for (int kk = 0; kk < 64; kk++) {
            float kv = ks[t][kk];
            d0 += kv * qs0[kc + kk];
            d1 += kv * qs1[kc + kk];
        }
    }
    const float SC = 0.044194173824159216f;
    d0 *= SC; d1 *= SC;
    float mx = fmaxf(d0, d1);
    float e0 = expf(d0 - mx), e1 = expf(d1 - mx);
    float inv = 1.0f / (e0 + e1);
    attn_pre[b * 4096 + (j0 + t)]        = e0 * inv;
    attn_pre[b * 4096 + 2048 + (j0 + t)] = e1 * inv;
}

// ---------------------------------------------------------------------------
// updates = (v^T @ attn_row) / (rowsum + eps); d-tile 0 also writes attn_out.
// ---------------------------------------------------------------------------
__global__ __launch_bounds__(128) void k_upd(const float* __restrict__ attn_pre,
                                             const float* __restrict__ v,
                                             float* __restrict__ upd,
                                             float* __restrict__ attn_out) {
    int b = blockIdx.y, d0 = blockIdx.x << 7, t = threadIdx.x;
    const float* a0p = attn_pre + b * 4096;
    const float* a1p = a0p + 2048;
    float s0 = 0.f, s1 = 0.f;
    for (int j = t; j < 2048; j += 128) { s0 += a0p[j]; s1 += a1p[j]; }
#pragma unroll
    for (int o = 16; o; o >>= 1) {
        s0 += __shfl_down_sync(0xffffffffu, s0, o);
        s1 += __shfl_down_sync(0xffffffffu, s1, o);
    }
    __shared__ float r0[4], r1[4];
    if ((t & 31) == 0) { r0[t >> 5] = s0; r1[t >> 5] = s1; }
    __syncthreads();
    float inv0 = 1.0f / (r0[0] + r0[1] + r0[2] + r0[3] + 1e-8f);
    float inv1 = 1.0f / (r1[0] + r1[1] + r1[2] + r1[3] + 1e-8f);

    if (d0 == 0) {
        float* ao0 = attn_out + b * 4096;
        float* ao1 = ao0 + 2048;
        for (int j = t; j < 2048; j += 128) {
            ao0[j] = a0p[j] * inv0;
            ao1[j] = a1p[j] * inv1;
        }
    }

    __shared__ float w0[256], w1[256];
    float acc0 = 0.f, acc1 = 0.f;
    const float* vb = v + (size_t)b * 2048 * D + d0 + t;
    for (int jc = 0; jc < 2048; jc += 256) {
        __syncthreads();
        w0[t] = a0p[jc + t]; w0[t + 128] = a0p[jc + t + 128];
        w1[t] = a1p[jc + t]; w1[t + 128] = a1p[jc + t + 128];
        __syncthreads();
#pragma unroll 8
        for (int jj = 0; jj < 256; jj++) {
            float vv = vb[(size_t)(jc + jj) * D];
            acc0 += vv * w0[jj];
            acc1 += vv * w1[jj];
        }
    }
    upd[(size_t)(b * 2 + 0) * D + d0 + t] = acc0 * inv0;
    upd[(size_t)(b * 2 + 1) * D + d0 + t] = acc1 * inv1;
}

// ---------------------------------------------------------------------------
// Fused GRU gates + LayerNorm(h_new). 64 blocks x 128 threads.
// ---------------------------------------------------------------------------
__global__ void k_gruln(const float* __restrict__ gx, const float* __restrict__ gh,
                        const float* __restrict__ slots,
                        const float* __restrict__ g, const float* __restrict__ b,
                        float* __restrict__ hnew, float* __restrict__ hln) {
    int r = blockIdx.x, t = threadIdx.x;
    const float* gxr = gx + (size_t)r * 1536;
    const float* ghr = gh + (size_t)r * 1536;
    float4 xr = ((const float4*)(gxr))[t];
    float4 hr = ((const float4*)(ghr))[t];
    float4 xz = ((const float4*)(gxr + 512))[t];
    float4 hz = ((const float4*)(ghr + 512))[t];
    float4 xn = ((const float4*)(gxr + 1024))[t];
    float4 hn = ((const float4*)(ghr + 1024))[t];
    float4 hp = ((const float4*)(slots + (size_t)r * D))[t];

    float h[4];
    {
        float rg, z, n;
        rg = sigmoidf_(xr.x + hr.x); z = sigmoidf_(xz.x + hz.x);
        n = tanhf(xn.x + rg * hn.x); h[0] = (1.f - z) * n + z * hp.x;
        rg = sigmoidf_(xr.y + hr.y); z = sigmoidf_(xz.y + hz.y);
        n = tanhf(xn.y + rg * hn.y); h[1] = (1.f - z) * n + z * hp.y;
        rg = sigmoidf_(xr.z + hr.z); z = sigmoidf_(xz.z + hz.z);
        n = tanhf(xn.z + rg * hn.z); h[2] = (1.f - z) * n + z * hp.z;
        rg = sigmoidf_(xr.w + hr.w); z = sigmoidf_(xz.w + hz.w);
        n = tanhf(xn.w + rg * hn.w); h[3] = (1.f - z) * n + z * hp.w;
    }
    ((float4*)(hnew + (size_t)r * D))[t] = make_float4(h[0], h[1], h[2], h[3]);

    float s  = h[0] + h[1] + h[2] + h[3];
    float s2 = h[0]*h[0] + h[1]*h[1] + h[2]*h[2] + h[3]*h[3];
#pragma unroll
    for (int o = 16; o; o >>= 1) {
        s  += __shfl_down_sync(0xffffffffu, s,  o);
        s2 += __shfl_down_sync(0xffffffffu, s2, o);
    }
    __shared__ float ss[4], ss2[4];
    __shared__ float sm, srs;
    if ((t & 31) == 0) { ss[t >> 5] = s; ss2[t >> 5] = s2; }
    __syncthreads();
    if (t == 0) {
        float S  = ss[0] + ss[1] + ss[2] + ss[3];
        float S2 = ss2[0] + ss2[1] + ss2[2] + ss2[3];
        float mm  = S * (1.0f / 512.0f);
        float var = S2 * (1.0f / 512.0f) - mm * mm;
        sm = mm; srs = rsqrtf(var + 1e-5f);
    }
    __syncthreads();
    float mm = sm, rs = srs;
    float4 gg = ((const float4*)g)[t];
    float4 bb = ((const float4*)b)[t];
    float4 o;
    o.x = (h[0] - mm) * rs * gg.x + bb.x;
    o.y = (h[1] - mm) * rs * gg.y + bb.y;
    o.z = (h[2] - mm) * rs * gg.z + bb.z;
    o.w = (h[3] - mm) * rs * gg.w + bb.w;
    ((float4*)(hln + (size_t)r * D))[t] = o;
}

// ---------------------------------------------------------------------------
// host
// ---------------------------------------------------------------------------
extern "C" void kernel_launch(void* const* d_in, const int* in_sizes, int n_in,
                              void* d_out, int out_size) {
    (void)in_sizes; (void)n_in; (void)out_size;
    const float* inputs     = (const float*)d_in[0];
    const float* init_slots = (const float*)d_in[1];
    const float* Wq  = (const float*)d_in[2];
    const float* bq  = (const float*)d_in[3];
    const float* Wk  = (const float*)d_in[4];
    const float* bk  = (const float*)d_in[5];
    const float* Wv  = (const float*)d_in[6];
    const float* bv  = (const float*)d_in[7];
    const float* ln_in_g = (const float*)d_in[8];
    const float* ln_in_b = (const float*)d_in[9];
    const float* ln_s_g  = (const float*)d_in[10];
    const float* ln_s_b  = (const float*)d_in[11];
    const float* ln_f_g  = (const float*)d_in[12];
    const float* ln_f_b  = (const float*)d_in[13];
    const float* gru_wih = (const float*)d_in[14];
    const float* gru_whh = (const float*)d_in[15];
    const float* gru_bih = (const float*)d_in[16];
    const float* gru_bhh = (const float*)d_in[17];
    const float* W1 = (const float*)d_in[18];
    const float* b1 = (const float*)d_in[19];
    const float* W2 = (const float*)d_in[20];
    const float* b2 = (const float*)d_in[21];

    float* out      = (float*)d_out;
    float* slots    = out;
    float* qout     = out + 32768;
    float* kout     = out + 65536;
    float* attn_out = out + 65536 + 33554432;

    float* S = nullptr;
    cudaGetSymbolAddress((void**)&S, g_scratch);
    float* v    = S + OFF_V;
    float* mean = S + OFF_MEAN;
    float* rstd = S + OFF_RSTD;
    float* attn = S + OFF_ATTN;
    float* sln  = S + OFF_SLN;
    float* upd  = S + OFF_UPD;
    float* gx   = S + OFF_GX;
    float* gh   = S + OFF_GH;
    float* hnew = S + OFF_HNEW;
    float* hln  = S + OFF_HLN;
    float* tbuf = S + OFF_T;
    __half* whi = (__half*)(S + OFF_WHI);

    cudaFuncSetAttribute(k_mmagemm, cudaFuncAttributeMaxDynamicSharedMemorySize,
                         PTOT);

    cudaMemcpyAsync(slots, init_slots, 32768 * sizeof(float),
                    cudaMemcpyDeviceToDevice);

    k_prepw<<<2048, 256>>>(Wk, Wv, whi);
    k_rowstats<<<NROWS, 128>>>(inputs, mean, rstd);
    k_mmagemm<<<dim3(8, 512), 256, PTOT>>>(inputs, whi, bk, bv,
                                           ln_in_g, ln_in_b, mean, rstd,
                                           kout, v);

    for (int it = 0; it < 3; ++it) {
        k_ln64<<<64, 128>>>(slots, ln_s_g, ln_s_b, sln);
        k_gemm64<0><<<dim3(16, 1), 256>>>(sln, sln, Wq, Wq, bq, bq, nullptr,
                                          qout, qout, 512, 0);
        k_dots<<<dim3(16, 32), 128>>>(qout, kout, attn);
        k_upd<<<dim3(4, 32), 128>>>(attn, v, upd, attn_out);
        k_gemm64<1><<<dim3(48, 2), 256>>>(upd, slots, gru_wih, gru_whh,
                                          gru_bih, gru_bhh, nullptr,
                                          gx, gh, 1536, 0);
        k_gruln<<<64, 128>>>(gx, gh, slots, ln_f_g, ln_f_b, hnew, hln);
        k_gemm64<0><<<dim3(16, 1), 256>>>(hln, hln, W1, W1, b1, b1, nullptr,
                                          tbuf, tbuf, 512, 1);
        k_gemm64<0><<<dim3(16, 1), 256>>>(tbuf, tbuf, W2, W2, b2, b2, hnew,
                                          slots, slots, 512, 0);
    }
}

// round 12
// speedup vs baseline: 1.4722x; 1.0667x over previous
#include <cuda_runtime.h>
#include <cuda_fp16.h>
#include <math.h>
#include <stdint.h>

// ---------------------------------------------------------------------------
// SlotAttention. B=32, N=2048, DIN=DOUT=HID=512, S=2, ITERS=3.
// Big LN+GEMM (k,v): pipelined mma.sync SINGLE-PASS fp16 (A rn, B rn).
// rel_err budget ~3e-4 << 1e-3 (validated error model rounds 9/11).
// 2 CTAs/SM (68KB smem each) to hide non-MMA overhead.
// ---------------------------------------------------------------------------

#define NROWS 65536
#define D 512

// ---- scratch ----
#define OFF_V     0
#define OFF_MEAN  33554432
#define OFF_RSTD  (33554432 + 65536)
#define OFF_ATTN  (33554432 + 131072)
#define OFF_SLN   (OFF_ATTN + 131072)
#define OFF_UPD   (OFF_SLN  + 32768)
#define OFF_GX    (OFF_UPD  + 32768)
#define OFF_GH    (OFF_GX   + 98304)
#define OFF_HNEW  (OFF_GH   + 98304)
#define OFF_HLN   (OFF_HNEW + 32768)
#define OFF_T     (OFF_HLN  + 32768)
#define OFF_WHI   (OFF_T    + 32768)   // 1024x512 fp16 = 131072 "floats"
#define SCRATCH_FLOATS (OFF_WHI + 131072)

__device__ __align__(256) float g_scratch[SCRATCH_FLOATS];

static __device__ __forceinline__ float sigmoidf_(float x) {
    return 1.0f / (1.0f + expf(-x));
}

static __device__ __forceinline__ uint32_t smem_u32(const void* p) {
    uint32_t a;
    asm("{ .reg .u64 t; cvta.to.shared.u64 t, %1; cvt.u32.u64 %0, t; }"
        : "=r"(a) : "l"(p));
    return a;
}
static __device__ __forceinline__ uint32_t h2u(__half2 h) {
    return *reinterpret_cast<uint32_t*>(&h);
}

#define LDSM4(r0, r1, r2, r3, a)                                              \
    asm volatile("ldmatrix.sync.aligned.m8n8.x4.shared.b16 {%0,%1,%2,%3}, [%4];" \
                 : "=r"(r0), "=r"(r1), "=r"(r2), "=r"(r3) : "r"(a))

#define MMA16816H(c, a, b0, b1)                                               \
    asm volatile("mma.sync.aligned.m16n8k16.row.col.f32.f16.f16.f32 "         \
                 "{%0,%1,%2,%3}, {%4,%5,%6,%7}, {%8,%9}, {%0,%1,%2,%3};"      \
                 : "+f"((c)[0]), "+f"((c)[1]), "+f"((c)[2]), "+f"((c)[3])     \
                 : "r"((a)[0]), "r"((a)[1]), "r"((a)[2]), "r"((a)[3]),        \
                   "r"(b0), "r"(b1))

#define CP16(dst, src)                                                        \
    asm volatile("cp.async.cg.shared.global [%0], [%1], 16;"                  \
                 :: "r"(dst), "l"(src))
#define CP_COMMIT() asm volatile("cp.async.commit_group;" ::: "memory")
#define CP_WAIT0()  asm volatile("cp.async.wait_group 0;" ::: "memory")

// ---------------------------------------------------------------------------
// k_rowstats
// ---------------------------------------------------------------------------
__global__ void k_rowstats(const float* __restrict__ x,
                           float* __restrict__ mean, float* __restrict__ rstd) {
    int row = blockIdx.x;
    int t = threadIdx.x;
    float4 v = ((const float4*)(x + (size_t)row * D))[t];
    float s  = v.x + v.y + v.z + v.w;
    float s2 = v.x * v.x + v.y * v.y + v.z * v.z + v.w * v.w;
#pragma unroll
    for (int o = 16; o; o >>= 1) {
        s  += __shfl_down_sync(0xffffffffu, s,  o);
        s2 += __shfl_down_sync(0xffffffffu, s2, o);
    }
    __shared__ float ss[4], ss2[4];
    if ((t & 31) == 0) { ss[t >> 5] = s; ss2[t >> 5] = s2; }
    __syncthreads();
    if (t == 0) {
        float S  = ss[0] + ss[1] + ss[2] + ss[3];
        float S2 = ss2[0] + ss2[1] + ss2[2] + ss2[3];
        float m   = S * (1.0f / 512.0f);
        float var = S2 * (1.0f / 512.0f) - m * m;
        mean[row] = m;
        rstd[row] = rsqrtf(var + 1e-5f);
    }
}

// ---------------------------------------------------------------------------
// k_prepw: W = [Wk | Wv] -> K-major fp16: Bh[n][k], n in [0,1024).
// ---------------------------------------------------------------------------
__global__ void k_prepw(const float* __restrict__ Wk, const float* __restrict__ Wv,
                        __half* __restrict__ Bh) {
    int idx = blockIdx.x * 256 + threadIdx.x;   // 0..524287
    int k = idx >> 10;
    int n = idx & 1023;
    float w = (n < 512) ? Wk[k * 512 + n] : Wv[k * 512 + (n - 512)];
    Bh[(size_t)n * 512 + k] = __float2half_rn(w);
}

// ---------------------------------------------------------------------------
// k_mmagemm: [K|V] = LN(x) @ fp16([Wk|Wv]) + bias, single-pass fp16.
// Double-buffered smem; cp.async B; A LDG->LN->fp16 in regs.
// Per k16 step: 6 LDSM + 16 independent MMAs.
// ---------------------------------------------------------------------------
#define PBUF  32768
#define PAHI  0
#define PBHI  16384
#define PG    65536
#define PBB   67584
#define PTOT  70656

__global__ __launch_bounds__(256, 2)
void k_mmagemm(const float* __restrict__ x,
               const __half* __restrict__ Bhg,
               const float* __restrict__ bk, const float* __restrict__ bv,
               const float* __restrict__ g, const float* __restrict__ bln,
               const float* __restrict__ mean, const float* __restrict__ rstd,
               float* __restrict__ outK, float* __restrict__ outV) {
    extern __shared__ char smraw[];
    char* smb = (char*)((((uintptr_t)smraw) + 1023) & ~(uintptr_t)1023);
    uint32_t sb = smem_u32(smb);
    int tid = threadIdx.x;
    int wid = tid >> 5;
    int lid = tid & 31;
    int n0 = blockIdx.x << 7;
    int m0 = blockIdx.y << 7;

    float* gs  = (float*)(smb + PG);
    float* bsn = (float*)(smb + PBB);
    for (int i = tid; i < 512; i += 256) { gs[i] = g[i]; bsn[i] = bln[i]; }

    const int ln = tid >> 1;          // local row 0..127
    const int kh = (tid & 1) << 5;    // k half 0/32 within 64-chunk
    const float m  = mean[m0 + ln];
    const float rs = rstd[m0 + ln];
    const float* xrow = x + (size_t)(m0 + ln) * D;
    const __half* bhr = Bhg + (size_t)(n0 + ln) * D;

    const int wm = (wid & 3) << 5;
    const int wn = (wid >> 2) << 6;

    uint32_t aoffA0, aoffA1, aoffB[4];
    {
        uint32_t r0 = (uint32_t)(wm + (lid & 15));
        aoffA0 = (r0 << 7) + ((lid >> 4) << 4);
        uint32_t r1 = r0 + 16;
        aoffA1 = (r1 << 7) + ((lid >> 4) << 4);
#pragma unroll
        for (int gi = 0; gi < 4; ++gi) {
            uint32_t rn = (uint32_t)(wn + (gi << 4) + (lid & 7) + ((lid >> 4) << 3));
            aoffB[gi] = (rn << 7) + (((lid >> 3) & 1) << 4);
        }
    }

    float acc[2][8][4];
#pragma unroll
    for (int i = 0; i < 2; i++)
#pragma unroll
        for (int j = 0; j < 8; j++)
#pragma unroll
            for (int q = 0; q < 4; q++) acc[i][j][q] = 0.f;

    __syncthreads();   // gs/bsn visible

    float4 ra[8];

    auto cpB = [&](int c, int p) {
        const int k0 = c << 6;
#pragma unroll
        for (int j = 0; j < 4; ++j) {
            uint32_t off = (ln << 7) + ((kh + (j << 3)) << 1);
            uint32_t sw = off ^ ((off >> 3) & 0x70);
            CP16(sb + p * PBUF + PBHI + sw, bhr + k0 + kh + (j << 3));
        }
        CP_COMMIT();
    };
    auto ldgA = [&](int c) {
        const int k0 = c << 6;
#pragma unroll
        for (int j = 0; j < 8; ++j)
            ra[j] = *(const float4*)(xrow + k0 + kh + (j << 2));
    };
    auto stsA = [&](int c, int p) {
        const int k0 = c << 6;
#pragma unroll
        for (int j = 0; j < 8; ++j) {
            const int kk = kh + (j << 2);
            float4 a = ra[j];
            float v0 = (a.x - m) * rs * gs[k0 + kk + 0] + bsn[k0 + kk + 0];
            float v1 = (a.y - m) * rs * gs[k0 + kk + 1] + bsn[k0 + kk + 1];
            float v2 = (a.z - m) * rs * gs[k0 + kk + 2] + bsn[k0 + kk + 2];
            float v3 = (a.w - m) * rs * gs[k0 + kk + 3] + bsn[k0 + kk + 3];
            __half h0 = __float2half_rn(v0), h1 = __float2half_rn(v1);
            __half h2 = __float2half_rn(v2), h3 = __float2half_rn(v3);
            uint32_t off = (ln << 7) + (kk << 1);
            uint32_t sw = off ^ ((off >> 3) & 0x70);
            *(uint2*)(smb + p * PBUF + PAHI + sw) =
                make_uint2(h2u(__halves2half2(h0, h1)), h2u(__halves2half2(h2, h3)));
        }
    };

    // Single pass: 16 independent MMAs per k16 step.
    auto compute = [&](int p) {
        const uint32_t base = sb + p * PBUF;
#pragma unroll
        for (int s = 0; s < 4; ++s) {
            const uint32_t kb = s << 5;
            uint32_t o0 = aoffA0 + kb, o1 = aoffA1 + kb;
            uint32_t sw0 = o0 ^ ((o0 >> 3) & 0x70);
            uint32_t sw1 = o1 ^ ((o1 >> 3) & 0x70);
            uint32_t ah[2][4], bh[4][4];
            LDSM4(ah[0][0], ah[0][1], ah[0][2], ah[0][3], base + PAHI + sw0);
            LDSM4(ah[1][0], ah[1][1], ah[1][2], ah[1][3], base + PAHI + sw1);
#pragma unroll
            for (int gi = 0; gi < 4; ++gi) {
                uint32_t ob = aoffB[gi] + kb;
                uint32_t swb = ob ^ ((ob >> 3) & 0x70);
                LDSM4(bh[gi][0], bh[gi][1], bh[gi][2], bh[gi][3], base + PBHI + swb);
            }
#pragma unroll
            for (int gi = 0; gi < 4; ++gi)
#pragma unroll
                for (int mt = 0; mt < 2; ++mt) {
                    MMA16816H(acc[mt][gi * 2 + 0], ah[mt], bh[gi][0], bh[gi][1]);
                    MMA16816H(acc[mt][gi * 2 + 1], ah[mt], bh[gi][2], bh[gi][3]);
                }
        }
    };

    // prologue
    ldgA(0);
    cpB(0, 0);
    stsA(0, 0);
    ldgA(1);
    CP_WAIT0();
    __syncthreads();

    for (int c = 0; c < 8; ++c) {
        const int p = c & 1;
        if (c < 7) cpB(c + 1, p ^ 1);
        compute(p);
        if (c < 7) {
            stsA(c + 1, p ^ 1);
            if (c < 6) ldgA(c + 2);
            CP_WAIT0();
            __syncthreads();
        }
    }
    __syncthreads();

    // epilogue: regs -> smem stage -> coalesced gmem (+bias)
    float* stage = (float*)smb;   // [128][132] = 67584B <= PTOT
    const int qrow = lid >> 2;
    const int qcol = (lid & 3) << 1;
#pragma unroll
    for (int mt = 0; mt < 2; ++mt) {
#pragma unroll
        for (int nt = 0; nt < 8; ++nt) {
            int r = wm + mt * 16 + qrow;
            int ccol = wn + nt * 8 + qcol;
            *(float2*)&stage[r * 132 + ccol] =
                make_float2(acc[mt][nt][0], acc[mt][nt][1]);
            *(float2*)&stage[(r + 8) * 132 + ccol] =
                make_float2(acc[mt][nt][2], acc[mt][nt][3]);
        }
    }
    __syncthreads();

    const float* bias = (n0 < 512) ? (bk + n0) : (bv + (n0 - 512));
    float* outp = (n0 < 512) ? (outK + n0) : (outV + (n0 - 512));
    {
        int row = tid >> 1;
        int ch = (tid & 1) << 6;
#pragma unroll
        for (int i = 0; i < 16; ++i) {
            int cb = ch + (i << 2);
            float4 o;
            o.x = stage[row * 132 + cb + 0] + bias[cb + 0];
            o.y = stage[row * 132 + cb + 1] + bias[cb + 1];
            o.z = stage[row * 132 + cb + 2] + bias[cb + 2];
            o.w = stage[row * 132 + cb + 3] + bias[cb + 3];
            *(float4*)(outp + (size_t)(m0 + row) * D + cb) = o;
        }
    }
}

// ---------------------------------------------------------------------------
// LN over 64 rows of 512.
// ---------------------------------------------------------------------------
__global__ void k_ln64(const float* __restrict__ in, const float* __restrict__ g,
                       const float* __restrict__ b, float* __restrict__ out) {
    int r = blockIdx.x, t = threadIdx.x;
    float4 v = ((const float4*)(in + (size_t)r * D))[t];
    float s  = v.x + v.y + v.z + v.w;
    float s2 = v.x * v.x + v.y * v.y + v.z * v.z + v.w * v.w;
#pragma unroll
    for (int o = 16; o; o >>= 1) {
        s  += __shfl_down_sync(0xffffffffu, s,  o);
        s2 += __shfl_down_sync(0xffffffffu, s2, o);
    }
    __shared__ float ss[4], ss2[4];
    __shared__ float sm, srs;
    if ((t & 31) == 0) { ss[t >> 5] = s; ss2[t >> 5] = s2; }
    __syncthreads();
    if (t == 0) {
        float S  = ss[0] + ss[1] + ss[2] + ss[3];
        float S2 = ss2[0] + ss2[1] + ss2[2] + ss2[3];
        float m   = S * (1.0f / 512.0f);
        float var = S2 * (1.0f / 512.0f) - m * m;
        sm = m; srs = rsqrtf(var + 1e-5f);
    }
    __syncthreads();
    float m = sm, rs = srs;
    float4 gg = ((const float4*)g)[t];
    float4 bb = ((const float4*)b)[t];
    float4 o;
    o.x = (v.x - m) * rs * gg.x + bb.x;
    o.y = (v.y - m) * rs * gg.y + bb.y;
    o.z = (v.z - m) * rs * gg.z + bb.z;
    o.w = (v.w - m) * rs * gg.w + bb.w;
    ((float4*)(out + (size_t)r * D))[t] = o;
}

// ---------------------------------------------------------------------------
// Small GEMM with register prefetch; gridDim.y selects (A,W,bias,out) set.
// ---------------------------------------------------------------------------
template <int TRANSW>
__global__ __launch_bounds__(256) void k_gemm64(
    const float* __restrict__ A, const float* __restrict__ A2,
    const float* __restrict__ W, const float* __restrict__ W2,
    const float* __restrict__ bias, const float* __restrict__ bias2,
    const float* __restrict__ resid,
    float* __restrict__ out, float* __restrict__ out2, int ncols, int relu) {
    __shared__ float As[32][64];
    __shared__ float Ws[32][33];
    int tid  = threadIdx.x;
    int col0 = blockIdx.x << 5;
    int ty = tid >> 5, tx = tid & 31;
    int ar0 = tid >> 3, akp = (tid & 7) << 2;

    const float* Ause = blockIdx.y ? A2 : A;
    const float* Wuse = blockIdx.y ? W2 : W;
    const float* buse = blockIdx.y ? bias2 : bias;
    float* outuse = blockIdx.y ? out2 : out;

    float acc[8];
#pragma unroll
    for (int i = 0; i < 8; i++) acc[i] = 0.f;

    int wn = tid >> 3, wkp = (tid & 7) << 2;
    int wk = tid >> 3, wnp = (tid & 7) << 2;

    float4 pa0 = *(const float4*)(Ause + (size_t)ar0 * D + akp);
    float4 pa1 = *(const float4*)(Ause + (size_t)(ar0 + 32) * D + akp);
    float4 pw;
    if (TRANSW)
        pw = *(const float4*)(Wuse + (size_t)(col0 + wn) * D + wkp);
    else
        pw = *(const float4*)(Wuse + (size_t)wk * ncols + col0 + wnp);

    for (int kt = 0; kt < 512; kt += 32) {
        As[akp + 0][ar0] = pa0.x; As[akp + 1][ar0] = pa0.y;
        As[akp + 2][ar0] = pa0.z; As[akp + 3][ar0] = pa0.w;
        As[akp + 0][ar0 + 32] = pa1.x; As[akp + 1][ar0 + 32] = pa1.y;
        As[akp + 2][ar0 + 32] = pa1.z; As[akp + 3][ar0 + 32] = pa1.w;
        if (TRANSW) {
            Ws[wkp + 0][wn] = pw.x; Ws[wkp + 1][wn] = pw.y;
            Ws[wkp + 2][wn] = pw.z; Ws[wkp + 3][wn] = pw.w;
        } else {
            Ws[wk][wnp + 0] = pw.x; Ws[wk][wnp + 1] = pw.y;
            Ws[wk][wnp + 2] = pw.z; Ws[wk][wnp + 3] = pw.w;
        }
        __syncthreads();
        if (kt + 32 < 512) {
            pa0 = *(const float4*)(Ause + (size_t)ar0 * D + kt + 32 + akp);
            pa1 = *(const float4*)(Ause + (size_t)(ar0 + 32) * D + kt + 32 + akp);
            if (TRANSW)
                pw = *(const float4*)(Wuse + (size_t)(col0 + wn) * D + kt + 32 + wkp);
            else
                pw = *(const float4*)(Wuse + (size_t)(kt + 32 + wk) * ncols + col0 + wnp);
        }
#pragma unroll
        for (int kk = 0; kk < 32; kk++) {
            float w = Ws[kk][tx];
            float a[8];
            *(float4*)&a[0] = *(const float4*)&As[kk][ty << 3];
            *(float4*)&a[4] = *(const float4*)&As[kk][(ty << 3) + 4];
#pragma unroll
            for (int r = 0; r < 8; r++) acc[r] += a[r] * w;
        }
        __syncthreads();
    }

    float bvv = buse[col0 + tx];
#pragma unroll
    for (int r = 0; r < 8; r++) {
        int row = (ty << 3) + r;
        float val = acc[r] + bvv;
        if (relu) val = fmaxf(val, 0.f);
        if (resid) val += resid[(size_t)row * D + col0 + tx];
        outuse[(size_t)row * ncols + col0 + tx] = val;
    }
}

// ---------------------------------------------------------------------------
// dots + softmax over the slot axis.
// ---------------------------------------------------------------------------
__global__ __launch_bounds__(128) void k_dots(const float* __restrict__ q,
                                              const float* __restrict__ k,
                                              float* __restrict__ attn_pre) {
    int b = blockIdx.y, j0 = blockIdx.x << 7;
    int t = threadIdx.x;
    __shared__ float qs0[512], qs1[512];
    __shared__ float ks[128][65];
    {
        float4 q0 = ((const float4*)(q + (size_t)(b * 2 + 0) * D))[t];
        float4 q1 = ((const float4*)(q + (size_t)(b * 2 + 1) * D))[t];
        *(float4*)&qs0[t << 2] = q0;
        *(float4*)&qs1[t << 2] = q1;
    }
    float d0 = 0.f, d1 = 0.f;
    const float* kb = k + ((size_t)b * 2048 + j0) * D;
    for (int kc = 0; kc < 512; kc += 64) {
        __syncthreads();
#pragma unroll
        for (int i = 0; i < 16; i++) {
            int f = t + (i << 7);
            int j = f >> 4, kp = (f & 15) << 2;
            float4 kv = *(const float4*)(kb + (size_t)j * D + kc + kp);
            ks[j][kp + 0] = kv.x; ks[j][kp + 1] = kv.y;
            ks[j][kp + 2] = kv.z; ks[j][kp + 3] = kv.w;
        }
        __syncthreads();
#pragma unroll
        for (int kk = 0; kk < 64; kk++) {
            float kv = ks[t][kk];
            d0 += kv * qs0[kc + kk];
            d1 += kv * qs1[kc + kk];
        }
    }
    const float SC = 0.044194173824159216f;
    d0 *= SC; d1 *= SC;
    float mx = fmaxf(d0, d1);
    float e0 = expf(d0 - mx), e1 = expf(d1 - mx);
    float inv = 1.0f / (e0 + e1);
    attn_pre[b * 4096 + (j0 + t)]        = e0 * inv;
    attn_pre[b * 4096 + 2048 + (j0 + t)] = e1 * inv;
}

// ---------------------------------------------------------------------------
// updates = (v^T @ attn_row) / (rowsum + eps); d-tile 0 also writes attn_out.
// ---------------------------------------------------------------------------
__global__ __launch_bounds__(128) void k_upd(const float* __restrict__ attn_pre,
                                             const float* __restrict__ v,
                                             float* __restrict__ upd,
                                             float* __restrict__ attn_out) {
    int b = blockIdx.y, d0 = blockIdx.x << 7, t = threadIdx.x;
    const float* a0p = attn_pre + b * 4096;
    const float* a1p = a0p + 2048;
    float s0 = 0.f, s1 = 0.f;
    for (int j = t; j < 2048; j += 128) { s0 += a0p[j]; s1 += a1p[j]; }
#pragma unroll
    for (int o = 16; o; o >>= 1) {
        s0 += __shfl_down_sync(0xffffffffu, s0, o);
        s1 += __shfl_down_sync(0xffffffffu, s1, o);
    }
    __shared__ float r0[4], r1[4];
    if ((t & 31) == 0) { r0[t >> 5] = s0; r1[t >> 5] = s1; }
    __syncthreads();
    float inv0 = 1.0f / (r0[0] + r0[1] + r0[2] + r0[3] + 1e-8f);
    float inv1 = 1.0f / (r1[0] + r1[1] + r1[2] + r1[3] + 1e-8f);

    if (d0 == 0) {
        float* ao0 = attn_out + b * 4096;
        float* ao1 = ao0 + 2048;
        for (int j = t; j < 2048; j += 128) {
            ao0[j] = a0p[j] * inv0;
            ao1[j] = a1p[j] * inv1;
        }
    }

    __shared__ float w0[256], w1[256];
    float acc0 = 0.f, acc1 = 0.f;
    const float* vb = v + (size_t)b * 2048 * D + d0 + t;
    for (int jc = 0; jc < 2048; jc += 256) {
        __syncthreads();
        w0[t] = a0p[jc + t]; w0[t + 128] = a0p[jc + t + 128];
        w1[t] = a1p[jc + t]; w1[t + 128] = a1p[jc + t + 128];
        __syncthreads();
#pragma unroll 8
        for (int jj = 0; jj < 256; jj++) {
            float vv = vb[(size_t)(jc + jj) * D];
            acc0 += vv * w0[jj];
            acc1 += vv * w1[jj];
        }
    }
    upd[(size_t)(b * 2 + 0) * D + d0 + t] = acc0 * inv0;
    upd[(size_t)(b * 2 + 1) * D + d0 + t] = acc1 * inv1;
}

// ---------------------------------------------------------------------------
// Fused GRU gates + LayerNorm(h_new). 64 blocks x 128 threads.
// ---------------------------------------------------------------------------
__global__ void k_gruln(const float* __restrict__ gx, const float* __restrict__ gh,
                        const float* __restrict__ slots,
                        const float* __restrict__ g, const float* __restrict__ b,
                        float* __restrict__ hnew, float* __restrict__ hln) {
    int r = blockIdx.x, t = threadIdx.x;
    const float* gxr = gx + (size_t)r * 1536;
    const float* ghr = gh + (size_t)r * 1536;
    float4 xr = ((const float4*)(gxr))[t];
    float4 hr = ((const float4*)(ghr))[t];
    float4 xz = ((const float4*)(gxr + 512))[t];
    float4 hz = ((const float4*)(ghr + 512))[t];
    float4 xn = ((const float4*)(gxr + 1024))[t];
    float4 hn = ((const float4*)(ghr + 1024))[t];
    float4 hp = ((const float4*)(slots + (size_t)r * D))[t];

    float h[4];
    {
        float rg, z, n;
        rg = sigmoidf_(xr.x + hr.x); z = sigmoidf_(xz.x + hz.x);
        n = tanhf(xn.x + rg * hn.x); h[0] = (1.f - z) * n + z * hp.x;
        rg = sigmoidf_(xr.y + hr.y); z = sigmoidf_(xz.y + hz.y);
        n = tanhf(xn.y + rg * hn.y); h[1] = (1.f - z) * n + z * hp.y;
        rg = sigmoidf_(xr.z + hr.z); z = sigmoidf_(xz.z + hz.z);
        n = tanhf(xn.z + rg * hn.z); h[2] = (1.f - z) * n + z * hp.z;
        rg = sigmoidf_(xr.w + hr.w); z = sigmoidf_(xz.w + hz.w);
        n = tanhf(xn.w + rg * hn.w); h[3] = (1.f - z) * n + z * hp.w;
    }
    ((float4*)(hnew + (size_t)r * D))[t] = make_float4(h[0], h[1], h[2], h[3]);

    float s  = h[0] + h[1] + h[2] + h[3];
    float s2 = h[0]*h[0] + h[1]*h[1] + h[2]*h[2] + h[3]*h[3];
#pragma unroll
    for (int o = 16; o; o >>= 1) {
        s  += __shfl_down_sync(0xffffffffu, s,  o);
        s2 += __shfl_down_sync(0xffffffffu, s2, o);
    }
    __shared__ float ss[4], ss2[4];
    __shared__ float sm, srs;
    if ((t & 31) == 0) { ss[t >> 5] = s; ss2[t >> 5] = s2; }
    __syncthreads();
    if (t == 0) {
        float S  = ss[0] + ss[1] + ss[2] + ss[3];
        float S2 = ss2[0] + ss2[1] + ss2[2] + ss2[3];
        float mm  = S * (1.0f / 512.0f);
        float var = S2 * (1.0f / 512.0f) - mm * mm;
        sm = mm; srs = rsqrtf(var + 1e-5f);
    }
    __syncthreads();
    float mm = sm, rs = srs;
    float4 gg = ((const float4*)g)[t];
    float4 bb = ((const float4*)b)[t];
    float4 o;
    o.x = (h[0] - mm) * rs * gg.x + bb.x;
    o.y = (h[1] - mm) * rs * gg.y + bb.y;
    o.z = (h[2] - mm) * rs * gg.z + bb.z;
    o.w = (h[3] - mm) * rs * gg.w + bb.w;
    ((float4*)(hln + (size_t)r * D))[t] = o;
}

// ---------------------------------------------------------------------------
// host
// ---------------------------------------------------------------------------
extern "C" void kernel_launch(void* const* d_in, const int* in_sizes, int n_in,
                              void* d_out, int out_size) {
    (void)in_sizes; (void)n_in; (void)out_size;
    const float* inputs     = (const float*)d_in[0];
    const float* init_slots = (const float*)d_in[1];
    const float* Wq  = (const float*)d_in[2];
    const float* bq  = (const float*)d_in[3];
    const float* Wk  = (const float*)d_in[4];
    const float* bk  = (const float*)d_in[5];
    const float* Wv  = (const float*)d_in[6];
    const float* bv  = (const float*)d_in[7];
    const float* ln_in_g = (const float*)d_in[8];
    const float* ln_in_b = (const float*)d_in[9];
    const float* ln_s_g  = (const float*)d_in[10];
    const float* ln_s_b  = (const float*)d_in[11];
    const float* ln_f_g  = (const float*)d_in[12];
    const float* ln_f_b  = (const float*)d_in[13];
    const float* gru_wih = (const float*)d_in[14];
    const float* gru_whh = (const float*)d_in[15];
    const float* gru_bih = (const float*)d_in[16];
    const float* gru_bhh = (const float*)d_in[17];
    const float* W1 = (const float*)d_in[18];
    const float* b1 = (const float*)d_in[19];
    const float* W2 = (const float*)d_in[20];
    const float* b2 = (const float*)d_in[21];

    float* out      = (float*)d_out;
    float* slots    = out;
    float* qout     = out + 32768;
    float* kout     = out + 65536;
    float* attn_out = out + 65536 + 33554432;

    float* S = nullptr;
    cudaGetSymbolAddress((void**)&S, g_scratch);
    float* v    = S + OFF_V;
    float* mean = S + OFF_MEAN;
    float* rstd = S + OFF_RSTD;
    float* attn = S + OFF_ATTN;
    float* sln  = S + OFF_SLN;
    float* upd  = S + OFF_UPD;
    float* gx   = S + OFF_GX;
    float* gh   = S + OFF_GH;
    float* hnew = S + OFF_HNEW;
    float* hln  = S + OFF_HLN;
    float* tbuf = S + OFF_T;
    __half* whi = (__half*)(S + OFF_WHI);

    cudaFuncSetAttribute(k_mmagemm, cudaFuncAttributeMaxDynamicSharedMemorySize,
                         PTOT);

    cudaMemcpyAsync(slots, init_slots, 32768 * sizeof(float),
                    cudaMemcpyDeviceToDevice);

    k_prepw<<<2048, 256>>>(Wk, Wv, whi);
    k_rowstats<<<NROWS, 128>>>(inputs, mean, rstd);
    k_mmagemm<<<dim3(8, 512), 256, PTOT>>>(inputs, whi, bk, bv,
                                           ln_in_g, ln_in_b, mean, rstd,
                                           kout, v);

    for (int it = 0; it < 3; ++it) {
        k_ln64<<<64, 128>>>(slots, ln_s_g, ln_s_b, sln);
        k_gemm64<0><<<dim3(16, 1), 256>>>(sln, sln, Wq, Wq, bq, bq, nullptr,
                                          qout, qout, 512, 0);
        k_dots<<<dim3(16, 32), 128>>>(qout, kout, attn);
        k_upd<<<dim3(4, 32), 128>>>(attn, v, upd, attn_out);
        k_gemm64<1><<<dim3(48, 2), 256>>>(upd, slots, gru_wih, gru_whh,
                                          gru_bih, gru_bhh, nullptr,
                                          gx, gh, 1536, 0);
        k_gruln<<<64, 128>>>(gx, gh, slots, ln_f_g, ln_f_b, hnew, hln);
        k_gemm64<0><<<dim3(16, 1), 256>>>(hln, hln, W1, W1, b1, b1, nullptr,
                                          tbuf, tbuf, 512, 1);
        k_gemm64<0><<<dim3(16, 1), 256>>>(tbuf, tbuf, W2, W2, b2, b2, hnew,
                                          slots, slots, 512, 0);
    }
}

// round 15
// speedup vs baseline: 1.7092x; 1.1610x over previous
#include <cuda_runtime.h>
#include <cuda_fp16.h>
#include <math.h>
#include <stdint.h>

// ---------------------------------------------------------------------------
// SlotAttention. B=32, N=2048, DIN=DOUT=HID=512, S=2, ITERS=3.
// k_prepx: LN(x)->fp16 once. Big GEMM: pure fp16 mma.sync; A via LDG(uint4)
// + proven STS path; B via cp.async.
// FIX vs R13/14: whi region is 262144 floats (1024x512 halves), xh moved
// past it (was overlapping -> Wv half clobbered by xh).
// ---------------------------------------------------------------------------

#define NROWS 65536
#define D 512

// ---- scratch ----
#define OFF_V     0
#define OFF_ATTN  33554432                 // 32*2*2048
#define OFF_SLN   (OFF_ATTN + 131072)
#define OFF_UPD   (OFF_SLN  + 32768)
#define OFF_GX    (OFF_UPD  + 32768)
#define OFF_GH    (OFF_GX   + 98304)
#define OFF_HNEW  (OFF_GH   + 98304)
#define OFF_HLN   (OFF_HNEW + 32768)
#define OFF_T     (OFF_HLN  + 32768)
#define OFF_WHI   (OFF_T    + 32768)       // 1024x512 fp16 = 524288 halves = 262144 floats
#define OFF_XH    (OFF_WHI  + 262144)      // 65536x512 fp16 = 16777216 floats
#define SCRATCH_FLOATS (OFF_XH + 16777216)

__device__ __align__(256) float g_scratch[SCRATCH_FLOATS];

static __device__ __forceinline__ float sigmoidf_(float x) {
    return 1.0f / (1.0f + expf(-x));
}

static __device__ __forceinline__ uint32_t smem_u32(const void* p) {
    uint32_t a;
    asm("{ .reg .u64 t; cvta.to.shared.u64 t, %1; cvt.u32.u64 %0, t; }"
        : "=r"(a) : "l"(p));
    return a;
}
static __device__ __forceinline__ uint32_t h2u(__half2 h) {
    return *reinterpret_cast<uint32_t*>(&h);
}

#define LDSM4(r0, r1, r2, r3, a)                                              \
    asm volatile("ldmatrix.sync.aligned.m8n8.x4.shared.b16 {%0,%1,%2,%3}, [%4];" \
                 : "=r"(r0), "=r"(r1), "=r"(r2), "=r"(r3) : "r"(a))

#define MMA16816H(c, a, b0, b1)                                               \
    asm volatile("mma.sync.aligned.m16n8k16.row.col.f32.f16.f16.f32 "         \
                 "{%0,%1,%2,%3}, {%4,%5,%6,%7}, {%8,%9}, {%0,%1,%2,%3};"      \
                 : "+f"((c)[0]), "+f"((c)[1]), "+f"((c)[2]), "+f"((c)[3])     \
                 : "r"((a)[0]), "r"((a)[1]), "r"((a)[2]), "r"((a)[3]),        \
                   "r"(b0), "r"(b1))

#define CP16(dst, src)                                                        \
    asm volatile("cp.async.cg.shared.global [%0], [%1], 16;"                  \
                 :: "r"(dst), "l"(src))
#define CP_COMMIT() asm volatile("cp.async.commit_group;" ::: "memory")
#define CP_WAIT0()  asm volatile("cp.async.wait_group 0;" ::: "memory")

// ---------------------------------------------------------------------------
// k_prepx: rowstats + LN + fp16 quantize in one pass. 65536 blocks x 128.
// ---------------------------------------------------------------------------
__global__ void k_prepx(const float* __restrict__ x,
                        const float* __restrict__ g, const float* __restrict__ b,
                        __half* __restrict__ xh) {
    int row = blockIdx.x;
    int t = threadIdx.x;
    float4 v = ((const float4*)(x + (size_t)row * D))[t];
    float s  = v.x + v.y + v.z + v.w;
    float s2 = v.x * v.x + v.y * v.y + v.z * v.z + v.w * v.w;
#pragma unroll
    for (int o = 16; o; o >>= 1) {
        s  += __shfl_down_sync(0xffffffffu, s,  o);
        s2 += __shfl_down_sync(0xffffffffu, s2, o);
    }
    __shared__ float ss[4], ss2[4];
    __shared__ float sm, srs;
    if ((t & 31) == 0) { ss[t >> 5] = s; ss2[t >> 5] = s2; }
    __syncthreads();
    if (t == 0) {
        float S  = ss[0] + ss[1] + ss[2] + ss[3];
        float S2 = ss2[0] + ss2[1] + ss2[2] + ss2[3];
        float m   = S * (1.0f / 512.0f);
        float var = S2 * (1.0f / 512.0f) - m * m;
        sm = m; srs = rsqrtf(var + 1e-5f);
    }
    __syncthreads();
    float m = sm, rs = srs;
    float4 gg = ((const float4*)g)[t];
    float4 bb = ((const float4*)b)[t];
    float v0 = (v.x - m) * rs * gg.x + bb.x;
    float v1 = (v.y - m) * rs * gg.y + bb.y;
    float v2 = (v.z - m) * rs * gg.z + bb.z;
    float v3 = (v.w - m) * rs * gg.w + bb.w;
    __half2 p0 = __halves2half2(__float2half_rn(v0), __float2half_rn(v1));
    __half2 p1 = __halves2half2(__float2half_rn(v2), __float2half_rn(v3));
    *(uint2*)(xh + (size_t)row * D + (t << 2)) = make_uint2(h2u(p0), h2u(p1));
}

// ---------------------------------------------------------------------------
// k_prepw: W = [Wk | Wv] -> K-major fp16: Bh[n][k], n in [0,1024).
// ---------------------------------------------------------------------------
__global__ void k_prepw(const float* __restrict__ Wk, const float* __restrict__ Wv,
                        __half* __restrict__ Bh) {
    int idx = blockIdx.x * 256 + threadIdx.x;   // 0..524287
    int k = idx >> 10;
    int n = idx & 1023;
    float w = (n < 512) ? Wk[k * 512 + n] : Wv[k * 512 + (n - 512)];
    Bh[(size_t)n * 512 + k] = __float2half_rn(w);
}

// ---------------------------------------------------------------------------
// k_mmagemm: [K|V] = xh @ Bh^T + bias. Pure fp16 GEMM.
// A: LDG uint4 from xh (prefetch 1 chunk ahead) + STS uint2.
// B: cp.async. K chunks of 64, double-buffered.
// ---------------------------------------------------------------------------
#define PBUF  32768
#define PAHI  0
#define PBHI  16384
#define PTOT  69632   // stage (67584B) + align slack

__global__ __launch_bounds__(256, 2)
void k_mmagemm(const __half* __restrict__ Ahg,
               const __half* __restrict__ Bhg,
               const float* __restrict__ bk, const float* __restrict__ bv,
               float* __restrict__ outK, float* __restrict__ outV) {
    extern __shared__ char smraw[];
    char* smb = (char*)((((uintptr_t)smraw) + 1023) & ~(uintptr_t)1023);
    uint32_t sb = smem_u32(smb);
    int tid = threadIdx.x;
    int wid = tid >> 5;
    int lid = tid & 31;
    int n0 = blockIdx.x << 7;
    int m0 = blockIdx.y << 7;

    const int ln = tid >> 1;          // local row 0..127
    const int kh = (tid & 1) << 5;    // k half 0/32 within 64-chunk
    const __half* ahr = Ahg + (size_t)(m0 + ln) * D;
    const __half* bhr = Bhg + (size_t)(n0 + ln) * D;

    const int wm = (wid & 3) << 5;
    const int wn = (wid >> 2) << 6;

    uint32_t aoffA0, aoffA1, aoffB[4];
    {
        uint32_t r0 = (uint32_t)(wm + (lid & 15));
        aoffA0 = (r0 << 7) + ((lid >> 4) << 4);
        uint32_t r1 = r0 + 16;
        aoffA1 = (r1 << 7) + ((lid >> 4) << 4);
#pragma unroll
        for (int gi = 0; gi < 4; ++gi) {
            uint32_t rn = (uint32_t)(wn + (gi << 4) + (lid & 7) + ((lid >> 4) << 3));
            aoffB[gi] = (rn << 7) + (((lid >> 3) & 1) << 4);
        }
    }

    float acc[2][8][4];
#pragma unroll
    for (int i = 0; i < 2; i++)
#pragma unroll
        for (int j = 0; j < 8; j++)
#pragma unroll
            for (int q = 0; q < 4; q++) acc[i][j][q] = 0.f;

    uint4 ra[4];   // A chunk prefetch: 4 x 16B = cols kh..kh+31

    auto cpB = [&](int c, int p) {
        const int k0 = c << 6;
#pragma unroll
        for (int j = 0; j < 4; ++j) {
            uint32_t off = (ln << 7) + ((kh + (j << 3)) << 1);
            uint32_t sw = off ^ ((off >> 3) & 0x70);
            CP16(sb + p * PBUF + PBHI + sw, bhr + k0 + kh + (j << 3));
        }
        CP_COMMIT();
    };
    auto ldgA = [&](int c) {
        const int k0 = c << 6;
#pragma unroll
        for (int j = 0; j < 4; ++j)
            ra[j] = *(const uint4*)(ahr + k0 + kh + (j << 3));
    };
    auto stsA = [&](int p) {
#pragma unroll
        for (int j = 0; j < 4; ++j) {
            const int kk = kh + (j << 3);
            uint32_t off0 = (ln << 7) + (kk << 1);
            uint32_t sw0 = off0 ^ ((off0 >> 3) & 0x70);
            *(uint2*)(smb + p * PBUF + PAHI + sw0) = make_uint2(ra[j].x, ra[j].y);
            uint32_t off1 = (ln << 7) + ((kk + 4) << 1);
            uint32_t sw1 = off1 ^ ((off1 >> 3) & 0x70);
            *(uint2*)(smb + p * PBUF + PAHI + sw1) = make_uint2(ra[j].z, ra[j].w);
        }
    };

    auto compute = [&](int p) {
        const uint32_t base = sb + p * PBUF;
#pragma unroll
        for (int s = 0; s < 4; ++s) {
            const uint32_t kb = s << 5;
            uint32_t o0 = aoffA0 + kb, o1 = aoffA1 + kb;
            uint32_t sw0 = o0 ^ ((o0 >> 3) & 0x70);
            uint32_t sw1 = o1 ^ ((o1 >> 3) & 0x70);
            uint32_t ah[2][4], bh[4][4];
            LDSM4(ah[0][0], ah[0][1], ah[0][2], ah[0][3], base + PAHI + sw0);
            LDSM4(ah[1][0], ah[1][1], ah[1][2], ah[1][3], base + PAHI + sw1);
#pragma unroll
            for (int gi = 0; gi < 4; ++gi) {
                uint32_t ob = aoffB[gi] + kb;
                uint32_t swb = ob ^ ((ob >> 3) & 0x70);
                LDSM4(bh[gi][0], bh[gi][1], bh[gi][2], bh[gi][3], base + PBHI + swb);
            }
#pragma unroll
            for (int gi = 0; gi < 4; ++gi)
#pragma unroll
                for (int mt = 0; mt < 2; ++mt) {
                    MMA16816H(acc[mt][gi * 2 + 0], ah[mt], bh[gi][0], bh[gi][1]);
                    MMA16816H(acc[mt][gi * 2 + 1], ah[mt], bh[gi][2], bh[gi][3]);
                }
        }
    };

    // prologue
    ldgA(0);
    cpB(0, 0);
    stsA(0);
    ldgA(1);
    CP_WAIT0();
    __syncthreads();

    for (int c = 0; c < 8; ++c) {
        const int p = c & 1;
        if (c < 7) cpB(c + 1, p ^ 1);
        compute(p);
        if (c < 7) {
            stsA(p ^ 1);
            if (c < 6) ldgA(c + 2);
            CP_WAIT0();
            __syncthreads();
        }
    }
    __syncthreads();

    // epilogue: regs -> smem stage -> coalesced gmem (+bias)
    float* stage = (float*)smb;   // [128][132] = 67584B <= PTOT
    const int qrow = lid >> 2;
    const int qcol = (lid & 3) << 1;
#pragma unroll
    for (int mt = 0; mt < 2; ++mt) {
#pragma unroll
        for (int nt = 0; nt < 8; ++nt) {
            int r = wm + mt * 16 + qrow;
            int ccol = wn + nt * 8 + qcol;
            *(float2*)&stage[r * 132 + ccol] =
                make_float2(acc[mt][nt][0], acc[mt][nt][1]);
            *(float2*)&stage[(r + 8) * 132 + ccol] =
                make_float2(acc[mt][nt][2], acc[mt][nt][3]);
        }
    }
    __syncthreads();

    const float* bias = (n0 < 512) ? (bk + n0) : (bv + (n0 - 512));
    float* outp = (n0 < 512) ? (outK + n0) : (outV + (n0 - 512));
    {
        int row = tid >> 1;
        int ch = (tid & 1) << 6;
#pragma unroll
        for (int i = 0; i < 16; ++i) {
            int cb = ch + (i << 2);
            float4 o;
            o.x = stage[row * 132 + cb + 0] + bias[cb + 0];
            o.y = stage[row * 132 + cb + 1] + bias[cb + 1];
            o.z = stage[row * 132 + cb + 2] + bias[cb + 2];
            o.w = stage[row * 132 + cb + 3] + bias[cb + 3];
            *(float4*)(outp + (size_t)(m0 + row) * D + cb) = o;
        }
    }
}

// ---------------------------------------------------------------------------
// LN over 64 rows of 512.
// ---------------------------------------------------------------------------
__global__ void k_ln64(const float* __restrict__ in, const float* __restrict__ g,
                       const float* __restrict__ b, float* __restrict__ out) {
    int r = blockIdx.x, t = threadIdx.x;
    float4 v = ((const float4*)(in + (size_t)r * D))[t];
    float s  = v.x + v.y + v.z + v.w;
    float s2 = v.x * v.x + v.y * v.y + v.z * v.z + v.w * v.w;
#pragma unroll
    for (int o = 16; o; o >>= 1) {
        s  += __shfl_down_sync(0xffffffffu, s,  o);
        s2 += __shfl_down_sync(0xffffffffu, s2, o);
    }
    __shared__ float ss[4], ss2[4];
    __shared__ float sm, srs;
    if ((t & 31) == 0) { ss[t >> 5] = s; ss2[t >> 5] = s2; }
    __syncthreads();
    if (t == 0) {
        float S  = ss[0] + ss[1] + ss[2] + ss[3];
        float S2 = ss2[0] + ss2[1] + ss2[2] + ss2[3];
        float m   = S * (1.0f / 512.0f);
        float var = S2 * (1.0f / 512.0f) - m * m;
        sm = m; srs = rsqrtf(var + 1e-5f);
    }
    __syncthreads();
    float m = sm, rs = srs;
    float4 gg = ((const float4*)g)[t];
    float4 bb = ((const float4*)b)[t];
    float4 o;
    o.x = (v.x - m) * rs * gg.x + bb.x;
    o.y = (v.y - m) * rs * gg.y + bb.y;
    o.z = (v.z - m) * rs * gg.z + bb.z;
    o.w = (v.w - m) * rs * gg.w + bb.w;
    ((float4*)(out + (size_t)r * D))[t] = o;
}

// ---------------------------------------------------------------------------
// Small GEMM with register prefetch; gridDim.y selects (A,W,bias,out) set.
// ---------------------------------------------------------------------------
template <int TRANSW>
__global__ __launch_bounds__(256) void k_gemm64(
    const float* __restrict__ A, const float* __restrict__ A2,
    const float* __restrict__ W, const float* __restrict__ W2,
    const float* __restrict__ bias, const float* __restrict__ bias2,
    const float* __restrict__ resid,
    float* __restrict__ out, float* __restrict__ out2, int ncols, int relu) {
    __shared__ float As[32][64];
    __shared__ float Ws[32][33];
    int tid  = threadIdx.x;
    int col0 = blockIdx.x << 5;
    int ty = tid >> 5, tx = tid & 31;
    int ar0 = tid >> 3, akp = (tid & 7) << 2;

    const float* Ause = blockIdx.y ? A2 : A;
    const float* Wuse = blockIdx.y ? W2 : W;
    const float* buse = blockIdx.y ? bias2 : bias;
    float* outuse = blockIdx.y ? out2 : out;

    float acc[8];
#pragma unroll
    for (int i = 0; i < 8; i++) acc[i] = 0.f;

    int wn = tid >> 3, wkp = (tid & 7) << 2;
    int wk = tid >> 3, wnp = (tid & 7) << 2;

    float4 pa0 = *(const float4*)(Ause + (size_t)ar0 * D + akp);
    float4 pa1 = *(const float4*)(Ause + (size_t)(ar0 + 32) * D + akp);
    float4 pw;
    if (TRANSW)
        pw = *(const float4*)(Wuse + (size_t)(col0 + wn) * D + wkp);
    else
        pw = *(const float4*)(Wuse + (size_t)wk * ncols + col0 + wnp);

    for (int kt = 0; kt < 512; kt += 32) {
        As[akp + 0][ar0] = pa0.x; As[akp + 1][ar0] = pa0.y;
        As[akp + 2][ar0] = pa0.z; As[akp + 3][ar0] = pa0.w;
        As[akp + 0][ar0 + 32] = pa1.x; As[akp + 1][ar0 + 32] = pa1.y;
        As[akp + 2][ar0 + 32] = pa1.z; As[akp + 3][ar0 + 32] = pa1.w;
        if (TRANSW) {
            Ws[wkp + 0][wn] = pw.x; Ws[wkp + 1][wn] = pw.y;
            Ws[wkp + 2][wn] = pw.z; Ws[wkp + 3][wn] = pw.w;
        } else {
            Ws[wk][wnp + 0] = pw.x; Ws[wk][wnp + 1] = pw.y;
            Ws[wk][wnp + 2] = pw.z; Ws[wk][wnp + 3] = pw.w;
        }
        __syncthreads();
        if (kt + 32 < 512) {
            pa0 = *(const float4*)(Ause + (size_t)ar0 * D + kt + 32 + akp);
            pa1 = *(const float4*)(Ause + (size_t)(ar0 + 32) * D + kt + 32 + akp);
            if (TRANSW)
                pw = *(const float4*)(Wuse + (size_t)(col0 + wn) * D + kt + 32 + wkp);
            else
                pw = *(const float4*)(Wuse + (size_t)(kt + 32 + wk) * ncols + col0 + wnp);
        }
#pragma unroll
        for (int kk = 0; kk < 32; kk++) {
            float w = Ws[kk][tx];
            float a[8];
            *(float4*)&a[0] = *(const float4*)&As[kk][ty << 3];
            *(float4*)&a[4] = *(const float4*)&As[kk][(ty << 3) + 4];
#pragma unroll
            for (int r = 0; r < 8; r++) acc[r] += a[r] * w;
        }
        __syncthreads();
    }

    float bvv = buse[col0 + tx];
#pragma unroll
    for (int r = 0; r < 8; r++) {
        int row = (ty << 3) + r;
        float val = acc[r] + bvv;
        if (relu) val = fmaxf(val, 0.f);
        if (resid) val += resid[(size_t)row * D + col0 + tx];
        outuse[(size_t)row * ncols + col0 + tx] = val;
    }
}

// ---------------------------------------------------------------------------
// dots + softmax over the slot axis.
// ---------------------------------------------------------------------------
__global__ __launch_bounds__(128) void k_dots(const float* __restrict__ q,
                                              const float* __restrict__ k,
                                              float* __restrict__ attn_pre) {
    int b = blockIdx.y, j0 = blockIdx.x << 7;
    int t = threadIdx.x;
    __shared__ float qs0[512], qs1[512];
    __shared__ float ks[128][65];
    {
        float4 q0 = ((const float4*)(q + (size_t)(b * 2 + 0) * D))[t];
        float4 q1 = ((const float4*)(q + (size_t)(b * 2 + 1) * D))[t];
        *(float4*)&qs0[t << 2] = q0;
        *(float4*)&qs1[t << 2] = q1;
    }
    float d0 = 0.f, d1 = 0.f;
    const float* kb = k + ((size_t)b * 2048 + j0) * D;
    for (int kc = 0; kc < 512; kc += 64) {
        __syncthreads();
#pragma unroll
        for (int i = 0; i < 16; i++) {
            int f = t + (i << 7);
            int j = f >> 4, kp = (f & 15) << 2;
            float4 kv = *(const float4*)(kb + (size_t)j * D + kc + kp);
            ks[j][kp + 0] = kv.x; ks[j][kp + 1] = kv.y;
            ks[j][kp + 2] = kv.z; ks[j][kp + 3] = kv.w;
        }
        __syncthreads();
#pragma unroll
        for (int kk = 0; kk < 64; kk++) {
            float kv = ks[t][kk];
            d0 += kv * qs0[kc + kk];
            d1 += kv * qs1[kc + kk];
        }
    }
    const float SC = 0.044194173824159216f;
    d0 *= SC; d1 *= SC;
    float mx = fmaxf(d0, d1);
    float e0 = expf(d0 - mx), e1 = expf(d1 - mx);
    float inv = 1.0f / (e0 + e1);
    attn_pre[b * 4096 + (j0 + t)]        = e0 * inv;
    attn_pre[b * 4096 + 2048 + (j0 + t)] = e1 * inv;
}

// ---------------------------------------------------------------------------
// updates = (v^T @ attn_row) / (rowsum + eps); d-tile 0 also writes attn_out.
// ---------------------------------------------------------------------------
__global__ __launch_bounds__(128) void k_upd(const float* __restrict__ attn_pre,
                                             const float* __restrict__ v,
                                             float* __restrict__ upd,
                                             float* __restrict__ attn_out) {
    int b = blockIdx.y, d0 = blockIdx.x << 7, t = threadIdx.x;
    const float* a0p = attn_pre + b * 4096;
    const float* a1p = a0p + 2048;
    float s0 = 0.f, s1 = 0.f;
    for (int j = t; j < 2048; j += 128) { s0 += a0p[j]; s1 += a1p[j]; }
#pragma unroll
    for (int o = 16; o; o >>= 1) {
        s0 += __shfl_down_sync(0xffffffffu, s0, o);
        s1 += __shfl_down_sync(0xffffffffu, s1, o);
    }
    __shared__ float r0[4], r1[4];
    if ((t & 31) == 0) { r0[t >> 5] = s0; r1[t >> 5] = s1; }
    __syncthreads();
    float inv0 = 1.0f / (r0[0] + r0[1] + r0[2] + r0[3] + 1e-8f);
    float inv1 = 1.0f / (r1[0] + r1[1] + r1[2] + r1[3] + 1e-8f);

    if (d0 == 0) {
        float* ao0 = attn_out + b * 4096;
        float* ao1 = ao0 + 2048;
        for (int j = t; j < 2048; j += 128) {
            ao0[j] = a0p[j] * inv0;
            ao1[j] = a1p[j] * inv1;
        }
    }

    __shared__ float w0[256], w1[256];
    float acc0 = 0.f, acc1 = 0.f;
    const float* vb = v + (size_t)b * 2048 * D + d0 + t;
    for (int jc = 0; jc < 2048; jc += 256) {
        __syncthreads();
        w0[t] = a0p[jc + t]; w0[t + 128] = a0p[jc + t + 128];
        w1[t] = a1p[jc + t]; w1[t + 128] = a1p[jc + t + 128];
        __syncthreads();
#pragma unroll 8
        for (int jj = 0; jj < 256; jj++) {
            float vv = vb[(size_t)(jc + jj) * D];
            acc0 += vv * w0[jj];
            acc1 += vv * w1[jj];
        }
    }
    upd[(size_t)(b * 2 + 0) * D + d0 + t] = acc0 * inv0;
    upd[(size_t)(b * 2 + 1) * D + d0 + t] = acc1 * inv1;
}

// ---------------------------------------------------------------------------
// Fused GRU gates + LayerNorm(h_new). 64 blocks x 128 threads.
// ---------------------------------------------------------------------------
__global__ void k_gruln(const float* __restrict__ gx, const float* __restrict__ gh,
                        const float* __restrict__ slots,
                        const float* __restrict__ g, const float* __restrict__ b,
                        float* __restrict__ hnew, float* __restrict__ hln) {
    int r = blockIdx.x, t = threadIdx.x;
    const float* gxr = gx + (size_t)r * 1536;
    const float* ghr = gh + (size_t)r * 1536;
    float4 xr = ((const float4*)(gxr))[t];
    float4 hr = ((const float4*)(ghr))[t];
    float4 xz = ((const float4*)(gxr + 512))[t];
    float4 hz = ((const float4*)(ghr + 512))[t];
    float4 xn = ((const float4*)(gxr + 1024))[t];
    float4 hn = ((const float4*)(ghr + 1024))[t];
    float4 hp = ((const float4*)(slots + (size_t)r * D))[t];

    float h[4];
    {
        float rg, z, n;
        rg = sigmoidf_(xr.x + hr.x); z = sigmoidf_(xz.x + hz.x);
        n = tanhf(xn.x + rg * hn.x); h[0] = (1.f - z) * n + z * hp.x;
        rg = sigmoidf_(xr.y + hr.y); z = sigmoidf_(xz.y + hz.y);
        n = tanhf(xn.y + rg * hn.y); h[1] = (1.f - z) * n + z * hp.y;
        rg = sigmoidf_(xr.z + hr.z); z = sigmoidf_(xz.z + hz.z);
        n = tanhf(xn.z + rg * hn.z); h[2] = (1.f - z) * n + z * hp.z;
        rg = sigmoidf_(xr.w + hr.w); z = sigmoidf_(xz.w + hz.w);
        n = tanhf(xn.w + rg * hn.w); h[3] = (1.f - z) * n + z * hp.w;
    }
    ((float4*)(hnew + (size_t)r * D))[t] = make_float4(h[0], h[1], h[2], h[3]);

    float s  = h[0] + h[1] + h[2] + h[3];
    float s2 = h[0]*h[0] + h[1]*h[1] + h[2]*h[2] + h[3]*h[3];
#pragma unroll
    for (int o = 16; o; o >>= 1) {
        s  += __shfl_down_sync(0xffffffffu, s,  o);
        s2 += __shfl_down_sync(0xffffffffu, s2, o);
    }
    __shared__ float ss[4], ss2[4];
    __shared__ float sm, srs;
    if ((t & 31) == 0) { ss[t >> 5] = s; ss2[t >> 5] = s2; }
    __syncthreads();
    if (t == 0) {
        float S  = ss[0] + ss[1] + ss[2] + ss[3];
        float S2 = ss2[0] + ss2[1] + ss2[2] + ss2[3];
        float mm  = S * (1.0f / 512.0f);
        float var = S2 * (1.0f / 512.0f) - mm * mm;
        sm = mm; srs = rsqrtf(var + 1e-5f);
    }
    __syncthreads();
    float mm = sm, rs = srs;
    float4 gg = ((const float4*)g)[t];
    float4 bb = ((const float4*)b)[t];
    float4 o;
    o.x = (h[0] - mm) * rs * gg.x + bb.x;
    o.y = (h[1] - mm) * rs * gg.y + bb.y;
    o.z = (h[2] - mm) * rs * gg.z + bb.z;
    o.w = (h[3] - mm) * rs * gg.w + bb.w;
    ((float4*)(hln + (size_t)r * D))[t] = o;
}

// ---------------------------------------------------------------------------
// host
// ---------------------------------------------------------------------------
extern "C" void kernel_launch(void* const* d_in, const int* in_sizes, int n_in,
                              void* d_out, int out_size) {
    (void)in_sizes; (void)n_in; (void)out_size;
    const float* inputs     = (const float*)d_in[0];
    const float* init_slots = (const float*)d_in[1];
    const float* Wq  = (const float*)d_in[2];
    const float* bq  = (const float*)d_in[3];
    const float* Wk  = (const float*)d_in[4];
    const float* bk  = (const float*)d_in[5];
    const float* Wv  = (const float*)d_in[6];
    const float* bv  = (const float*)d_in[7];
    const float* ln_in_g = (const float*)d_in[8];
    const float* ln_in_b = (const float*)d_in[9];
    const float* ln_s_g  = (const float*)d_in[10];
    const float* ln_s_b  = (const float*)d_in[11];
    const float* ln_f_g  = (const float*)d_in[12];
    const float* ln_f_b  = (const float*)d_in[13];
    const float* gru_wih = (const float*)d_in[14];
    const float* gru_whh = (const float*)d_in[15];
    const float* gru_bih = (const float*)d_in[16];
    const float* gru_bhh = (const float*)d_in[17];
    const float* W1 = (const float*)d_in[18];
    const float* b1 = (const float*)d_in[19];
    const float* W2 = (const float*)d_in[20];
    const float* b2 = (const float*)d_in[21];

    float* out      = (float*)d_out;
    float* slots    = out;
    float* qout     = out + 32768;
    float* kout     = out + 65536;
    float* attn_out = out + 65536 + 33554432;

    float* S = nullptr;
    cudaGetSymbolAddress((void**)&S, g_scratch);
    float* v    = S + OFF_V;
    float* attn = S + OFF_ATTN;
    float* sln  = S + OFF_SLN;
    float* upd  = S + OFF_UPD;
    float* gx   = S + OFF_GX;
    float* gh   = S + OFF_GH;
    float* hnew = S + OFF_HNEW;
    float* hln  = S + OFF_HLN;
    float* tbuf = S + OFF_T;
    __half* whi = (__half*)(S + OFF_WHI);
    __half* xh  = (__half*)(S + OFF_XH);

    cudaFuncSetAttribute(k_mmagemm, cudaFuncAttributeMaxDynamicSharedMemorySize,
                         PTOT);

    cudaMemcpyAsync(slots, init_slots, 32768 * sizeof(float),
                    cudaMemcpyDeviceToDevice);

    k_prepw<<<2048, 256>>>(Wk, Wv, whi);
    k_prepx<<<NROWS, 128>>>(inputs, ln_in_g, ln_in_b, xh);
    k_mmagemm<<<dim3(8, 512), 256, PTOT>>>(xh, whi, bk, bv, kout, v);

    for (int it = 0; it < 3; ++it) {
        k_ln64<<<64, 128>>>(slots, ln_s_g, ln_s_b, sln);
        k_gemm64<0><<<dim3(16, 1), 256>>>(sln, sln, Wq, Wq, bq, bq, nullptr,
                                          qout, qout, 512, 0);
        k_dots<<<dim3(16, 32), 128>>>(qout, kout, attn);
        k_upd<<<dim3(4, 32), 128>>>(attn, v, upd, attn_out);
        k_gemm64<1><<<dim3(48, 2), 256>>>(upd, slots, gru_wih, gru_whh,
                                          gru_bih, gru_bhh, nullptr,
                                          gx, gh, 1536, 0);
        k_gruln<<<64, 128>>>(gx, gh, slots, ln_f_g, ln_f_b, hnew, hln);
        k_gemm64<0><<<dim3(16, 1), 256>>>(hln, hln, W1, W1, b1, b1, nullptr,
                                          tbuf, tbuf, 512, 1);
        k_gemm64<0><<<dim3(16, 1), 256>>>(tbuf, tbuf, W2, W2, b2, b2, hnew,
                                          slots, slots, 512, 0);
    }
}